// round 4
// baseline (speedup 1.0000x reference)
#include <cuda_runtime.h>
#include <cuda_bf16.h>
#include <mma.h>
#include <cstdint>

using namespace nvcuda;

#define BATCH 2
#define SEQ   8192
#define DIMC  1024
#define NH    16
#define HD    64
#define CHUNK 128
#define NT    64
#define NROWS 16384
#define QKVN  3072
#define SCALE_ATTN 0.125f
#define EPS_BIT 1.1920929e-07f
#define EPS_OUT 1e-06f

// ---------------- static device scratch ----------------
__device__ int8_t        g_xq[(size_t)NROWS * DIMC];
__device__ float         g_adeq[NROWS];
__device__ int8_t        g_wq_qkv[(size_t)QKVN * DIMC];
__device__ int8_t        g_wq_proj[(size_t)DIMC * DIMC];
__device__ float         g_wdeq[2];
__device__ float         g_part[256];
__device__ float         g_qkv[(size_t)NROWS * QKVN];
__device__ float         g_q[(size_t)BATCH * NH * NT * CHUNK * HD];
__device__ float         g_k[(size_t)BATCH * NH * NT * CHUNK * HD];
__device__ float         g_v[(size_t)BATCH * NH * NT * CHUNK * HD];
__device__ float         g_kvsum[(size_t)BATCH * NH * NT * HD * HD];
__device__ float         g_kvpre[(size_t)BATCH * NH * NT * HD * HD];
__device__ float         g_attn[(size_t)NROWS * DIMC];
__device__ int8_t        g_xq2[(size_t)NROWS * DIMC];
__device__ float         g_adeq2[NROWS];

// ---------------- helpers ----------------
__device__ __forceinline__ float fexp(float x) {
    x = fmaxf(x, -80.0f);
    float y = x * 1.4426950408889634f;
    float n = rintf(y);
    float g = fmaf(-n, 0.6931471805599453f, x);
    float p = 1.9841270e-4f;
    p = fmaf(p, g, 1.3888889e-3f);
    p = fmaf(p, g, 8.3333333e-3f);
    p = fmaf(p, g, 4.1666667e-2f);
    p = fmaf(p, g, 1.6666667e-1f);
    p = fmaf(p, g, 5.0e-1f);
    p = fmaf(p, g, 1.0f);
    p = fmaf(p, g, 1.0f);
    float s = __int_as_float(((int)n + 127) << 23);
    return p * s;
}

__device__ __forceinline__ void split2(float v, __nv_bfloat16& hi, __nv_bfloat16& lo) {
    hi = __float2bfloat16(v);
    lo = __float2bfloat16(v - __bfloat162float(hi));
}

// float (already rounded+clamped to s8 range) -> packed 4x int8.
// NOTE: go through int, NOT (char): plain char is UNSIGNED on the aarch64
// GPU host, and float->uchar saturates negatives to 0.
__device__ __forceinline__ uint32_t pack_s8(float a, float b, float c, float d) {
    int ia = (int)a, ib = (int)b, ic = (int)c, id = (int)d;
    return (uint32_t)(ia & 0xFF) | ((uint32_t)(ib & 0xFF) << 8) |
           ((uint32_t)(ic & 0xFF) << 16) | ((uint32_t)(id & 0xFF) << 24);
}

// ---------------- weight quant ----------------
__global__ void absmean_partial(const float* __restrict__ w, int n) {
    __shared__ float red[256];
    int tid = threadIdx.x;
    float s = 0.f;
    for (int i = blockIdx.x * 256 + tid; i < n; i += 65536) s += fabsf(w[i]);
    red[tid] = s; __syncthreads();
    for (int st = 128; st > 0; st >>= 1) { if (tid < st) red[tid] += red[tid + st]; __syncthreads(); }
    if (tid == 0) g_part[blockIdx.x] = red[0];
}

__global__ void absmean_final(int n, int slot) {
    __shared__ float red[256];
    int tid = threadIdx.x;
    red[tid] = g_part[tid]; __syncthreads();
    for (int st = 128; st > 0; st >>= 1) { if (tid < st) red[tid] += red[tid + st]; __syncthreads(); }
    if (tid == 0) g_wdeq[slot] = fmaxf(red[0] / (float)n, 1e-5f);
}

__global__ void quant_weight(const float* __restrict__ w, int8_t* __restrict__ wq,
                             int n, int slot) {
    float s = 1.0f / g_wdeq[slot];
    int i4 = (blockIdx.x * blockDim.x + threadIdx.x) * 4;
    if (i4 >= n) return;
    float4 wv = *(const float4*)(w + i4);
    float a = fminf(fmaxf(rintf(wv.x * s), -1.f), 1.f);
    float b = fminf(fmaxf(rintf(wv.y * s), -1.f), 1.f);
    float c = fminf(fmaxf(rintf(wv.z * s), -1.f), 1.f);
    float d = fminf(fmaxf(rintf(wv.w * s), -1.f), 1.f);
    *(uint32_t*)(wq + i4) = pack_s8(a, b, c, d);
}

// ---------------- activation quant for QKV input ----------------
__global__ void __launch_bounds__(256) act_quant_x(const float* __restrict__ x,
                                                   const float* __restrict__ nw) {
    __shared__ float red[256];
    __shared__ float bc;
    int row = blockIdx.x, tid = threadIdx.x;
    float4 xv = ((const float4*)(x + (size_t)row * DIMC))[tid];
    float4 wv = ((const float4*)nw)[tid];
    float ss = xv.x*xv.x + xv.y*xv.y + xv.z*xv.z + xv.w*xv.w;
    red[tid] = ss; __syncthreads();
    for (int st = 128; st > 0; st >>= 1) { if (tid < st) red[tid] += red[tid + st]; __syncthreads(); }
    if (tid == 0) bc = rsqrtf(red[0] * (1.0f / DIMC) + EPS_BIT);
    __syncthreads();
    float r = bc;
    float n0 = xv.x*r*wv.x, n1 = xv.y*r*wv.y, n2 = xv.z*r*wv.z, n3 = xv.w*r*wv.w;
    float amax = fmaxf(fmaxf(fabsf(n0), fabsf(n1)), fmaxf(fabsf(n2), fabsf(n3)));
    red[tid] = amax; __syncthreads();
    for (int st = 128; st > 0; st >>= 1) { if (tid < st) red[tid] = fmaxf(red[tid], red[tid + st]); __syncthreads(); }
    if (tid == 0) {
        float mx = fmaxf(red[0], 1e-5f);
        bc = 127.0f / mx;
        g_adeq[row] = mx * (1.0f / 127.0f);
    }
    __syncthreads();
    float sc = bc;
    float a = fminf(fmaxf(rintf(n0 * sc), -128.f), 127.f);
    float b = fminf(fmaxf(rintf(n1 * sc), -128.f), 127.f);
    float c = fminf(fmaxf(rintf(n2 * sc), -128.f), 127.f);
    float d = fminf(fmaxf(rintf(n3 * sc), -128.f), 127.f);
    ((uint32_t*)(g_xq + (size_t)row * DIMC))[tid] = pack_s8(a, b, c, d);
}

// ---------------- double-norm + act quant for proj input ----------------
__global__ void __launch_bounds__(256) norm2_quant(const float* __restrict__ nw,
                                                   const float* __restrict__ pnw) {
    __shared__ float red[256];
    __shared__ float bc;
    int row = blockIdx.x, tid = threadIdx.x;
    float4 xv = ((const float4*)(g_attn + (size_t)row * DIMC))[tid];
    float4 wv = ((const float4*)nw)[tid];
    float4 pv = ((const float4*)pnw)[tid];
    float ss = xv.x*xv.x + xv.y*xv.y + xv.z*xv.z + xv.w*xv.w;
    red[tid] = ss; __syncthreads();
    for (int st = 128; st > 0; st >>= 1) { if (tid < st) red[tid] += red[tid + st]; __syncthreads(); }
    if (tid == 0) bc = rsqrtf(red[0] * (1.0f / DIMC) + EPS_OUT);
    __syncthreads();
    float r1 = bc;
    float z0 = xv.x*r1*wv.x, z1 = xv.y*r1*wv.y, z2 = xv.z*r1*wv.z, z3 = xv.w*r1*wv.w;
    float ss2 = z0*z0 + z1*z1 + z2*z2 + z3*z3;
    red[tid] = ss2; __syncthreads();
    for (int st = 128; st > 0; st >>= 1) { if (tid < st) red[tid] += red[tid + st]; __syncthreads(); }
    if (tid == 0) bc = rsqrtf(red[0] * (1.0f / DIMC) + EPS_BIT);
    __syncthreads();
    float r2 = bc;
    float n0 = z0*r2*pv.x, n1 = z1*r2*pv.y, n2 = z2*r2*pv.z, n3 = z3*r2*pv.w;
    float amax = fmaxf(fmaxf(fabsf(n0), fabsf(n1)), fmaxf(fabsf(n2), fabsf(n3)));
    red[tid] = amax; __syncthreads();
    for (int st = 128; st > 0; st >>= 1) { if (tid < st) red[tid] = fmaxf(red[tid], red[tid + st]); __syncthreads(); }
    if (tid == 0) {
        float mx = fmaxf(red[0], 1e-5f);
        bc = 127.0f / mx;
        g_adeq2[row] = mx * (1.0f / 127.0f);
    }
    __syncthreads();
    float sc = bc;
    float a = fminf(fmaxf(rintf(n0 * sc), -128.f), 127.f);
    float b = fminf(fmaxf(rintf(n1 * sc), -128.f), 127.f);
    float c = fminf(fmaxf(rintf(n2 * sc), -128.f), 127.f);
    float d = fminf(fmaxf(rintf(n3 * sc), -128.f), 127.f);
    ((uint32_t*)(g_xq2 + (size_t)row * DIMC))[tid] = pack_s8(a, b, c, d);
}

// ---------------- int8 IMMA GEMM: C[M,N] = A[M,1024] @ W[N,1024]^T * adeq*wdeq + bias ----------------
#define GLD 80
__global__ void __launch_bounds__(256) gemm_s8(
    const int8_t* __restrict__ A, const int8_t* __restrict__ W,
    float* __restrict__ C, int N,
    const float* __restrict__ adeq, int wslot, const float* __restrict__ bias)
{
    __shared__ __align__(16) int8_t As[128 * GLD];
    __shared__ __align__(16) int8_t Bs[128 * GLD];
    __shared__ __align__(16) int    CsAll[8 * 16 * 20];

    int tid = threadIdx.x;
    int wid = tid >> 5, lane = tid & 31;
    int wm = wid >> 2, wn = wid & 3;            // warp tile 64x32
    int bm = blockIdx.y * 128;
    int bn = blockIdx.x * 128;
    float wdeq = g_wdeq[wslot];

    wmma::fragment<wmma::accumulator, 16, 16, 16, int> c[4][2];
    #pragma unroll
    for (int i = 0; i < 4; i++)
        #pragma unroll
        for (int j = 0; j < 2; j++) wmma::fill_fragment(c[i][j], 0);

    int row = tid >> 1;
    int off = (tid & 1) * 32;
    const int8_t* Ag = A + (size_t)(bm + row) * 1024 + off;
    const int8_t* Bg = W + (size_t)(bn + row) * 1024 + off;

    uint4 a0 = *(const uint4*)(Ag);
    uint4 a1 = *(const uint4*)(Ag + 16);
    uint4 b0 = *(const uint4*)(Bg);
    uint4 b1 = *(const uint4*)(Bg + 16);

    for (int kt = 0; kt < 16; kt++) {
        *(uint4*)(&As[row * GLD + off])      = a0;
        *(uint4*)(&As[row * GLD + off + 16]) = a1;
        *(uint4*)(&Bs[row * GLD + off])      = b0;
        *(uint4*)(&Bs[row * GLD + off + 16]) = b1;
        __syncthreads();
        if (kt + 1 < 16) {
            int kn = (kt + 1) * 64;
            a0 = *(const uint4*)(Ag + kn);
            a1 = *(const uint4*)(Ag + kn + 16);
            b0 = *(const uint4*)(Bg + kn);
            b1 = *(const uint4*)(Bg + kn + 16);
        }
        #pragma unroll
        for (int sk = 0; sk < 4; sk++) {
            int k0 = sk * 16;
            wmma::fragment<wmma::matrix_a, 16, 16, 16, signed char, wmma::row_major> af[4];
            wmma::fragment<wmma::matrix_b, 16, 16, 16, signed char, wmma::col_major> bf[2];
            #pragma unroll
            for (int i = 0; i < 4; i++)
                wmma::load_matrix_sync(af[i], (const signed char*)&As[(wm * 64 + i * 16) * GLD + k0], GLD);
            #pragma unroll
            for (int j = 0; j < 2; j++)
                wmma::load_matrix_sync(bf[j], (const signed char*)&Bs[(wn * 32 + j * 16) * GLD + k0], GLD);
            #pragma unroll
            for (int i = 0; i < 4; i++)
                #pragma unroll
                for (int j = 0; j < 2; j++)
                    wmma::mma_sync(c[i][j], af[i], bf[j], c[i][j]);
        }
        __syncthreads();
    }

    int* Csw = &CsAll[wid * 320];
    #pragma unroll
    for (int i = 0; i < 4; i++) {
        #pragma unroll
        for (int j = 0; j < 2; j++) {
            __syncwarp();
            wmma::store_matrix_sync(Csw, c[i][j], 20, wmma::mem_row_major);
            __syncwarp();
            int r  = lane >> 1;
            int cc = (lane & 1) * 8;
            int grow = bm + wm * 64 + i * 16 + r;
            int gcol = bn + wn * 32 + j * 16 + cc;
            float sc = adeq[grow] * wdeq;
            float* dst = C + (size_t)grow * N + gcol;
            float4 o1, o2;
            o1.x = (float)Csw[r*20+cc+0]*sc + bias[gcol+0];
            o1.y = (float)Csw[r*20+cc+1]*sc + bias[gcol+1];
            o1.z = (float)Csw[r*20+cc+2]*sc + bias[gcol+2];
            o1.w = (float)Csw[r*20+cc+3]*sc + bias[gcol+3];
            o2.x = (float)Csw[r*20+cc+4]*sc + bias[gcol+4];
            o2.y = (float)Csw[r*20+cc+5]*sc + bias[gcol+5];
            o2.z = (float)Csw[r*20+cc+6]*sc + bias[gcol+6];
            o2.w = (float)Csw[r*20+cc+7]*sc + bias[gcol+7];
            *(float4*)(dst)     = o1;
            *(float4*)(dst + 4) = o2;
        }
    }
}

// ---------------- rope + split ----------------
__global__ void __launch_bounds__(256) rope_split(const float* __restrict__ cosb,
                                                  const float* __restrict__ sinb) {
    int idx = blockIdx.x * 256 + threadIdx.x;
    int i = idx & 31;
    int tmp = idx >> 5;
    int h = tmp & 15;
    int row = tmp >> 4;
    int b = row >> 13, n = row & 8191;
    int t = n >> 7, r = n & 127;
    const float* src = g_qkv + (size_t)row * QKVN + h * 64 + 2 * i;
    float2 q2 = *(const float2*)(src);
    float2 k2 = *(const float2*)(src + 1024);
    float2 v2 = *(const float2*)(src + 2048);
    float c = cosb[n * 32 + i], s = sinb[n * 32 + i];
    float2 qo = make_float2(q2.x * c - q2.y * s, q2.y * c + q2.x * s);
    float2 ko = make_float2(k2.x * c - k2.y * s, k2.y * c + k2.x * s);
    size_t dst = (((size_t)b * NH + h) * NT + t) * (CHUNK * HD) + r * 64 + 2 * i;
    *(float2*)(g_q + dst) = qo;
    *(float2*)(g_k + dst) = ko;
    *(float2*)(g_v + dst) = v2;
}

// ---------------- intra-chunk attention (split-bf16 tensor cores) ----------------
#define QHI_OFF 0
#define QLO_OFF (128*72)
#define KHI_OFF (2*128*72)
#define KLO_OFF (3*128*72)
#define PHI_OFF (4*128*72)
#define PLO_OFF (4*128*72 + 128*136)
#define BF_TOTAL (4*128*72 + 2*128*136)
#define SS_LD 132

__global__ void __launch_bounds__(512) attn_intra() {
    int t = blockIdx.x, h = blockIdx.y, b = blockIdx.z;
    extern __shared__ __align__(16) char smraw[];
    __nv_bfloat16* bfm = (__nv_bfloat16*)smraw;
    float* sS = (float*)(smraw + (size_t)BF_TOTAL * 2);
    float* rowsum = sS + 128 * SS_LD;

    __nv_bfloat16* sQhi = bfm + QHI_OFF;
    __nv_bfloat16* sQlo = bfm + QLO_OFF;
    __nv_bfloat16* sKhi = bfm + KHI_OFF;
    __nv_bfloat16* sKlo = bfm + KLO_OFF;
    __nv_bfloat16* sPhi = bfm + PHI_OFF;
    __nv_bfloat16* sPlo = bfm + PLO_OFF;
    __nv_bfloat16* sVhi = sQhi;
    __nv_bfloat16* sVlo = sQlo;

    size_t base = (((size_t)b * NH + h) * NT + t) * (CHUNK * HD);
    int tid = threadIdx.x;
    int wid = tid >> 5;

    #pragma unroll
    for (int u = 0; u < 4; u++) {
        int i = tid + u * 512;
        int r = i >> 4, c4 = (i & 15) * 4;
        float4 qv = *(const float4*)(g_q + base + (size_t)r * 64 + c4);
        float4 kv = *(const float4*)(g_k + base + (size_t)r * 64 + c4);
        __nv_bfloat16 hi, lo;
        split2(qv.x, hi, lo); sQhi[r*72+c4+0]=hi; sQlo[r*72+c4+0]=lo;
        split2(qv.y, hi, lo); sQhi[r*72+c4+1]=hi; sQlo[r*72+c4+1]=lo;
        split2(qv.z, hi, lo); sQhi[r*72+c4+2]=hi; sQlo[r*72+c4+2]=lo;
        split2(qv.w, hi, lo); sQhi[r*72+c4+3]=hi; sQlo[r*72+c4+3]=lo;
        split2(kv.x, hi, lo); sKhi[r*72+c4+0]=hi; sKlo[r*72+c4+0]=lo;
        split2(kv.y, hi, lo); sKhi[r*72+c4+1]=hi; sKlo[r*72+c4+1]=lo;
        split2(kv.z, hi, lo); sKhi[r*72+c4+2]=hi; sKlo[r*72+c4+2]=lo;
        split2(kv.w, hi, lo); sKhi[r*72+c4+3]=hi; sKlo[r*72+c4+3]=lo;
    }
    __syncthreads();

    // QK^T: 16 warps, warp tile 16 rows x 64 cols
    {
        int r0 = (wid >> 1) * 16;
        int cbase = (wid & 1) * 64;
        wmma::fragment<wmma::accumulator, 16, 16, 16, float> c[4];
        #pragma unroll
        for (int j = 0; j < 4; j++) wmma::fill_fragment(c[j], 0.0f);
        #pragma unroll
        for (int sk = 0; sk < 4; sk++) {
            int k0 = sk * 16;
            wmma::fragment<wmma::matrix_a, 16, 16, 16, __nv_bfloat16, wmma::row_major> ah, al;
            wmma::load_matrix_sync(ah, &sQhi[r0 * 72 + k0], 72);
            wmma::load_matrix_sync(al, &sQlo[r0 * 72 + k0], 72);
            #pragma unroll
            for (int j = 0; j < 4; j++) {
                int col0 = cbase + j * 16;
                wmma::fragment<wmma::matrix_b, 16, 16, 16, __nv_bfloat16, wmma::col_major> bh, bl;
                wmma::load_matrix_sync(bh, &sKhi[col0 * 72 + k0], 72);
                wmma::load_matrix_sync(bl, &sKlo[col0 * 72 + k0], 72);
                wmma::mma_sync(c[j], ah, bh, c[j]);
                wmma::mma_sync(c[j], ah, bl, c[j]);
                wmma::mma_sync(c[j], al, bh, c[j]);
            }
        }
        #pragma unroll
        for (int j = 0; j < 4; j++) {
            #pragma unroll
            for (int e = 0; e < c[j].num_elements; e++) c[j].x[e] *= SCALE_ATTN;
            wmma::store_matrix_sync(&sS[r0 * SS_LD + cbase + j * 16], c[j], SS_LD, wmma::mem_row_major);
        }
    }
    __syncthreads();

    // softmax: 4 threads per row
    {
        int r = tid >> 2;
        int c0 = (tid & 3) * 32;
        float mx = -3.0e38f;
        for (int c = c0; c < c0 + 32; c++)
            if (c <= r) mx = fmaxf(mx, sS[r * SS_LD + c]);
        mx = fmaxf(mx, __shfl_xor_sync(0xffffffffu, mx, 1));
        mx = fmaxf(mx, __shfl_xor_sync(0xffffffffu, mx, 2));
        float sum = 0.f;
        for (int c = c0; c < c0 + 32; c++) {
            float e = (c <= r) ? fexp(sS[r * SS_LD + c] - mx) : 0.f;
            sum += e;
            __nv_bfloat16 hi, lo;
            split2(e, hi, lo);
            sPhi[r * 136 + c] = hi;
            sPlo[r * 136 + c] = lo;
        }
        sum += __shfl_xor_sync(0xffffffffu, sum, 1);
        sum += __shfl_xor_sync(0xffffffffu, sum, 2);
        if ((tid & 3) == 0) rowsum[r] = sum;
    }
    // V load into Q slots (Q dead; all warps past QK^T via sync above)
    #pragma unroll
    for (int u = 0; u < 4; u++) {
        int i = tid + u * 512;
        int r = i >> 4, c4 = (i & 15) * 4;
        float4 vv = *(const float4*)(g_v + base + (size_t)r * 64 + c4);
        __nv_bfloat16 hi, lo;
        split2(vv.x, hi, lo); sVhi[r*72+c4+0]=hi; sVlo[r*72+c4+0]=lo;
        split2(vv.y, hi, lo); sVhi[r*72+c4+1]=hi; sVlo[r*72+c4+1]=lo;
        split2(vv.z, hi, lo); sVhi[r*72+c4+2]=hi; sVlo[r*72+c4+2]=lo;
        split2(vv.w, hi, lo); sVhi[r*72+c4+3]=hi; sVlo[r*72+c4+3]=lo;
    }
    __syncthreads();

    // S_t = K^T V (64x64): one 16x16 tile per warp
    {
        int d0 = (wid >> 2) * 16;
        int e0 = (wid & 3) * 16;
        wmma::fragment<wmma::accumulator, 16, 16, 16, float> c;
        wmma::fill_fragment(c, 0.0f);
        #pragma unroll
        for (int sk = 0; sk < 8; sk++) {
            int r0 = sk * 16;
            wmma::fragment<wmma::matrix_a, 16, 16, 16, __nv_bfloat16, wmma::col_major> ah, al;
            wmma::fragment<wmma::matrix_b, 16, 16, 16, __nv_bfloat16, wmma::row_major> bh, bl;
            wmma::load_matrix_sync(ah, &sKhi[r0 * 72 + d0], 72);
            wmma::load_matrix_sync(al, &sKlo[r0 * 72 + d0], 72);
            wmma::load_matrix_sync(bh, &sVhi[r0 * 72 + e0], 72);
            wmma::load_matrix_sync(bl, &sVlo[r0 * 72 + e0], 72);
            wmma::mma_sync(c, ah, bh, c);
            wmma::mma_sync(c, ah, bl, c);
            wmma::mma_sync(c, al, bh, c);
        }
        size_t kb = (((size_t)b * NH + h) * NT + t) * (HD * HD);
        wmma::store_matrix_sync(g_kvsum + kb + (size_t)d0 * 64 + e0, c, 64, wmma::mem_row_major);
    }

    // o_intra = P @ V (128x64): warp tile 16x32
    {
        int r0 = (wid >> 1) * 16;
        int cbase = (wid & 1) * 32;
        wmma::fragment<wmma::accumulator, 16, 16, 16, float> c[2];
        #pragma unroll
        for (int j = 0; j < 2; j++) wmma::fill_fragment(c[j], 0.0f);
        #pragma unroll
        for (int sk = 0; sk < 8; sk++) {
            int k0 = sk * 16;
            wmma::fragment<wmma::matrix_a, 16, 16, 16, __nv_bfloat16, wmma::row_major> ah, al;
            wmma::load_matrix_sync(ah, &sPhi[r0 * 136 + k0], 136);
            wmma::load_matrix_sync(al, &sPlo[r0 * 136 + k0], 136);
            #pragma unroll
            for (int j = 0; j < 2; j++) {
                int col0 = cbase + j * 16;
                wmma::fragment<wmma::matrix_b, 16, 16, 16, __nv_bfloat16, wmma::row_major> bh, bl;
                wmma::load_matrix_sync(bh, &sVhi[k0 * 72 + col0], 72);
                wmma::load_matrix_sync(bl, &sVlo[k0 * 72 + col0], 72);
                wmma::mma_sync(c[j], ah, bh, c[j]);
                wmma::mma_sync(c[j], ah, bl, c[j]);
                wmma::mma_sync(c[j], al, bh, c[j]);
            }
        }
        __syncthreads();
        #pragma unroll
        for (int j = 0; j < 2; j++)
            wmma::store_matrix_sync(&sS[r0 * SS_LD + cbase + j * 16], c[j], SS_LD, wmma::mem_row_major);
    }
    __syncthreads();

    #pragma unroll
    for (int u = 0; u < 4; u++) {
        int i = tid + u * 512;
        int r = i >> 4, c4 = (i & 15) * 4;
        float inv = 1.0f / rowsum[r];
        float4 o;
        o.x = sS[r * SS_LD + c4 + 0] * inv;
        o.y = sS[r * SS_LD + c4 + 1] * inv;
        o.z = sS[r * SS_LD + c4 + 2] * inv;
        o.w = sS[r * SS_LD + c4 + 3] * inv;
        size_t grow = (size_t)b * SEQ + (size_t)t * CHUNK + r;
        *(float4*)(g_attn + grow * DIMC + h * 64 + c4) = o;
    }
}

// ---------------- exclusive prefix-sum of chunk KV matrices ----------------
__global__ void __launch_bounds__(256) kv_prefix() {
    int bh = blockIdx.x;
    int tid = threadIdx.x;
    size_t base = (size_t)bh * NT * (HD * HD);
    float acc[16];
    #pragma unroll
    for (int c = 0; c < 16; c++) acc[c] = 0.f;
    for (int t = 0; t < NT; t++) {
        size_t p = base + (size_t)t * (HD * HD);
        #pragma unroll
        for (int c = 0; c < 16; c++) {
            size_t off = p + c * 256 + tid;
            float v = g_kvsum[off];
            g_kvpre[off] = acc[c];
            acc[c] += v;
        }
    }
}

// ---------------- o_inter = q @ kv_prefix ----------------
#define IQHI 0
#define IQLO (128*72)
#define IKHI (2*128*72)
#define IKLO (2*128*72 + 64*72)
#define IBF_TOTAL (2*128*72 + 2*64*72)
__global__ void __launch_bounds__(256) attn_inter() {
    int t = blockIdx.x, h = blockIdx.y, b = blockIdx.z;
    extern __shared__ __align__(16) char smraw2[];
    __nv_bfloat16* bfm = (__nv_bfloat16*)smraw2;
    float* sO = (float*)(smraw2 + (size_t)IBF_TOTAL * 2);

    __nv_bfloat16* sQhi = bfm + IQHI;
    __nv_bfloat16* sQlo = bfm + IQLO;
    __nv_bfloat16* sKhi = bfm + IKHI;
    __nv_bfloat16* sKlo = bfm + IKLO;

    size_t base = (((size_t)b * NH + h) * NT + t) * (CHUNK * HD);
    size_t kb   = (((size_t)b * NH + h) * NT + t) * (HD * HD);
    int tid = threadIdx.x;
    int wid = tid >> 5;

    #pragma unroll
    for (int u = 0; u < 8; u++) {
        int i = tid + u * 256;
        int r = i >> 4, c4 = (i & 15) * 4;
        float4 qv = *(const float4*)(g_q + base + (size_t)r * 64 + c4);
        __nv_bfloat16 hi, lo;
        split2(qv.x, hi, lo); sQhi[r*72+c4+0]=hi; sQlo[r*72+c4+0]=lo;
        split2(qv.y, hi, lo); sQhi[r*72+c4+1]=hi; sQlo[r*72+c4+1]=lo;
        split2(qv.z, hi, lo); sQhi[r*72+c4+2]=hi; sQlo[r*72+c4+2]=lo;
        split2(qv.w, hi, lo); sQhi[r*72+c4+3]=hi; sQlo[r*72+c4+3]=lo;
    }
    #pragma unroll
    for (int u = 0; u < 4; u++) {
        int i = tid + u * 256;
        int r = i >> 4, c4 = (i & 15) * 4;
        float4 kv = *(const float4*)(g_kvpre + kb + (size_t)r * 64 + c4);
        __nv_bfloat16 hi, lo;
        split2(kv.x, hi, lo); sKhi[r*72+c4+0]=hi; sKlo[r*72+c4+0]=lo;
        split2(kv.y, hi, lo); sKhi[r*72+c4+1]=hi; sKlo[r*72+c4+1]=lo;
        split2(kv.z, hi, lo); sKhi[r*72+c4+2]=hi; sKlo[r*72+c4+2]=lo;
        split2(kv.w, hi, lo); sKhi[r*72+c4+3]=hi; sKlo[r*72+c4+3]=lo;
    }
    __syncthreads();

    {
        int r0 = wid * 16;
        wmma::fragment<wmma::accumulator, 16, 16, 16, float> c[4];
        #pragma unroll
        for (int j = 0; j < 4; j++) wmma::fill_fragment(c[j], 0.0f);
        #pragma unroll
        for (int sk = 0; sk < 4; sk++) {
            int k0 = sk * 16;
            wmma::fragment<wmma::matrix_a, 16, 16, 16, __nv_bfloat16, wmma::row_major> ah, al;
            wmma::load_matrix_sync(ah, &sQhi[r0 * 72 + k0], 72);
            wmma::load_matrix_sync(al, &sQlo[r0 * 72 + k0], 72);
            #pragma unroll
            for (int j = 0; j < 4; j++) {
                int col0 = j * 16;
                wmma::fragment<wmma::matrix_b, 16, 16, 16, __nv_bfloat16, wmma::row_major> bh, bl;
                wmma::load_matrix_sync(bh, &sKhi[k0 * 72 + col0], 72);
                wmma::load_matrix_sync(bl, &sKlo[k0 * 72 + col0], 72);
                wmma::mma_sync(c[j], ah, bh, c[j]);
                wmma::mma_sync(c[j], ah, bl, c[j]);
                wmma::mma_sync(c[j], al, bh, c[j]);
            }
        }
        #pragma unroll
        for (int j = 0; j < 4; j++)
            wmma::store_matrix_sync(&sO[r0 * 68 + j * 16], c[j], 68, wmma::mem_row_major);
    }
    __syncthreads();

    #pragma unroll
    for (int u = 0; u < 8; u++) {
        int i = tid + u * 256;
        int r = i >> 4, c4 = (i & 15) * 4;
        size_t grow = (size_t)b * SEQ + (size_t)t * CHUNK + r;
        float* dst = g_attn + grow * DIMC + h * 64 + c4;
        float4 old = *(float4*)dst;
        old.x += sO[r * 68 + c4 + 0];
        old.y += sO[r * 68 + c4 + 1];
        old.z += sO[r * 68 + c4 + 2];
        old.w += sO[r * 68 + c4 + 3];
        *(float4*)dst = old;
    }
}

// ---------------- launch ----------------
extern "C" void kernel_launch(void* const* d_in, const int* in_sizes, int n_in,
                              void* d_out, int out_size) {
    const float* x       = (const float*)d_in[0];
    const float* cosb    = (const float*)d_in[1];
    const float* sinb    = (const float*)d_in[2];
    const float* qkv_w   = (const float*)d_in[3];
    const float* qkv_b   = (const float*)d_in[4];
    const float* qkv_nw  = (const float*)d_in[5];
    const float* proj_w  = (const float*)d_in[6];
    const float* proj_b  = (const float*)d_in[7];
    const float* proj_nw = (const float*)d_in[8];
    const float* norm_w  = (const float*)d_in[9];
    float* out = (float*)d_out;

    size_t smem_intra = (size_t)BF_TOTAL * 2 + (128 * SS_LD + 128) * sizeof(float);
    size_t smem_inter = (size_t)IBF_TOTAL * 2 + (128 * 68) * sizeof(float);

    static bool attr_done = false;
    if (!attr_done) {
        cudaFuncSetAttribute(attn_intra, cudaFuncAttributeMaxDynamicSharedMemorySize, (int)smem_intra);
        cudaFuncSetAttribute(attn_inter, cudaFuncAttributeMaxDynamicSharedMemorySize, (int)smem_inter);
        attr_done = true;
    }

    int8_t *xq_p, *wqkv_p, *wproj_p, *xq2_p;
    float *qkv_p, *adeq_p, *adeq2_p;
    cudaGetSymbolAddress((void**)&xq_p,    g_xq);
    cudaGetSymbolAddress((void**)&wqkv_p,  g_wq_qkv);
    cudaGetSymbolAddress((void**)&wproj_p, g_wq_proj);
    cudaGetSymbolAddress((void**)&xq2_p,   g_xq2);
    cudaGetSymbolAddress((void**)&qkv_p,   g_qkv);
    cudaGetSymbolAddress((void**)&adeq_p,  g_adeq);
    cudaGetSymbolAddress((void**)&adeq2_p, g_adeq2);

    // weight quantization
    absmean_partial<<<256, 256>>>(qkv_w, QKVN * DIMC);
    absmean_final<<<1, 256>>>(QKVN * DIMC, 0);
    quant_weight<<<(QKVN * DIMC / 4 + 255) / 256, 256>>>(qkv_w, wqkv_p, QKVN * DIMC, 0);
    absmean_partial<<<256, 256>>>(proj_w, DIMC * DIMC);
    absmean_final<<<1, 256>>>(DIMC * DIMC, 1);
    quant_weight<<<(DIMC * DIMC / 4 + 255) / 256, 256>>>(proj_w, wproj_p, DIMC * DIMC, 1);

    // QKV bitlinear
    act_quant_x<<<NROWS, 256>>>(x, qkv_nw);
    {
        dim3 grid(QKVN / 128, NROWS / 128);
        gemm_s8<<<grid, 256>>>(xq_p, wqkv_p, qkv_p, QKVN, adeq_p, 0, qkv_b);
    }

    // rope + split
    rope_split<<<(NROWS * NH * 32) / 256, 256>>>(cosb, sinb);

    // attention
    {
        dim3 grid(NT, NH, BATCH);
        attn_intra<<<grid, 512, smem_intra>>>();
    }
    kv_prefix<<<BATCH * NH, 256>>>();
    {
        dim3 grid(NT, NH, BATCH);
        attn_inter<<<grid, 256, smem_inter>>>();
    }

    // output norm + proj bitlinear
    norm2_quant<<<NROWS, 256>>>(norm_w, proj_nw);
    {
        dim3 grid(DIMC / 128, NROWS / 128);
        gemm_s8<<<grid, 256>>>(xq2_p, wproj_p, out, DIMC, adeq2_p, 1, proj_b);
    }
}

// round 5
// speedup vs baseline: 1.7778x; 1.7778x over previous
#include <cuda_runtime.h>
#include <cuda_bf16.h>
#include <mma.h>
#include <cstdint>

using namespace nvcuda;

#define BATCH 2
#define SEQ   8192
#define DIMC  1024
#define NH    16
#define HD    64
#define CHUNK 128
#define NT    64
#define NROWS 16384
#define QKVN  3072
#define SCALE_ATTN 0.125f
#define EPS_BIT 1.1920929e-07f
#define EPS_OUT 1e-06f

// ---------------- static device scratch ----------------
__device__ __nv_bfloat16 g_xq[(size_t)NROWS * DIMC];
__device__ float         g_adeq[NROWS];
__device__ __nv_bfloat16 g_wq_qkv[(size_t)QKVN * DIMC];
__device__ __nv_bfloat16 g_wq_proj[(size_t)DIMC * DIMC];
__device__ float         g_wdeq[2];
__device__ float         g_part[256];
__device__ float         g_qkv[(size_t)NROWS * QKVN];
__device__ float         g_q[(size_t)BATCH * NH * NT * CHUNK * HD];
__device__ float         g_k[(size_t)BATCH * NH * NT * CHUNK * HD];
__device__ float         g_v[(size_t)BATCH * NH * NT * CHUNK * HD];
__device__ float         g_kvsum[(size_t)BATCH * NH * NT * HD * HD];
__device__ float         g_kvpre[(size_t)BATCH * NH * NT * HD * HD];
__device__ float         g_attn[(size_t)NROWS * DIMC];
__device__ __nv_bfloat16 g_xq2[(size_t)NROWS * DIMC];
__device__ float         g_adeq2[NROWS];

// ---------------- helpers ----------------
__device__ __forceinline__ float fexp(float x) {
    x = fmaxf(x, -80.0f);
    float y = x * 1.4426950408889634f;
    float n = rintf(y);
    float g = fmaf(-n, 0.6931471805599453f, x);
    float p = 1.9841270e-4f;
    p = fmaf(p, g, 1.3888889e-3f);
    p = fmaf(p, g, 8.3333333e-3f);
    p = fmaf(p, g, 4.1666667e-2f);
    p = fmaf(p, g, 1.6666667e-1f);
    p = fmaf(p, g, 5.0e-1f);
    p = fmaf(p, g, 1.0f);
    p = fmaf(p, g, 1.0f);
    float s = __int_as_float(((int)n + 127) << 23);
    return p * s;
}

__device__ __forceinline__ void split2(float v, __nv_bfloat16& hi, __nv_bfloat16& lo) {
    hi = __float2bfloat16(v);
    lo = __float2bfloat16(v - __bfloat162float(hi));
}

// ---------------- weight quant ----------------
__global__ void absmean_partial(const float* __restrict__ w, int n) {
    __shared__ float red[256];
    int tid = threadIdx.x;
    float s = 0.f;
    for (int i = blockIdx.x * 256 + tid; i < n; i += 65536) s += fabsf(w[i]);
    red[tid] = s; __syncthreads();
    for (int st = 128; st > 0; st >>= 1) { if (tid < st) red[tid] += red[tid + st]; __syncthreads(); }
    if (tid == 0) g_part[blockIdx.x] = red[0];
}

__global__ void absmean_final(int n, int slot) {
    __shared__ float red[256];
    int tid = threadIdx.x;
    red[tid] = g_part[tid]; __syncthreads();
    for (int st = 128; st > 0; st >>= 1) { if (tid < st) red[tid] += red[tid + st]; __syncthreads(); }
    if (tid == 0) g_wdeq[slot] = fmaxf(red[0] / (float)n, 1e-5f);
}

__global__ void quant_weight(const float* __restrict__ w, __nv_bfloat16* __restrict__ wq,
                             int n, int slot) {
    float s = 1.0f / g_wdeq[slot];
    int i4 = (blockIdx.x * blockDim.x + threadIdx.x) * 4;
    if (i4 >= n) return;
    float4 wv = *(const float4*)(w + i4);
    __nv_bfloat162 p0, p1;
    p0.x = __float2bfloat16(fminf(fmaxf(rintf(wv.x * s), -1.f), 1.f));
    p0.y = __float2bfloat16(fminf(fmaxf(rintf(wv.y * s), -1.f), 1.f));
    p1.x = __float2bfloat16(fminf(fmaxf(rintf(wv.z * s), -1.f), 1.f));
    p1.y = __float2bfloat16(fminf(fmaxf(rintf(wv.w * s), -1.f), 1.f));
    *(__nv_bfloat162*)(wq + i4)     = p0;
    *(__nv_bfloat162*)(wq + i4 + 2) = p1;
}

// ---------------- activation quant for QKV input ----------------
__global__ void __launch_bounds__(256) act_quant_x(const float* __restrict__ x,
                                                   const float* __restrict__ nw) {
    __shared__ float red[256];
    __shared__ float bc;
    int row = blockIdx.x, tid = threadIdx.x;
    float4 xv = ((const float4*)(x + (size_t)row * DIMC))[tid];
    float4 wv = ((const float4*)nw)[tid];
    float ss = xv.x*xv.x + xv.y*xv.y + xv.z*xv.z + xv.w*xv.w;
    red[tid] = ss; __syncthreads();
    for (int st = 128; st > 0; st >>= 1) { if (tid < st) red[tid] += red[tid + st]; __syncthreads(); }
    if (tid == 0) bc = rsqrtf(red[0] * (1.0f / DIMC) + EPS_BIT);
    __syncthreads();
    float r = bc;
    float n0 = xv.x*r*wv.x, n1 = xv.y*r*wv.y, n2 = xv.z*r*wv.z, n3 = xv.w*r*wv.w;
    float amax = fmaxf(fmaxf(fabsf(n0), fabsf(n1)), fmaxf(fabsf(n2), fabsf(n3)));
    red[tid] = amax; __syncthreads();
    for (int st = 128; st > 0; st >>= 1) { if (tid < st) red[tid] = fmaxf(red[tid], red[tid + st]); __syncthreads(); }
    if (tid == 0) {
        float mx = fmaxf(red[0], 1e-5f);
        bc = 127.0f / mx;
        g_adeq[row] = mx * (1.0f / 127.0f);
    }
    __syncthreads();
    float sc = bc;
    __nv_bfloat162 p0, p1;
    p0.x = __float2bfloat16(fminf(fmaxf(rintf(n0 * sc), -128.f), 127.f));
    p0.y = __float2bfloat16(fminf(fmaxf(rintf(n1 * sc), -128.f), 127.f));
    p1.x = __float2bfloat16(fminf(fmaxf(rintf(n2 * sc), -128.f), 127.f));
    p1.y = __float2bfloat16(fminf(fmaxf(rintf(n3 * sc), -128.f), 127.f));
    __nv_bfloat16* out = g_xq + (size_t)row * DIMC + tid * 4;
    *(__nv_bfloat162*)(out)     = p0;
    *(__nv_bfloat162*)(out + 2) = p1;
}

// ---------------- double-norm + act quant for proj input ----------------
__global__ void __launch_bounds__(256) norm2_quant(const float* __restrict__ nw,
                                                   const float* __restrict__ pnw) {
    __shared__ float red[256];
    __shared__ float bc;
    int row = blockIdx.x, tid = threadIdx.x;
    float4 xv = ((const float4*)(g_attn + (size_t)row * DIMC))[tid];
    float4 wv = ((const float4*)nw)[tid];
    float4 pv = ((const float4*)pnw)[tid];
    float ss = xv.x*xv.x + xv.y*xv.y + xv.z*xv.z + xv.w*xv.w;
    red[tid] = ss; __syncthreads();
    for (int st = 128; st > 0; st >>= 1) { if (tid < st) red[tid] += red[tid + st]; __syncthreads(); }
    if (tid == 0) bc = rsqrtf(red[0] * (1.0f / DIMC) + EPS_OUT);
    __syncthreads();
    float r1 = bc;
    float z0 = xv.x*r1*wv.x, z1 = xv.y*r1*wv.y, z2 = xv.z*r1*wv.z, z3 = xv.w*r1*wv.w;
    float ss2 = z0*z0 + z1*z1 + z2*z2 + z3*z3;
    red[tid] = ss2; __syncthreads();
    for (int st = 128; st > 0; st >>= 1) { if (tid < st) red[tid] += red[tid + st]; __syncthreads(); }
    if (tid == 0) bc = rsqrtf(red[0] * (1.0f / DIMC) + EPS_BIT);
    __syncthreads();
    float r2 = bc;
    float n0 = z0*r2*pv.x, n1 = z1*r2*pv.y, n2 = z2*r2*pv.z, n3 = z3*r2*pv.w;
    float amax = fmaxf(fmaxf(fabsf(n0), fabsf(n1)), fmaxf(fabsf(n2), fabsf(n3)));
    red[tid] = amax; __syncthreads();
    for (int st = 128; st > 0; st >>= 1) { if (tid < st) red[tid] = fmaxf(red[tid], red[tid + st]); __syncthreads(); }
    if (tid == 0) {
        float mx = fmaxf(red[0], 1e-5f);
        bc = 127.0f / mx;
        g_adeq2[row] = mx * (1.0f / 127.0f);
    }
    __syncthreads();
    float sc = bc;
    __nv_bfloat162 p0, p1;
    p0.x = __float2bfloat16(fminf(fmaxf(rintf(n0 * sc), -128.f), 127.f));
    p0.y = __float2bfloat16(fminf(fmaxf(rintf(n1 * sc), -128.f), 127.f));
    p1.x = __float2bfloat16(fminf(fmaxf(rintf(n2 * sc), -128.f), 127.f));
    p1.y = __float2bfloat16(fminf(fmaxf(rintf(n3 * sc), -128.f), 127.f));
    __nv_bfloat16* out = g_xq2 + (size_t)row * DIMC + tid * 4;
    *(__nv_bfloat162*)(out)     = p0;
    *(__nv_bfloat162*)(out + 2) = p1;
}

// ---------------- bf16 HMMA GEMM, double-buffered smem ----------------
// C[M,N] = A[M,1024] @ W[N,1024]^T * (adeq[m]*wdeq) + bias[n]
#define GLD 72
#define GEMM_SMEM (2 * 128 * GLD * 2 * 2 + 8 * 16 * 20 * 4)   // As+Bs (bf16, 2 bufs) + Cs (f32)
__global__ void __launch_bounds__(256) gemm_bf16(
    const __nv_bfloat16* __restrict__ A, const __nv_bfloat16* __restrict__ W,
    float* __restrict__ C, int N,
    const float* __restrict__ adeq, int wslot, const float* __restrict__ bias)
{
    extern __shared__ __align__(16) char gsm[];
    __nv_bfloat16* As = (__nv_bfloat16*)gsm;                       // 2 x 128 x GLD
    __nv_bfloat16* Bs = As + 2 * 128 * GLD;                        // 2 x 128 x GLD
    float* CsAll = (float*)(Bs + 2 * 128 * GLD);                   // 8 x 16 x 20

    int tid = threadIdx.x;
    int wid = tid >> 5, lane = tid & 31;
    int wm = wid >> 2, wn = wid & 3;            // warp tile 64(M) x 32(N)
    int bm = blockIdx.y * 128;
    int bn = blockIdx.x * 128;
    float wdeq = g_wdeq[wslot];

    wmma::fragment<wmma::accumulator, 16, 16, 16, float> c[4][2];
    #pragma unroll
    for (int i = 0; i < 4; i++)
        #pragma unroll
        for (int j = 0; j < 2; j++) wmma::fill_fragment(c[i][j], 0.0f);

    int row = tid >> 1;                 // 0..127
    int off = (tid & 1) * 32;           // element offset within 64-wide K tile
    const __nv_bfloat16* Ag = A + (size_t)(bm + row) * 1024 + off;
    const __nv_bfloat16* Bg = W + (size_t)(bn + row) * 1024 + off;

    uint4 ra[4], rb[4];
    #pragma unroll
    for (int i = 0; i < 4; i++) {
        ra[i] = *(const uint4*)(Ag + i * 8);
        rb[i] = *(const uint4*)(Bg + i * 8);
    }

    for (int kt = 0; kt < 16; kt++) {
        int buf = kt & 1;
        __nv_bfloat16* as = As + buf * (128 * GLD);
        __nv_bfloat16* bs = Bs + buf * (128 * GLD);
        #pragma unroll
        for (int i = 0; i < 4; i++) {
            *(uint4*)(as + row * GLD + off + i * 8) = ra[i];
            *(uint4*)(bs + row * GLD + off + i * 8) = rb[i];
        }
        if (kt < 15) {
            int kn = (kt + 1) * 64;
            #pragma unroll
            for (int i = 0; i < 4; i++) {
                ra[i] = *(const uint4*)(Ag + kn + i * 8);
                rb[i] = *(const uint4*)(Bg + kn + i * 8);
            }
        }
        __syncthreads();
        int m0 = wm * 64, n0 = wn * 32;
        #pragma unroll
        for (int sk = 0; sk < 4; sk++) {
            int k0 = sk * 16;
            wmma::fragment<wmma::matrix_a, 16, 16, 16, __nv_bfloat16, wmma::row_major> af[4];
            wmma::fragment<wmma::matrix_b, 16, 16, 16, __nv_bfloat16, wmma::col_major> bf[2];
            #pragma unroll
            for (int i = 0; i < 4; i++)
                wmma::load_matrix_sync(af[i], &as[(m0 + i * 16) * GLD + k0], GLD);
            #pragma unroll
            for (int j = 0; j < 2; j++)
                wmma::load_matrix_sync(bf[j], &bs[(n0 + j * 16) * GLD + k0], GLD);
            #pragma unroll
            for (int i = 0; i < 4; i++)
                #pragma unroll
                for (int j = 0; j < 2; j++)
                    wmma::mma_sync(c[i][j], af[i], bf[j], c[i][j]);
        }
        // double-buffered: no trailing sync needed
    }

    float* Csw = &CsAll[wid * 320];
    #pragma unroll
    for (int i = 0; i < 4; i++) {
        #pragma unroll
        for (int j = 0; j < 2; j++) {
            __syncwarp();
            wmma::store_matrix_sync(Csw, c[i][j], 20, wmma::mem_row_major);
            __syncwarp();
            int r  = lane >> 1;
            int cc = (lane & 1) * 8;
            int grow = bm + wm * 64 + i * 16 + r;
            int gcol = bn + wn * 32 + j * 16 + cc;
            float sc = adeq[grow] * wdeq;
            float* dst = C + (size_t)grow * N + gcol;
            float4 o1, o2;
            o1.x = Csw[r*20+cc+0]*sc + bias[gcol+0];
            o1.y = Csw[r*20+cc+1]*sc + bias[gcol+1];
            o1.z = Csw[r*20+cc+2]*sc + bias[gcol+2];
            o1.w = Csw[r*20+cc+3]*sc + bias[gcol+3];
            o2.x = Csw[r*20+cc+4]*sc + bias[gcol+4];
            o2.y = Csw[r*20+cc+5]*sc + bias[gcol+5];
            o2.z = Csw[r*20+cc+6]*sc + bias[gcol+6];
            o2.w = Csw[r*20+cc+7]*sc + bias[gcol+7];
            *(float4*)(dst)     = o1;
            *(float4*)(dst + 4) = o2;
        }
    }
}

// ---------------- rope + split ----------------
__global__ void __launch_bounds__(256) rope_split(const float* __restrict__ cosb,
                                                  const float* __restrict__ sinb) {
    int idx = blockIdx.x * 256 + threadIdx.x;
    int i = idx & 31;
    int tmp = idx >> 5;
    int h = tmp & 15;
    int row = tmp >> 4;
    int b = row >> 13, n = row & 8191;
    int t = n >> 7, r = n & 127;
    const float* src = g_qkv + (size_t)row * QKVN + h * 64 + 2 * i;
    float2 q2 = *(const float2*)(src);
    float2 k2 = *(const float2*)(src + 1024);
    float2 v2 = *(const float2*)(src + 2048);
    float c = cosb[n * 32 + i], s = sinb[n * 32 + i];
    float2 qo = make_float2(q2.x * c - q2.y * s, q2.y * c + q2.x * s);
    float2 ko = make_float2(k2.x * c - k2.y * s, k2.y * c + k2.x * s);
    size_t dst = (((size_t)b * NH + h) * NT + t) * (CHUNK * HD) + r * 64 + 2 * i;
    *(float2*)(g_q + dst) = qo;
    *(float2*)(g_k + dst) = ko;
    *(float2*)(g_v + dst) = v2;
}

// ---------------- intra-chunk attention (split-bf16 tensor cores) ----------------
#define QHI_OFF 0
#define QLO_OFF (128*72)
#define KHI_OFF (2*128*72)
#define KLO_OFF (3*128*72)
#define PHI_OFF (4*128*72)
#define PLO_OFF (4*128*72 + 128*136)
#define BF_TOTAL (4*128*72 + 2*128*136)
#define SS_LD 132

__global__ void __launch_bounds__(512) attn_intra() {
    int t = blockIdx.x, h = blockIdx.y, b = blockIdx.z;
    extern __shared__ __align__(16) char smraw[];
    __nv_bfloat16* bfm = (__nv_bfloat16*)smraw;
    float* sS = (float*)(smraw + (size_t)BF_TOTAL * 2);
    float* rowsum = sS + 128 * SS_LD;

    __nv_bfloat16* sQhi = bfm + QHI_OFF;
    __nv_bfloat16* sQlo = bfm + QLO_OFF;
    __nv_bfloat16* sKhi = bfm + KHI_OFF;
    __nv_bfloat16* sKlo = bfm + KLO_OFF;
    __nv_bfloat16* sPhi = bfm + PHI_OFF;
    __nv_bfloat16* sPlo = bfm + PLO_OFF;
    __nv_bfloat16* sVhi = sQhi;
    __nv_bfloat16* sVlo = sQlo;

    size_t base = (((size_t)b * NH + h) * NT + t) * (CHUNK * HD);
    int tid = threadIdx.x;
    int wid = tid >> 5;

    #pragma unroll
    for (int u = 0; u < 4; u++) {
        int i = tid + u * 512;
        int r = i >> 4, c4 = (i & 15) * 4;
        float4 qv = *(const float4*)(g_q + base + (size_t)r * 64 + c4);
        float4 kv = *(const float4*)(g_k + base + (size_t)r * 64 + c4);
        __nv_bfloat16 hi, lo;
        split2(qv.x, hi, lo); sQhi[r*72+c4+0]=hi; sQlo[r*72+c4+0]=lo;
        split2(qv.y, hi, lo); sQhi[r*72+c4+1]=hi; sQlo[r*72+c4+1]=lo;
        split2(qv.z, hi, lo); sQhi[r*72+c4+2]=hi; sQlo[r*72+c4+2]=lo;
        split2(qv.w, hi, lo); sQhi[r*72+c4+3]=hi; sQlo[r*72+c4+3]=lo;
        split2(kv.x, hi, lo); sKhi[r*72+c4+0]=hi; sKlo[r*72+c4+0]=lo;
        split2(kv.y, hi, lo); sKhi[r*72+c4+1]=hi; sKlo[r*72+c4+1]=lo;
        split2(kv.z, hi, lo); sKhi[r*72+c4+2]=hi; sKlo[r*72+c4+2]=lo;
        split2(kv.w, hi, lo); sKhi[r*72+c4+3]=hi; sKlo[r*72+c4+3]=lo;
    }
    __syncthreads();

    // QK^T: 16 warps, warp tile 16 rows x 64 cols
    {
        int r0 = (wid >> 1) * 16;
        int cbase = (wid & 1) * 64;
        wmma::fragment<wmma::accumulator, 16, 16, 16, float> c[4];
        #pragma unroll
        for (int j = 0; j < 4; j++) wmma::fill_fragment(c[j], 0.0f);
        #pragma unroll
        for (int sk = 0; sk < 4; sk++) {
            int k0 = sk * 16;
            wmma::fragment<wmma::matrix_a, 16, 16, 16, __nv_bfloat16, wmma::row_major> ah, al;
            wmma::load_matrix_sync(ah, &sQhi[r0 * 72 + k0], 72);
            wmma::load_matrix_sync(al, &sQlo[r0 * 72 + k0], 72);
            #pragma unroll
            for (int j = 0; j < 4; j++) {
                int col0 = cbase + j * 16;
                wmma::fragment<wmma::matrix_b, 16, 16, 16, __nv_bfloat16, wmma::col_major> bh, bl;
                wmma::load_matrix_sync(bh, &sKhi[col0 * 72 + k0], 72);
                wmma::load_matrix_sync(bl, &sKlo[col0 * 72 + k0], 72);
                wmma::mma_sync(c[j], ah, bh, c[j]);
                wmma::mma_sync(c[j], ah, bl, c[j]);
                wmma::mma_sync(c[j], al, bh, c[j]);
            }
        }
        #pragma unroll
        for (int j = 0; j < 4; j++) {
            #pragma unroll
            for (int e = 0; e < c[j].num_elements; e++) c[j].x[e] *= SCALE_ATTN;
            wmma::store_matrix_sync(&sS[r0 * SS_LD + cbase + j * 16], c[j], SS_LD, wmma::mem_row_major);
        }
    }
    __syncthreads();

    // softmax: 4 threads per row
    {
        int r = tid >> 2;
        int c0 = (tid & 3) * 32;
        float mx = -3.0e38f;
        for (int c = c0; c < c0 + 32; c++)
            if (c <= r) mx = fmaxf(mx, sS[r * SS_LD + c]);
        mx = fmaxf(mx, __shfl_xor_sync(0xffffffffu, mx, 1));
        mx = fmaxf(mx, __shfl_xor_sync(0xffffffffu, mx, 2));
        float sum = 0.f;
        for (int c = c0; c < c0 + 32; c++) {
            float e = (c <= r) ? fexp(sS[r * SS_LD + c] - mx) : 0.f;
            sum += e;
            __nv_bfloat16 hi, lo;
            split2(e, hi, lo);
            sPhi[r * 136 + c] = hi;
            sPlo[r * 136 + c] = lo;
        }
        sum += __shfl_xor_sync(0xffffffffu, sum, 1);
        sum += __shfl_xor_sync(0xffffffffu, sum, 2);
        if ((tid & 3) == 0) rowsum[r] = sum;
    }
    // V load into Q slots (Q dead; all warps past QK^T via sync above)
    #pragma unroll
    for (int u = 0; u < 4; u++) {
        int i = tid + u * 512;
        int r = i >> 4, c4 = (i & 15) * 4;
        float4 vv = *(const float4*)(g_v + base + (size_t)r * 64 + c4);
        __nv_bfloat16 hi, lo;
        split2(vv.x, hi, lo); sVhi[r*72+c4+0]=hi; sVlo[r*72+c4+0]=lo;
        split2(vv.y, hi, lo); sVhi[r*72+c4+1]=hi; sVlo[r*72+c4+1]=lo;
        split2(vv.z, hi, lo); sVhi[r*72+c4+2]=hi; sVlo[r*72+c4+2]=lo;
        split2(vv.w, hi, lo); sVhi[r*72+c4+3]=hi; sVlo[r*72+c4+3]=lo;
    }
    __syncthreads();

    // S_t = K^T V (64x64): one 16x16 tile per warp
    {
        int d0 = (wid >> 2) * 16;
        int e0 = (wid & 3) * 16;
        wmma::fragment<wmma::accumulator, 16, 16, 16, float> c;
        wmma::fill_fragment(c, 0.0f);
        #pragma unroll
        for (int sk = 0; sk < 8; sk++) {
            int r0 = sk * 16;
            wmma::fragment<wmma::matrix_a, 16, 16, 16, __nv_bfloat16, wmma::col_major> ah, al;
            wmma::fragment<wmma::matrix_b, 16, 16, 16, __nv_bfloat16, wmma::row_major> bh, bl;
            wmma::load_matrix_sync(ah, &sKhi[r0 * 72 + d0], 72);
            wmma::load_matrix_sync(al, &sKlo[r0 * 72 + d0], 72);
            wmma::load_matrix_sync(bh, &sVhi[r0 * 72 + e0], 72);
            wmma::load_matrix_sync(bl, &sVlo[r0 * 72 + e0], 72);
            wmma::mma_sync(c, ah, bh, c);
            wmma::mma_sync(c, ah, bl, c);
            wmma::mma_sync(c, al, bh, c);
        }
        size_t kb = (((size_t)b * NH + h) * NT + t) * (HD * HD);
        wmma::store_matrix_sync(g_kvsum + kb + (size_t)d0 * 64 + e0, c, 64, wmma::mem_row_major);
    }

    // o_intra = P @ V (128x64): warp tile 16x32
    {
        int r0 = (wid >> 1) * 16;
        int cbase = (wid & 1) * 32;
        wmma::fragment<wmma::accumulator, 16, 16, 16, float> c[2];
        #pragma unroll
        for (int j = 0; j < 2; j++) wmma::fill_fragment(c[j], 0.0f);
        #pragma unroll
        for (int sk = 0; sk < 8; sk++) {
            int k0 = sk * 16;
            wmma::fragment<wmma::matrix_a, 16, 16, 16, __nv_bfloat16, wmma::row_major> ah, al;
            wmma::load_matrix_sync(ah, &sPhi[r0 * 136 + k0], 136);
            wmma::load_matrix_sync(al, &sPlo[r0 * 136 + k0], 136);
            #pragma unroll
            for (int j = 0; j < 2; j++) {
                int col0 = cbase + j * 16;
                wmma::fragment<wmma::matrix_b, 16, 16, 16, __nv_bfloat16, wmma::row_major> bh, bl;
                wmma::load_matrix_sync(bh, &sVhi[k0 * 72 + col0], 72);
                wmma::load_matrix_sync(bl, &sVlo[k0 * 72 + col0], 72);
                wmma::mma_sync(c[j], ah, bh, c[j]);
                wmma::mma_sync(c[j], ah, bl, c[j]);
                wmma::mma_sync(c[j], al, bh, c[j]);
            }
        }
        __syncthreads();
        #pragma unroll
        for (int j = 0; j < 2; j++)
            wmma::store_matrix_sync(&sS[r0 * SS_LD + cbase + j * 16], c[j], SS_LD, wmma::mem_row_major);
    }
    __syncthreads();

    #pragma unroll
    for (int u = 0; u < 4; u++) {
        int i = tid + u * 512;
        int r = i >> 4, c4 = (i & 15) * 4;
        float inv = 1.0f / rowsum[r];
        float4 o;
        o.x = sS[r * SS_LD + c4 + 0] * inv;
        o.y = sS[r * SS_LD + c4 + 1] * inv;
        o.z = sS[r * SS_LD + c4 + 2] * inv;
        o.w = sS[r * SS_LD + c4 + 3] * inv;
        size_t grow = (size_t)b * SEQ + (size_t)t * CHUNK + r;
        *(float4*)(g_attn + grow * DIMC + h * 64 + c4) = o;
    }
}

// ---------------- exclusive prefix-sum of chunk KV matrices ----------------
__global__ void __launch_bounds__(256) kv_prefix() {
    int bh = blockIdx.x;
    int tid = threadIdx.x;
    size_t base = (size_t)bh * NT * (HD * HD);
    float acc[16];
    #pragma unroll
    for (int c = 0; c < 16; c++) acc[c] = 0.f;
    for (int t = 0; t < NT; t++) {
        size_t p = base + (size_t)t * (HD * HD);
        #pragma unroll
        for (int c = 0; c < 16; c++) {
            size_t off = p + c * 256 + tid;
            float v = g_kvsum[off];
            g_kvpre[off] = acc[c];
            acc[c] += v;
        }
    }
}

// ---------------- o_inter = q @ kv_prefix ----------------
#define IQHI 0
#define IQLO (128*72)
#define IKHI (2*128*72)
#define IKLO (2*128*72 + 64*72)
#define IBF_TOTAL (2*128*72 + 2*64*72)
__global__ void __launch_bounds__(256) attn_inter() {
    int t = blockIdx.x, h = blockIdx.y, b = blockIdx.z;
    extern __shared__ __align__(16) char smraw2[];
    __nv_bfloat16* bfm = (__nv_bfloat16*)smraw2;
    float* sO = (float*)(smraw2 + (size_t)IBF_TOTAL * 2);

    __nv_bfloat16* sQhi = bfm + IQHI;
    __nv_bfloat16* sQlo = bfm + IQLO;
    __nv_bfloat16* sKhi = bfm + IKHI;
    __nv_bfloat16* sKlo = bfm + IKLO;

    size_t base = (((size_t)b * NH + h) * NT + t) * (CHUNK * HD);
    size_t kb   = (((size_t)b * NH + h) * NT + t) * (HD * HD);
    int tid = threadIdx.x;
    int wid = tid >> 5;

    #pragma unroll
    for (int u = 0; u < 8; u++) {
        int i = tid + u * 256;
        int r = i >> 4, c4 = (i & 15) * 4;
        float4 qv = *(const float4*)(g_q + base + (size_t)r * 64 + c4);
        __nv_bfloat16 hi, lo;
        split2(qv.x, hi, lo); sQhi[r*72+c4+0]=hi; sQlo[r*72+c4+0]=lo;
        split2(qv.y, hi, lo); sQhi[r*72+c4+1]=hi; sQlo[r*72+c4+1]=lo;
        split2(qv.z, hi, lo); sQhi[r*72+c4+2]=hi; sQlo[r*72+c4+2]=lo;
        split2(qv.w, hi, lo); sQhi[r*72+c4+3]=hi; sQlo[r*72+c4+3]=lo;
    }
    #pragma unroll
    for (int u = 0; u < 4; u++) {
        int i = tid + u * 256;
        int r = i >> 4, c4 = (i & 15) * 4;
        float4 kv = *(const float4*)(g_kvpre + kb + (size_t)r * 64 + c4);
        __nv_bfloat16 hi, lo;
        split2(kv.x, hi, lo); sKhi[r*72+c4+0]=hi; sKlo[r*72+c4+0]=lo;
        split2(kv.y, hi, lo); sKhi[r*72+c4+1]=hi; sKlo[r*72+c4+1]=lo;
        split2(kv.z, hi, lo); sKhi[r*72+c4+2]=hi; sKlo[r*72+c4+2]=lo;
        split2(kv.w, hi, lo); sKhi[r*72+c4+3]=hi; sKlo[r*72+c4+3]=lo;
    }
    __syncthreads();

    {
        int r0 = wid * 16;
        wmma::fragment<wmma::accumulator, 16, 16, 16, float> c[4];
        #pragma unroll
        for (int j = 0; j < 4; j++) wmma::fill_fragment(c[j], 0.0f);
        #pragma unroll
        for (int sk = 0; sk < 4; sk++) {
            int k0 = sk * 16;
            wmma::fragment<wmma::matrix_a, 16, 16, 16, __nv_bfloat16, wmma::row_major> ah, al;
            wmma::load_matrix_sync(ah, &sQhi[r0 * 72 + k0], 72);
            wmma::load_matrix_sync(al, &sQlo[r0 * 72 + k0], 72);
            #pragma unroll
            for (int j = 0; j < 4; j++) {
                int col0 = j * 16;
                wmma::fragment<wmma::matrix_b, 16, 16, 16, __nv_bfloat16, wmma::row_major> bh, bl;
                wmma::load_matrix_sync(bh, &sKhi[k0 * 72 + col0], 72);
                wmma::load_matrix_sync(bl, &sKlo[k0 * 72 + col0], 72);
                wmma::mma_sync(c[j], ah, bh, c[j]);
                wmma::mma_sync(c[j], ah, bl, c[j]);
                wmma::mma_sync(c[j], al, bh, c[j]);
            }
        }
        #pragma unroll
        for (int j = 0; j < 4; j++)
            wmma::store_matrix_sync(&sO[r0 * 68 + j * 16], c[j], 68, wmma::mem_row_major);
    }
    __syncthreads();

    #pragma unroll
    for (int u = 0; u < 8; u++) {
        int i = tid + u * 256;
        int r = i >> 4, c4 = (i & 15) * 4;
        size_t grow = (size_t)b * SEQ + (size_t)t * CHUNK + r;
        float* dst = g_attn + grow * DIMC + h * 64 + c4;
        float4 old = *(float4*)dst;
        old.x += sO[r * 68 + c4 + 0];
        old.y += sO[r * 68 + c4 + 1];
        old.z += sO[r * 68 + c4 + 2];
        old.w += sO[r * 68 + c4 + 3];
        *(float4*)dst = old;
    }
}

// ---------------- launch ----------------
extern "C" void kernel_launch(void* const* d_in, const int* in_sizes, int n_in,
                              void* d_out, int out_size) {
    const float* x       = (const float*)d_in[0];
    const float* cosb    = (const float*)d_in[1];
    const float* sinb    = (const float*)d_in[2];
    const float* qkv_w   = (const float*)d_in[3];
    const float* qkv_b   = (const float*)d_in[4];
    const float* qkv_nw  = (const float*)d_in[5];
    const float* proj_w  = (const float*)d_in[6];
    const float* proj_b  = (const float*)d_in[7];
    const float* proj_nw = (const float*)d_in[8];
    const float* norm_w  = (const float*)d_in[9];
    float* out = (float*)d_out;

    size_t smem_intra = (size_t)BF_TOTAL * 2 + (128 * SS_LD + 128) * sizeof(float);
    size_t smem_inter = (size_t)IBF_TOTAL * 2 + (128 * 68) * sizeof(float);

    static bool attr_done = false;
    if (!attr_done) {
        cudaFuncSetAttribute(attn_intra, cudaFuncAttributeMaxDynamicSharedMemorySize, (int)smem_intra);
        cudaFuncSetAttribute(attn_inter, cudaFuncAttributeMaxDynamicSharedMemorySize, (int)smem_inter);
        cudaFuncSetAttribute(gemm_bf16,  cudaFuncAttributeMaxDynamicSharedMemorySize, GEMM_SMEM);
        attr_done = true;
    }

    __nv_bfloat16 *xq_p, *wqkv_p, *wproj_p, *xq2_p;
    float *qkv_p, *adeq_p, *adeq2_p;
    cudaGetSymbolAddress((void**)&xq_p,    g_xq);
    cudaGetSymbolAddress((void**)&wqkv_p,  g_wq_qkv);
    cudaGetSymbolAddress((void**)&wproj_p, g_wq_proj);
    cudaGetSymbolAddress((void**)&xq2_p,   g_xq2);
    cudaGetSymbolAddress((void**)&qkv_p,   g_qkv);
    cudaGetSymbolAddress((void**)&adeq_p,  g_adeq);
    cudaGetSymbolAddress((void**)&adeq2_p, g_adeq2);

    // Launch order arranged so gemm1 is the 6th launch (ncu -s 5 -c 1 capture slot).
    absmean_partial<<<256, 256>>>(qkv_w, QKVN * DIMC);                               // 1
    absmean_final<<<1, 256>>>(QKVN * DIMC, 0);                                       // 2
    quant_weight<<<(QKVN * DIMC / 4 + 255) / 256, 256>>>(qkv_w, wqkv_p, QKVN * DIMC, 0); // 3
    act_quant_x<<<NROWS, 256>>>(x, qkv_nw);                                          // 4
    absmean_partial<<<256, 256>>>(proj_w, DIMC * DIMC);                              // 5
    {
        dim3 grid(QKVN / 128, NROWS / 128);
        gemm_bf16<<<grid, 256, GEMM_SMEM>>>(xq_p, wqkv_p, qkv_p, QKVN, adeq_p, 0, qkv_b); // 6 <- profiled
    }
    absmean_final<<<1, 256>>>(DIMC * DIMC, 1);
    quant_weight<<<(DIMC * DIMC / 4 + 255) / 256, 256>>>(proj_w, wproj_p, DIMC * DIMC, 1);

    rope_split<<<(NROWS * NH * 32) / 256, 256>>>(cosb, sinb);

    {
        dim3 grid(NT, NH, BATCH);
        attn_intra<<<grid, 512, smem_intra>>>();
    }
    kv_prefix<<<BATCH * NH, 256>>>();
    {
        dim3 grid(NT, NH, BATCH);
        attn_inter<<<grid, 256, smem_inter>>>();
    }

    norm2_quant<<<NROWS, 256>>>(norm_w, proj_nw);
    {
        dim3 grid(DIMC / 128, NROWS / 128);
        gemm_bf16<<<grid, 256, GEMM_SMEM>>>(xq2_p, wproj_p, out, DIMC, adeq2_p, 1, proj_b);
    }
}

// round 6
// speedup vs baseline: 1.8856x; 1.0606x over previous
#include <cuda_runtime.h>
#include <cuda_bf16.h>
#include <mma.h>
#include <cstdint>

using namespace nvcuda;

#define BATCH 2
#define SEQ   8192
#define DIMC  1024
#define NH    16
#define HD    64
#define CHUNK 128
#define NT    64
#define NROWS 16384
#define QKVN  3072
#define SCALE_ATTN 0.125f
#define EPS_BIT 1.1920929e-07f
#define EPS_OUT 1e-06f

// ---------------- static device scratch ----------------
__device__ __nv_bfloat16 g_xq[(size_t)NROWS * DIMC];
__device__ float         g_adeq[NROWS];
__device__ __nv_bfloat16 g_wq_qkv[(size_t)QKVN * DIMC];
__device__ __nv_bfloat16 g_wq_proj[(size_t)DIMC * DIMC];
__device__ float         g_wdeq[2];
__device__ float         g_part[256];
__device__ float         g_q[(size_t)BATCH * NH * NT * CHUNK * HD];
__device__ float         g_k[(size_t)BATCH * NH * NT * CHUNK * HD];
__device__ float         g_v[(size_t)BATCH * NH * NT * CHUNK * HD];
__device__ float         g_kvsum[(size_t)BATCH * NH * NT * HD * HD];
__device__ float         g_kvpre[(size_t)BATCH * NH * NT * HD * HD];
__device__ float         g_attn[(size_t)NROWS * DIMC];
__device__ __nv_bfloat16 g_xq2[(size_t)NROWS * DIMC];
__device__ float         g_adeq2[NROWS];

// ---------------- helpers ----------------
__device__ __forceinline__ float fexp(float x) {
    x = fmaxf(x, -80.0f);
    float y = x * 1.4426950408889634f;
    float n = rintf(y);
    float g = fmaf(-n, 0.6931471805599453f, x);
    float p = 1.9841270e-4f;
    p = fmaf(p, g, 1.3888889e-3f);
    p = fmaf(p, g, 8.3333333e-3f);
    p = fmaf(p, g, 4.1666667e-2f);
    p = fmaf(p, g, 1.6666667e-1f);
    p = fmaf(p, g, 5.0e-1f);
    p = fmaf(p, g, 1.0f);
    p = fmaf(p, g, 1.0f);
    float s = __int_as_float(((int)n + 127) << 23);
    return p * s;
}

__device__ __forceinline__ void split2(float v, __nv_bfloat16& hi, __nv_bfloat16& lo) {
    hi = __float2bfloat16(v);
    lo = __float2bfloat16(v - __bfloat162float(hi));
}

// split a float4 into hi/lo bf16 pairs (for vectorized smem stores)
__device__ __forceinline__ void split4(float4 v,
    __nv_bfloat162& h01, __nv_bfloat162& l01,
    __nv_bfloat162& h23, __nv_bfloat162& l23) {
    h01.x = __float2bfloat16(v.x); l01.x = __float2bfloat16(v.x - __bfloat162float(h01.x));
    h01.y = __float2bfloat16(v.y); l01.y = __float2bfloat16(v.y - __bfloat162float(h01.y));
    h23.x = __float2bfloat16(v.z); l23.x = __float2bfloat16(v.z - __bfloat162float(h23.x));
    h23.y = __float2bfloat16(v.w); l23.y = __float2bfloat16(v.w - __bfloat162float(h23.y));
}

// ---------------- weight quant (2-launch pipeline) ----------------
__global__ void absmean_partial(const float* __restrict__ w, int n) {
    __shared__ float red[256];
    int tid = threadIdx.x;
    float s = 0.f;
    for (int i = blockIdx.x * 256 + tid; i < n; i += 65536) s += fabsf(w[i]);
    red[tid] = s; __syncthreads();
    for (int st = 128; st > 0; st >>= 1) { if (tid < st) red[tid] += red[tid + st]; __syncthreads(); }
    if (tid == 0) g_part[blockIdx.x] = red[0];
}

// every block re-reduces the 256 partials (1KB, deterministic), quantizes its slice
__global__ void __launch_bounds__(256) quant_weight_fused(const float* __restrict__ w,
                                                          __nv_bfloat16* __restrict__ wq,
                                                          int n, int slot) {
    __shared__ float red[256];
    int tid = threadIdx.x;
    red[tid] = g_part[tid]; __syncthreads();
    for (int st = 128; st > 0; st >>= 1) { if (tid < st) red[tid] += red[tid + st]; __syncthreads(); }
    float wdeq = fmaxf(red[0] / (float)n, 1e-5f);
    if (blockIdx.x == 0 && tid == 0) g_wdeq[slot] = wdeq;
    float s = 1.0f / wdeq;
    int i4 = (blockIdx.x * 256 + tid) * 4;
    if (i4 >= n) return;
    float4 wv = *(const float4*)(w + i4);
    __nv_bfloat162 p0, p1;
    p0.x = __float2bfloat16(fminf(fmaxf(rintf(wv.x * s), -1.f), 1.f));
    p0.y = __float2bfloat16(fminf(fmaxf(rintf(wv.y * s), -1.f), 1.f));
    p1.x = __float2bfloat16(fminf(fmaxf(rintf(wv.z * s), -1.f), 1.f));
    p1.y = __float2bfloat16(fminf(fmaxf(rintf(wv.w * s), -1.f), 1.f));
    *(__nv_bfloat162*)(wq + i4)     = p0;
    *(__nv_bfloat162*)(wq + i4 + 2) = p1;
}

// ---------------- activation quant for QKV input ----------------
__global__ void __launch_bounds__(256) act_quant_x(const float* __restrict__ x,
                                                   const float* __restrict__ nw) {
    __shared__ float red[256];
    __shared__ float bc;
    int row = blockIdx.x, tid = threadIdx.x;
    float4 xv = ((const float4*)(x + (size_t)row * DIMC))[tid];
    float4 wv = ((const float4*)nw)[tid];
    float ss = xv.x*xv.x + xv.y*xv.y + xv.z*xv.z + xv.w*xv.w;
    red[tid] = ss; __syncthreads();
    for (int st = 128; st > 0; st >>= 1) { if (tid < st) red[tid] += red[tid + st]; __syncthreads(); }
    if (tid == 0) bc = rsqrtf(red[0] * (1.0f / DIMC) + EPS_BIT);
    __syncthreads();
    float r = bc;
    float n0 = xv.x*r*wv.x, n1 = xv.y*r*wv.y, n2 = xv.z*r*wv.z, n3 = xv.w*r*wv.w;
    float amax = fmaxf(fmaxf(fabsf(n0), fabsf(n1)), fmaxf(fabsf(n2), fabsf(n3)));
    red[tid] = amax; __syncthreads();
    for (int st = 128; st > 0; st >>= 1) { if (tid < st) red[tid] = fmaxf(red[tid], red[tid + st]); __syncthreads(); }
    if (tid == 0) {
        float mx = fmaxf(red[0], 1e-5f);
        bc = 127.0f / mx;
        g_adeq[row] = mx * (1.0f / 127.0f);
    }
    __syncthreads();
    float sc = bc;
    __nv_bfloat162 p0, p1;
    p0.x = __float2bfloat16(fminf(fmaxf(rintf(n0 * sc), -128.f), 127.f));
    p0.y = __float2bfloat16(fminf(fmaxf(rintf(n1 * sc), -128.f), 127.f));
    p1.x = __float2bfloat16(fminf(fmaxf(rintf(n2 * sc), -128.f), 127.f));
    p1.y = __float2bfloat16(fminf(fmaxf(rintf(n3 * sc), -128.f), 127.f));
    __nv_bfloat16* out = g_xq + (size_t)row * DIMC + tid * 4;
    *(__nv_bfloat162*)(out)     = p0;
    *(__nv_bfloat162*)(out + 2) = p1;
}

// ---------------- double-norm + act quant for proj input ----------------
__global__ void __launch_bounds__(256) norm2_quant(const float* __restrict__ nw,
                                                   const float* __restrict__ pnw) {
    __shared__ float red[256];
    __shared__ float bc;
    int row = blockIdx.x, tid = threadIdx.x;
    float4 xv = ((const float4*)(g_attn + (size_t)row * DIMC))[tid];
    float4 wv = ((const float4*)nw)[tid];
    float4 pv = ((const float4*)pnw)[tid];
    float ss = xv.x*xv.x + xv.y*xv.y + xv.z*xv.z + xv.w*xv.w;
    red[tid] = ss; __syncthreads();
    for (int st = 128; st > 0; st >>= 1) { if (tid < st) red[tid] += red[tid + st]; __syncthreads(); }
    if (tid == 0) bc = rsqrtf(red[0] * (1.0f / DIMC) + EPS_OUT);
    __syncthreads();
    float r1 = bc;
    float z0 = xv.x*r1*wv.x, z1 = xv.y*r1*wv.y, z2 = xv.z*r1*wv.z, z3 = xv.w*r1*wv.w;
    float ss2 = z0*z0 + z1*z1 + z2*z2 + z3*z3;
    red[tid] = ss2; __syncthreads();
    for (int st = 128; st > 0; st >>= 1) { if (tid < st) red[tid] += red[tid + st]; __syncthreads(); }
    if (tid == 0) bc = rsqrtf(red[0] * (1.0f / DIMC) + EPS_BIT);
    __syncthreads();
    float r2 = bc;
    float n0 = z0*r2*pv.x, n1 = z1*r2*pv.y, n2 = z2*r2*pv.z, n3 = z3*r2*pv.w;
    float amax = fmaxf(fmaxf(fabsf(n0), fabsf(n1)), fmaxf(fabsf(n2), fabsf(n3)));
    red[tid] = amax; __syncthreads();
    for (int st = 128; st > 0; st >>= 1) { if (tid < st) red[tid] = fmaxf(red[tid], red[tid + st]); __syncthreads(); }
    if (tid == 0) {
        float mx = fmaxf(red[0], 1e-5f);
        bc = 127.0f / mx;
        g_adeq2[row] = mx * (1.0f / 127.0f);
    }
    __syncthreads();
    float sc = bc;
    __nv_bfloat162 p0, p1;
    p0.x = __float2bfloat16(fminf(fmaxf(rintf(n0 * sc), -128.f), 127.f));
    p0.y = __float2bfloat16(fminf(fmaxf(rintf(n1 * sc), -128.f), 127.f));
    p1.x = __float2bfloat16(fminf(fmaxf(rintf(n2 * sc), -128.f), 127.f));
    p1.y = __float2bfloat16(fminf(fmaxf(rintf(n3 * sc), -128.f), 127.f));
    __nv_bfloat16* out = g_xq2 + (size_t)row * DIMC + tid * 4;
    *(__nv_bfloat162*)(out)     = p0;
    *(__nv_bfloat162*)(out + 2) = p1;
}

// ---------------- bf16 HMMA GEMM, double-buffered; QKV variant fuses rope+split ----------------
#define GLD 72
#define GEMM_SMEM (2 * 128 * GLD * 2 * 2 + 8 * 16 * 20 * 4)
template<bool QKV>
__global__ void __launch_bounds__(256) gemm_bf16_t(
    const __nv_bfloat16* __restrict__ A, const __nv_bfloat16* __restrict__ W,
    float* __restrict__ C, int N,
    const float* __restrict__ adeq, int wslot, const float* __restrict__ bias,
    const float* __restrict__ cosb, const float* __restrict__ sinb)
{
    extern __shared__ __align__(16) char gsm[];
    __nv_bfloat16* As = (__nv_bfloat16*)gsm;
    __nv_bfloat16* Bs = As + 2 * 128 * GLD;
    float* CsAll = (float*)(Bs + 2 * 128 * GLD);

    int tid = threadIdx.x;
    int wid = tid >> 5, lane = tid & 31;
    int wm = wid >> 2, wn = wid & 3;            // warp tile 64(M) x 32(N)
    int bm = blockIdx.y * 128;
    int bn = blockIdx.x * 128;
    float wdeq = g_wdeq[wslot];

    wmma::fragment<wmma::accumulator, 16, 16, 16, float> c[4][2];
    #pragma unroll
    for (int i = 0; i < 4; i++)
        #pragma unroll
        for (int j = 0; j < 2; j++) wmma::fill_fragment(c[i][j], 0.0f);

    int row = tid >> 1;
    int off = (tid & 1) * 32;
    const __nv_bfloat16* Ag = A + (size_t)(bm + row) * 1024 + off;
    const __nv_bfloat16* Bg = W + (size_t)(bn + row) * 1024 + off;

    uint4 ra[4], rb[4];
    #pragma unroll
    for (int i = 0; i < 4; i++) {
        ra[i] = *(const uint4*)(Ag + i * 8);
        rb[i] = *(const uint4*)(Bg + i * 8);
    }

    for (int kt = 0; kt < 16; kt++) {
        int buf = kt & 1;
        __nv_bfloat16* as = As + buf * (128 * GLD);
        __nv_bfloat16* bs = Bs + buf * (128 * GLD);
        #pragma unroll
        for (int i = 0; i < 4; i++) {
            *(uint4*)(as + row * GLD + off + i * 8) = ra[i];
            *(uint4*)(bs + row * GLD + off + i * 8) = rb[i];
        }
        if (kt < 15) {
            int kn = (kt + 1) * 64;
            #pragma unroll
            for (int i = 0; i < 4; i++) {
                ra[i] = *(const uint4*)(Ag + kn + i * 8);
                rb[i] = *(const uint4*)(Bg + kn + i * 8);
            }
        }
        __syncthreads();
        int m0 = wm * 64, n0 = wn * 32;
        #pragma unroll
        for (int sk = 0; sk < 4; sk++) {
            int k0 = sk * 16;
            wmma::fragment<wmma::matrix_a, 16, 16, 16, __nv_bfloat16, wmma::row_major> af[4];
            wmma::fragment<wmma::matrix_b, 16, 16, 16, __nv_bfloat16, wmma::col_major> bf[2];
            #pragma unroll
            for (int i = 0; i < 4; i++)
                wmma::load_matrix_sync(af[i], &as[(m0 + i * 16) * GLD + k0], GLD);
            #pragma unroll
            for (int j = 0; j < 2; j++)
                wmma::load_matrix_sync(bf[j], &bs[(n0 + j * 16) * GLD + k0], GLD);
            #pragma unroll
            for (int i = 0; i < 4; i++)
                #pragma unroll
                for (int j = 0; j < 2; j++)
                    wmma::mma_sync(c[i][j], af[i], bf[j], c[i][j]);
        }
        __syncthreads();
    }

    float* Csw = &CsAll[wid * 320];
    #pragma unroll
    for (int i = 0; i < 4; i++) {
        #pragma unroll
        for (int j = 0; j < 2; j++) {
            __syncwarp();
            wmma::store_matrix_sync(Csw, c[i][j], 20, wmma::mem_row_major);
            __syncwarp();
            int r  = lane >> 1;
            int cc = (lane & 1) * 8;
            int grow = bm + wm * 64 + i * 16 + r;
            int gcol = bn + wn * 32 + j * 16 + cc;
            float sc = adeq[grow] * wdeq;
            float v[8];
            #pragma unroll
            for (int u = 0; u < 8; u++)
                v[u] = Csw[r * 20 + cc + u] * sc + bias[gcol + u];
            if (QKV) {
                // epilogue: rope + split into chunked per-head q/k/v
                int which = gcol >> 10;
                int rem = gcol & 1023;
                int h = rem >> 6, d = rem & 63;
                int b = grow >> 13, n = grow & 8191;
                int t = n >> 7, rr = n & 127;
                if (which < 2) {
                    int i0 = d >> 1;
                    #pragma unroll
                    for (int m = 0; m < 4; m++) {
                        float cth = cosb[n * 32 + i0 + m];
                        float sth = sinb[n * 32 + i0 + m];
                        float e = v[2*m], o = v[2*m+1];
                        v[2*m]   = e * cth - o * sth;
                        v[2*m+1] = o * cth + e * sth;
                    }
                }
                float* dstbase = (which == 0) ? g_q : (which == 1) ? g_k : g_v;
                float* dst = dstbase + (((size_t)b * NH + h) * NT + t) * (CHUNK * HD)
                           + (size_t)rr * 64 + d;
                *(float4*)(dst)     = make_float4(v[0], v[1], v[2], v[3]);
                *(float4*)(dst + 4) = make_float4(v[4], v[5], v[6], v[7]);
            } else {
                float* dst = C + (size_t)grow * N + gcol;
                *(float4*)(dst)     = make_float4(v[0], v[1], v[2], v[3]);
                *(float4*)(dst + 4) = make_float4(v[4], v[5], v[6], v[7]);
            }
        }
    }
}

// ---------------- intra-chunk attention (split-bf16 tensor cores) ----------------
#define QHI_OFF 0
#define QLO_OFF (128*72)
#define KHI_OFF (2*128*72)
#define KLO_OFF (3*128*72)
#define PHI_OFF (4*128*72)
#define PLO_OFF (4*128*72 + 128*136)
#define BF_TOTAL (4*128*72 + 2*128*136)
#define SS_LD 132

__global__ void __launch_bounds__(512) attn_intra() {
    int t = blockIdx.x, h = blockIdx.y, b = blockIdx.z;
    extern __shared__ __align__(16) char smraw[];
    __nv_bfloat16* bfm = (__nv_bfloat16*)smraw;
    float* sS = (float*)(smraw + (size_t)BF_TOTAL * 2);
    float* rowsum = sS + 128 * SS_LD;

    __nv_bfloat16* sQhi = bfm + QHI_OFF;
    __nv_bfloat16* sQlo = bfm + QLO_OFF;
    __nv_bfloat16* sKhi = bfm + KHI_OFF;
    __nv_bfloat16* sKlo = bfm + KLO_OFF;
    __nv_bfloat16* sPhi = bfm + PHI_OFF;
    __nv_bfloat16* sPlo = bfm + PLO_OFF;
    __nv_bfloat16* sVhi = sQhi;
    __nv_bfloat16* sVlo = sQlo;

    size_t base = (((size_t)b * NH + h) * NT + t) * (CHUNK * HD);
    int tid = threadIdx.x;
    int wid = tid >> 5;

    #pragma unroll
    for (int u = 0; u < 4; u++) {
        int i = tid + u * 512;
        int r = i >> 4, c4 = (i & 15) * 4;
        float4 qv = *(const float4*)(g_q + base + (size_t)r * 64 + c4);
        float4 kv = *(const float4*)(g_k + base + (size_t)r * 64 + c4);
        __nv_bfloat162 h01, l01, h23, l23;
        split4(qv, h01, l01, h23, l23);
        *(__nv_bfloat162*)(sQhi + r*72 + c4)     = h01;
        *(__nv_bfloat162*)(sQhi + r*72 + c4 + 2) = h23;
        *(__nv_bfloat162*)(sQlo + r*72 + c4)     = l01;
        *(__nv_bfloat162*)(sQlo + r*72 + c4 + 2) = l23;
        split4(kv, h01, l01, h23, l23);
        *(__nv_bfloat162*)(sKhi + r*72 + c4)     = h01;
        *(__nv_bfloat162*)(sKhi + r*72 + c4 + 2) = h23;
        *(__nv_bfloat162*)(sKlo + r*72 + c4)     = l01;
        *(__nv_bfloat162*)(sKlo + r*72 + c4 + 2) = l23;
    }
    __syncthreads();

    // QK^T: 16 warps, warp tile 16 rows x 64 cols
    {
        int r0 = (wid >> 1) * 16;
        int cbase = (wid & 1) * 64;
        wmma::fragment<wmma::accumulator, 16, 16, 16, float> c[4];
        #pragma unroll
        for (int j = 0; j < 4; j++) wmma::fill_fragment(c[j], 0.0f);
        #pragma unroll
        for (int sk = 0; sk < 4; sk++) {
            int k0 = sk * 16;
            wmma::fragment<wmma::matrix_a, 16, 16, 16, __nv_bfloat16, wmma::row_major> ah, al;
            wmma::load_matrix_sync(ah, &sQhi[r0 * 72 + k0], 72);
            wmma::load_matrix_sync(al, &sQlo[r0 * 72 + k0], 72);
            #pragma unroll
            for (int j = 0; j < 4; j++) {
                int col0 = cbase + j * 16;
                wmma::fragment<wmma::matrix_b, 16, 16, 16, __nv_bfloat16, wmma::col_major> bh, bl;
                wmma::load_matrix_sync(bh, &sKhi[col0 * 72 + k0], 72);
                wmma::load_matrix_sync(bl, &sKlo[col0 * 72 + k0], 72);
                wmma::mma_sync(c[j], ah, bh, c[j]);
                wmma::mma_sync(c[j], ah, bl, c[j]);
                wmma::mma_sync(c[j], al, bh, c[j]);
            }
        }
        #pragma unroll
        for (int j = 0; j < 4; j++) {
            #pragma unroll
            for (int e = 0; e < c[j].num_elements; e++) c[j].x[e] *= SCALE_ATTN;
            wmma::store_matrix_sync(&sS[r0 * SS_LD + cbase + j * 16], c[j], SS_LD, wmma::mem_row_major);
        }
    }
    __syncthreads();

    // softmax: 4 threads per row
    {
        int r = tid >> 2;
        int c0 = (tid & 3) * 32;
        float mx = -3.0e38f;
        for (int c = c0; c < c0 + 32; c++)
            if (c <= r) mx = fmaxf(mx, sS[r * SS_LD + c]);
        mx = fmaxf(mx, __shfl_xor_sync(0xffffffffu, mx, 1));
        mx = fmaxf(mx, __shfl_xor_sync(0xffffffffu, mx, 2));
        float sum = 0.f;
        for (int c = c0; c < c0 + 32; c++) {
            float e = (c <= r) ? fexp(sS[r * SS_LD + c] - mx) : 0.f;
            sum += e;
            __nv_bfloat16 hi, lo;
            split2(e, hi, lo);
            sPhi[r * 136 + c] = hi;
            sPlo[r * 136 + c] = lo;
        }
        sum += __shfl_xor_sync(0xffffffffu, sum, 1);
        sum += __shfl_xor_sync(0xffffffffu, sum, 2);
        if ((tid & 3) == 0) rowsum[r] = sum;
    }
    // V load into Q slots (Q dead; all warps past QK^T via sync above)
    #pragma unroll
    for (int u = 0; u < 4; u++) {
        int i = tid + u * 512;
        int r = i >> 4, c4 = (i & 15) * 4;
        float4 vv = *(const float4*)(g_v + base + (size_t)r * 64 + c4);
        __nv_bfloat162 h01, l01, h23, l23;
        split4(vv, h01, l01, h23, l23);
        *(__nv_bfloat162*)(sVhi + r*72 + c4)     = h01;
        *(__nv_bfloat162*)(sVhi + r*72 + c4 + 2) = h23;
        *(__nv_bfloat162*)(sVlo + r*72 + c4)     = l01;
        *(__nv_bfloat162*)(sVlo + r*72 + c4 + 2) = l23;
    }
    __syncthreads();

    // S_t = K^T V (64x64): one 16x16 tile per warp
    {
        int d0 = (wid >> 2) * 16;
        int e0 = (wid & 3) * 16;
        wmma::fragment<wmma::accumulator, 16, 16, 16, float> c;
        wmma::fill_fragment(c, 0.0f);
        #pragma unroll
        for (int sk = 0; sk < 8; sk++) {
            int r0 = sk * 16;
            wmma::fragment<wmma::matrix_a, 16, 16, 16, __nv_bfloat16, wmma::col_major> ah, al;
            wmma::fragment<wmma::matrix_b, 16, 16, 16, __nv_bfloat16, wmma::row_major> bh, bl;
            wmma::load_matrix_sync(ah, &sKhi[r0 * 72 + d0], 72);
            wmma::load_matrix_sync(al, &sKlo[r0 * 72 + d0], 72);
            wmma::load_matrix_sync(bh, &sVhi[r0 * 72 + e0], 72);
            wmma::load_matrix_sync(bl, &sVlo[r0 * 72 + e0], 72);
            wmma::mma_sync(c, ah, bh, c);
            wmma::mma_sync(c, ah, bl, c);
            wmma::mma_sync(c, al, bh, c);
        }
        size_t kb = (((size_t)b * NH + h) * NT + t) * (HD * HD);
        wmma::store_matrix_sync(g_kvsum + kb + (size_t)d0 * 64 + e0, c, 64, wmma::mem_row_major);
    }

    // o_intra = P @ V (128x64): warp tile 16x32
    {
        int r0 = (wid >> 1) * 16;
        int cbase = (wid & 1) * 32;
        wmma::fragment<wmma::accumulator, 16, 16, 16, float> c[2];
        #pragma unroll
        for (int j = 0; j < 2; j++) wmma::fill_fragment(c[j], 0.0f);
        #pragma unroll
        for (int sk = 0; sk < 8; sk++) {
            int k0 = sk * 16;
            wmma::fragment<wmma::matrix_a, 16, 16, 16, __nv_bfloat16, wmma::row_major> ah, al;
            wmma::load_matrix_sync(ah, &sPhi[r0 * 136 + k0], 136);
            wmma::load_matrix_sync(al, &sPlo[r0 * 136 + k0], 136);
            #pragma unroll
            for (int j = 0; j < 2; j++) {
                int col0 = cbase + j * 16;
                wmma::fragment<wmma::matrix_b, 16, 16, 16, __nv_bfloat16, wmma::row_major> bh, bl;
                wmma::load_matrix_sync(bh, &sVhi[k0 * 72 + col0], 72);
                wmma::load_matrix_sync(bl, &sVlo[k0 * 72 + col0], 72);
                wmma::mma_sync(c[j], ah, bh, c[j]);
                wmma::mma_sync(c[j], ah, bl, c[j]);
                wmma::mma_sync(c[j], al, bh, c[j]);
            }
        }
        __syncthreads();
        #pragma unroll
        for (int j = 0; j < 2; j++)
            wmma::store_matrix_sync(&sS[r0 * SS_LD + cbase + j * 16], c[j], SS_LD, wmma::mem_row_major);
    }
    __syncthreads();

    #pragma unroll
    for (int u = 0; u < 4; u++) {
        int i = tid + u * 512;
        int r = i >> 4, c4 = (i & 15) * 4;
        float inv = 1.0f / rowsum[r];
        float4 o;
        o.x = sS[r * SS_LD + c4 + 0] * inv;
        o.y = sS[r * SS_LD + c4 + 1] * inv;
        o.z = sS[r * SS_LD + c4 + 2] * inv;
        o.w = sS[r * SS_LD + c4 + 3] * inv;
        size_t grow = (size_t)b * SEQ + (size_t)t * CHUNK + r;
        *(float4*)(g_attn + grow * DIMC + h * 64 + c4) = o;
    }
}

// ---------------- exclusive prefix-sum of chunk KV matrices (parallel over slices) ----------------
__global__ void __launch_bounds__(256) kv_prefix() {
    int blk = blockIdx.x;             // 256 blocks
    int bh = blk >> 3, s = blk & 7;   // 8 slices of 512 elements
    int tid = threadIdx.x;
    size_t base = (size_t)bh * NT * (HD * HD) + s * 512 + tid * 2;
    float2 acc = make_float2(0.f, 0.f);
    for (int t = 0; t < NT; t++) {
        size_t off = base + (size_t)t * (HD * HD);
        float2 v = *(const float2*)(g_kvsum + off);
        *(float2*)(g_kvpre + off) = acc;
        acc.x += v.x; acc.y += v.y;
    }
}

// ---------------- o_inter = q @ kv_prefix ----------------
#define IQHI 0
#define IQLO (128*72)
#define IKHI (2*128*72)
#define IKLO (2*128*72 + 64*72)
#define IBF_TOTAL (2*128*72 + 2*64*72)
__global__ void __launch_bounds__(256) attn_inter() {
    int t = blockIdx.x, h = blockIdx.y, b = blockIdx.z;
    extern __shared__ __align__(16) char smraw2[];
    __nv_bfloat16* bfm = (__nv_bfloat16*)smraw2;
    float* sO = (float*)(smraw2 + (size_t)IBF_TOTAL * 2);

    __nv_bfloat16* sQhi = bfm + IQHI;
    __nv_bfloat16* sQlo = bfm + IQLO;
    __nv_bfloat16* sKhi = bfm + IKHI;
    __nv_bfloat16* sKlo = bfm + IKLO;

    size_t base = (((size_t)b * NH + h) * NT + t) * (CHUNK * HD);
    size_t kb   = (((size_t)b * NH + h) * NT + t) * (HD * HD);
    int tid = threadIdx.x;
    int wid = tid >> 5;

    #pragma unroll
    for (int u = 0; u < 8; u++) {
        int i = tid + u * 256;
        int r = i >> 4, c4 = (i & 15) * 4;
        float4 qv = *(const float4*)(g_q + base + (size_t)r * 64 + c4);
        __nv_bfloat162 h01, l01, h23, l23;
        split4(qv, h01, l01, h23, l23);
        *(__nv_bfloat162*)(sQhi + r*72 + c4)     = h01;
        *(__nv_bfloat162*)(sQhi + r*72 + c4 + 2) = h23;
        *(__nv_bfloat162*)(sQlo + r*72 + c4)     = l01;
        *(__nv_bfloat162*)(sQlo + r*72 + c4 + 2) = l23;
    }
    #pragma unroll
    for (int u = 0; u < 4; u++) {
        int i = tid + u * 256;
        int r = i >> 4, c4 = (i & 15) * 4;
        float4 kv = *(const float4*)(g_kvpre + kb + (size_t)r * 64 + c4);
        __nv_bfloat162 h01, l01, h23, l23;
        split4(kv, h01, l01, h23, l23);
        *(__nv_bfloat162*)(sKhi + r*72 + c4)     = h01;
        *(__nv_bfloat162*)(sKhi + r*72 + c4 + 2) = h23;
        *(__nv_bfloat162*)(sKlo + r*72 + c4)     = l01;
        *(__nv_bfloat162*)(sKlo + r*72 + c4 + 2) = l23;
    }
    __syncthreads();

    {
        int r0 = wid * 16;
        wmma::fragment<wmma::accumulator, 16, 16, 16, float> c[4];
        #pragma unroll
        for (int j = 0; j < 4; j++) wmma::fill_fragment(c[j], 0.0f);
        #pragma unroll
        for (int sk = 0; sk < 4; sk++) {
            int k0 = sk * 16;
            wmma::fragment<wmma::matrix_a, 16, 16, 16, __nv_bfloat16, wmma::row_major> ah, al;
            wmma::load_matrix_sync(ah, &sQhi[r0 * 72 + k0], 72);
            wmma::load_matrix_sync(al, &sQlo[r0 * 72 + k0], 72);
            #pragma unroll
            for (int j = 0; j < 4; j++) {
                int col0 = j * 16;
                wmma::fragment<wmma::matrix_b, 16, 16, 16, __nv_bfloat16, wmma::row_major> bh, bl;
                wmma::load_matrix_sync(bh, &sKhi[k0 * 72 + col0], 72);
                wmma::load_matrix_sync(bl, &sKlo[k0 * 72 + col0], 72);
                wmma::mma_sync(c[j], ah, bh, c[j]);
                wmma::mma_sync(c[j], ah, bl, c[j]);
                wmma::mma_sync(c[j], al, bh, c[j]);
            }
        }
        #pragma unroll
        for (int j = 0; j < 4; j++)
            wmma::store_matrix_sync(&sO[r0 * 68 + j * 16], c[j], 68, wmma::mem_row_major);
    }
    __syncthreads();

    #pragma unroll
    for (int u = 0; u < 8; u++) {
        int i = tid + u * 256;
        int r = i >> 4, c4 = (i & 15) * 4;
        size_t grow = (size_t)b * SEQ + (size_t)t * CHUNK + r;
        float* dst = g_attn + grow * DIMC + h * 64 + c4;
        float4 old = *(float4*)dst;
        old.x += sO[r * 68 + c4 + 0];
        old.y += sO[r * 68 + c4 + 1];
        old.z += sO[r * 68 + c4 + 2];
        old.w += sO[r * 68 + c4 + 3];
        *(float4*)dst = old;
    }
}

// ---------------- launch ----------------
extern "C" void kernel_launch(void* const* d_in, const int* in_sizes, int n_in,
                              void* d_out, int out_size) {
    const float* x       = (const float*)d_in[0];
    const float* cosb    = (const float*)d_in[1];
    const float* sinb    = (const float*)d_in[2];
    const float* qkv_w   = (const float*)d_in[3];
    const float* qkv_b   = (const float*)d_in[4];
    const float* qkv_nw  = (const float*)d_in[5];
    const float* proj_w  = (const float*)d_in[6];
    const float* proj_b  = (const float*)d_in[7];
    const float* proj_nw = (const float*)d_in[8];
    const float* norm_w  = (const float*)d_in[9];
    float* out = (float*)d_out;

    size_t smem_intra = (size_t)BF_TOTAL * 2 + (128 * SS_LD + 128) * sizeof(float);
    size_t smem_inter = (size_t)IBF_TOTAL * 2 + (128 * 68) * sizeof(float);

    static bool attr_done = false;
    if (!attr_done) {
        cudaFuncSetAttribute(attn_intra, cudaFuncAttributeMaxDynamicSharedMemorySize, (int)smem_intra);
        cudaFuncSetAttribute(attn_inter, cudaFuncAttributeMaxDynamicSharedMemorySize, (int)smem_inter);
        cudaFuncSetAttribute(gemm_bf16_t<true>,  cudaFuncAttributeMaxDynamicSharedMemorySize, GEMM_SMEM);
        cudaFuncSetAttribute(gemm_bf16_t<false>, cudaFuncAttributeMaxDynamicSharedMemorySize, GEMM_SMEM);
        attr_done = true;
    }

    __nv_bfloat16 *xq_p, *wqkv_p, *wproj_p, *xq2_p;
    float *adeq_p, *adeq2_p;
    cudaGetSymbolAddress((void**)&xq_p,    g_xq);
    cudaGetSymbolAddress((void**)&wqkv_p,  g_wq_qkv);
    cudaGetSymbolAddress((void**)&wproj_p, g_wq_proj);
    cudaGetSymbolAddress((void**)&xq2_p,   g_xq2);
    cudaGetSymbolAddress((void**)&adeq_p,  g_adeq);
    cudaGetSymbolAddress((void**)&adeq2_p, g_adeq2);

    // Launch order: gemm<QKV> is my launch #4 -> ncu capture slot (-s 5, offset 2).
    absmean_partial<<<256, 256>>>(qkv_w, QKVN * DIMC);                                    // 1
    quant_weight_fused<<<QKVN * DIMC / 1024, 256>>>(qkv_w, wqkv_p, QKVN * DIMC, 0);       // 2
    act_quant_x<<<NROWS, 256>>>(x, qkv_nw);                                               // 3
    {
        dim3 grid(QKVN / 128, NROWS / 128);
        gemm_bf16_t<true><<<grid, 256, GEMM_SMEM>>>(xq_p, wqkv_p, nullptr, QKVN,
                                                    adeq_p, 0, qkv_b, cosb, sinb);        // 4 <- profiled
    }
    absmean_partial<<<256, 256>>>(proj_w, DIMC * DIMC);                                   // 5
    quant_weight_fused<<<DIMC * DIMC / 1024, 256>>>(proj_w, wproj_p, DIMC * DIMC, 1);     // 6

    {
        dim3 grid(NT, NH, BATCH);
        attn_intra<<<grid, 512, smem_intra>>>();                                          // 7
    }
    kv_prefix<<<256, 256>>>();                                                            // 8
    {
        dim3 grid(NT, NH, BATCH);
        attn_inter<<<grid, 256, smem_inter>>>();                                          // 9
    }

    norm2_quant<<<NROWS, 256>>>(norm_w, proj_nw);                                         // 10
    {
        dim3 grid(DIMC / 128, NROWS / 128);
        gemm_bf16_t<false><<<grid, 256, GEMM_SMEM>>>(xq2_p, wproj_p, out, DIMC,
                                                     adeq2_p, 1, proj_b, cosb, sinb);     // 11
    }
}

// round 8
// speedup vs baseline: 1.9621x; 1.0406x over previous
#include <cuda_runtime.h>
#include <cuda_bf16.h>
#include <mma.h>
#include <cstdint>

using namespace nvcuda;

#define BATCH 2
#define SEQ   8192
#define DIMC  1024
#define NH    16
#define HD    64
#define CHUNK 128
#define NT    64
#define NROWS 16384
#define QKVN  3072
#define SCALE_ATTN 0.125f
#define EPS_BIT 1.1920929e-07f
#define EPS_OUT 1e-06f

// ---------------- static device scratch ----------------
__device__ __nv_bfloat16 g_xq[(size_t)NROWS * DIMC];
__device__ float         g_adeq[NROWS];
__device__ __nv_bfloat16 g_wq_qkv[(size_t)QKVN * DIMC];
__device__ __nv_bfloat16 g_wq_proj[(size_t)DIMC * DIMC];
__device__ float         g_wdeq[2];
__device__ float         g_part[256];
__device__ float         g_q[(size_t)BATCH * NH * NT * CHUNK * HD];
__device__ float         g_k[(size_t)BATCH * NH * NT * CHUNK * HD];
__device__ float         g_v[(size_t)BATCH * NH * NT * CHUNK * HD];
__device__ float         g_kvsum[(size_t)BATCH * NH * NT * HD * HD];
__device__ float         g_kvpre[(size_t)BATCH * NH * NT * HD * HD];
__device__ float         g_attn[(size_t)NROWS * DIMC];
__device__ __nv_bfloat16 g_xq2[(size_t)NROWS * DIMC];
__device__ float         g_adeq2[NROWS];

// ---------------- helpers ----------------
__device__ __forceinline__ uint32_t smem_u32(const void* smem_ptr) {
    uint32_t addr;
    asm("{ .reg .u64 tmp; cvta.to.shared.u64 tmp, %1; cvt.u32.u64 %0, tmp; }"
        : "=r"(addr) : "l"(smem_ptr));
    return addr;
}
__device__ __forceinline__ void cp_async16(uint32_t dst, const void* src) {
    asm volatile("cp.async.cg.shared.global [%0], [%1], 16;" :: "r"(dst), "l"(src) : "memory");
}
#define CP_COMMIT() asm volatile("cp.async.commit_group;" ::: "memory")
#define CP_WAIT(n)  asm volatile("cp.async.wait_group %0;" :: "n"(n) : "memory")

__device__ __forceinline__ float fexp(float x) {
    x = fmaxf(x, -80.0f);
    float y = x * 1.4426950408889634f;
    float n = rintf(y);
    float g = fmaf(-n, 0.6931471805599453f, x);
    float p = 1.9841270e-4f;
    p = fmaf(p, g, 1.3888889e-3f);
    p = fmaf(p, g, 8.3333333e-3f);
    p = fmaf(p, g, 4.1666667e-2f);
    p = fmaf(p, g, 1.6666667e-1f);
    p = fmaf(p, g, 5.0e-1f);
    p = fmaf(p, g, 1.0f);
    p = fmaf(p, g, 1.0f);
    float s = __int_as_float(((int)n + 127) << 23);
    return p * s;
}
__device__ __forceinline__ void split2(float v, __nv_bfloat16& hi, __nv_bfloat16& lo) {
    hi = __float2bfloat16(v);
    lo = __float2bfloat16(v - __bfloat162float(hi));
}
__device__ __forceinline__ void split4(float4 v,
    __nv_bfloat162& h01, __nv_bfloat162& l01,
    __nv_bfloat162& h23, __nv_bfloat162& l23) {
    h01.x = __float2bfloat16(v.x); l01.x = __float2bfloat16(v.x - __bfloat162float(h01.x));
    h01.y = __float2bfloat16(v.y); l01.y = __float2bfloat16(v.y - __bfloat162float(h01.y));
    h23.x = __float2bfloat16(v.z); l23.x = __float2bfloat16(v.z - __bfloat162float(h23.x));
    h23.y = __float2bfloat16(v.w); l23.y = __float2bfloat16(v.w - __bfloat162float(h23.y));
}

// ---------------- weight quant ----------------
__global__ void absmean_partial(const float* __restrict__ w, int n) {
    __shared__ float red[256];
    int tid = threadIdx.x;
    float s = 0.f;
    for (int i = blockIdx.x * 256 + tid; i < n; i += 65536) s += fabsf(w[i]);
    red[tid] = s; __syncthreads();
    for (int st = 128; st > 0; st >>= 1) { if (tid < st) red[tid] += red[tid + st]; __syncthreads(); }
    if (tid == 0) g_part[blockIdx.x] = red[0];
}

__global__ void __launch_bounds__(256) quant_weight_fused(const float* __restrict__ w,
                                                          __nv_bfloat16* __restrict__ wq,
                                                          int n, int slot) {
    __shared__ float red[256];
    int tid = threadIdx.x;
    red[tid] = g_part[tid]; __syncthreads();
    for (int st = 128; st > 0; st >>= 1) { if (tid < st) red[tid] += red[tid + st]; __syncthreads(); }
    float wdeq = fmaxf(red[0] / (float)n, 1e-5f);
    if (blockIdx.x == 0 && tid == 0) g_wdeq[slot] = wdeq;
    float s = 1.0f / wdeq;
    int i4 = (blockIdx.x * 256 + tid) * 4;
    if (i4 >= n) return;
    float4 wv = *(const float4*)(w + i4);
    __nv_bfloat162 p0, p1;
    p0.x = __float2bfloat16(fminf(fmaxf(rintf(wv.x * s), -1.f), 1.f));
    p0.y = __float2bfloat16(fminf(fmaxf(rintf(wv.y * s), -1.f), 1.f));
    p1.x = __float2bfloat16(fminf(fmaxf(rintf(wv.z * s), -1.f), 1.f));
    p1.y = __float2bfloat16(fminf(fmaxf(rintf(wv.w * s), -1.f), 1.f));
    *(__nv_bfloat162*)(wq + i4)     = p0;
    *(__nv_bfloat162*)(wq + i4 + 2) = p1;
}

// ---------------- activation quant for QKV input ----------------
__global__ void __launch_bounds__(256) act_quant_x(const float* __restrict__ x,
                                                   const float* __restrict__ nw) {
    __shared__ float red[256];
    __shared__ float bc;
    int row = blockIdx.x, tid = threadIdx.x;
    float4 xv = ((const float4*)(x + (size_t)row * DIMC))[tid];
    float4 wv = ((const float4*)nw)[tid];
    float ss = xv.x*xv.x + xv.y*xv.y + xv.z*xv.z + xv.w*xv.w;
    red[tid] = ss; __syncthreads();
    for (int st = 128; st > 0; st >>= 1) { if (tid < st) red[tid] += red[tid + st]; __syncthreads(); }
    if (tid == 0) bc = rsqrtf(red[0] * (1.0f / DIMC) + EPS_BIT);
    __syncthreads();
    float r = bc;
    float n0 = xv.x*r*wv.x, n1 = xv.y*r*wv.y, n2 = xv.z*r*wv.z, n3 = xv.w*r*wv.w;
    float amax = fmaxf(fmaxf(fabsf(n0), fabsf(n1)), fmaxf(fabsf(n2), fabsf(n3)));
    red[tid] = amax; __syncthreads();
    for (int st = 128; st > 0; st >>= 1) { if (tid < st) red[tid] = fmaxf(red[tid], red[tid + st]); __syncthreads(); }
    if (tid == 0) {
        float mx = fmaxf(red[0], 1e-5f);
        bc = 127.0f / mx;
        g_adeq[row] = mx * (1.0f / 127.0f);
    }
    __syncthreads();
    float sc = bc;
    __nv_bfloat162 p0, p1;
    p0.x = __float2bfloat16(fminf(fmaxf(rintf(n0 * sc), -128.f), 127.f));
    p0.y = __float2bfloat16(fminf(fmaxf(rintf(n1 * sc), -128.f), 127.f));
    p1.x = __float2bfloat16(fminf(fmaxf(rintf(n2 * sc), -128.f), 127.f));
    p1.y = __float2bfloat16(fminf(fmaxf(rintf(n3 * sc), -128.f), 127.f));
    __nv_bfloat16* out = g_xq + (size_t)row * DIMC + tid * 4;
    *(__nv_bfloat162*)(out)     = p0;
    *(__nv_bfloat162*)(out + 2) = p1;
}

// ---------------- double-norm + act quant for proj input ----------------
__global__ void __launch_bounds__(256) norm2_quant(const float* __restrict__ nw,
                                                   const float* __restrict__ pnw) {
    __shared__ float red[256];
    __shared__ float bc;
    int row = blockIdx.x, tid = threadIdx.x;
    float4 xv = ((const float4*)(g_attn + (size_t)row * DIMC))[tid];
    float4 wv = ((const float4*)nw)[tid];
    float4 pv = ((const float4*)pnw)[tid];
    float ss = xv.x*xv.x + xv.y*xv.y + xv.z*xv.z + xv.w*xv.w;
    red[tid] = ss; __syncthreads();
    for (int st = 128; st > 0; st >>= 1) { if (tid < st) red[tid] += red[tid + st]; __syncthreads(); }
    if (tid == 0) bc = rsqrtf(red[0] * (1.0f / DIMC) + EPS_OUT);
    __syncthreads();
    float r1 = bc;
    float z0 = xv.x*r1*wv.x, z1 = xv.y*r1*wv.y, z2 = xv.z*r1*wv.z, z3 = xv.w*r1*wv.w;
    float ss2 = z0*z0 + z1*z1 + z2*z2 + z3*z3;
    red[tid] = ss2; __syncthreads();
    for (int st = 128; st > 0; st >>= 1) { if (tid < st) red[tid] += red[tid + st]; __syncthreads(); }
    if (tid == 0) bc = rsqrtf(red[0] * (1.0f / DIMC) + EPS_BIT);
    __syncthreads();
    float r2 = bc;
    float n0 = z0*r2*pv.x, n1 = z1*r2*pv.y, n2 = z2*r2*pv.z, n3 = z3*r2*pv.w;
    float amax = fmaxf(fmaxf(fabsf(n0), fabsf(n1)), fmaxf(fabsf(n2), fabsf(n3)));
    red[tid] = amax; __syncthreads();
    for (int st = 128; st > 0; st >>= 1) { if (tid < st) red[tid] = fmaxf(red[tid], red[tid + st]); __syncthreads(); }
    if (tid == 0) {
        float mx = fmaxf(red[0], 1e-5f);
        bc = 127.0f / mx;
        g_adeq2[row] = mx * (1.0f / 127.0f);
    }
    __syncthreads();
    float sc = bc;
    __nv_bfloat162 p0, p1;
    p0.x = __float2bfloat16(fminf(fmaxf(rintf(n0 * sc), -128.f), 127.f));
    p0.y = __float2bfloat16(fminf(fmaxf(rintf(n1 * sc), -128.f), 127.f));
    p1.x = __float2bfloat16(fminf(fmaxf(rintf(n2 * sc), -128.f), 127.f));
    p1.y = __float2bfloat16(fminf(fmaxf(rintf(n3 * sc), -128.f), 127.f));
    __nv_bfloat16* out = g_xq2 + (size_t)row * DIMC + tid * 4;
    *(__nv_bfloat162*)(out)     = p0;
    *(__nv_bfloat162*)(out + 2) = p1;
}

// ---------------- bf16 HMMA GEMM, cp.async 2-stage pipeline, 2 CTAs/SM ----------------
// C[M,N] = A[M,1024] @ W[N,1024]^T * (adeq[m]*wdeq) + bias[n]
#define GLD 72
#define STAGE_BYTES (128 * GLD * 2)
#define GEMM_SMEM (4 * STAGE_BYTES + 8 * 16 * 20 * 4)
template<bool QKV>
__global__ void __launch_bounds__(256, 2) gemm_bf16_t(
    const __nv_bfloat16* __restrict__ A, const __nv_bfloat16* __restrict__ W,
    float* __restrict__ C, int N,
    const float* __restrict__ adeq, int wslot, const float* __restrict__ bias,
    const float* __restrict__ cosb, const float* __restrict__ sinb)
{
    extern __shared__ __align__(16) char gsm[];
    __nv_bfloat16* AsBuf[2] = { (__nv_bfloat16*)gsm,
                                (__nv_bfloat16*)(gsm + STAGE_BYTES) };
    __nv_bfloat16* BsBuf[2] = { (__nv_bfloat16*)(gsm + 2 * STAGE_BYTES),
                                (__nv_bfloat16*)(gsm + 3 * STAGE_BYTES) };
    float* CsAll = (float*)(gsm + 4 * STAGE_BYTES);

    int tid = threadIdx.x;
    int wid = tid >> 5, lane = tid & 31;
    int wm = wid >> 2, wn = wid & 3;            // warp tile 64(M) x 32(N)
    int bm = blockIdx.y * 128;
    int bn = blockIdx.x * 128;

    wmma::fragment<wmma::accumulator, 16, 16, 16, float> c[4][2];
    #pragma unroll
    for (int i = 0; i < 4; i++)
        #pragma unroll
        for (int j = 0; j < 2; j++) wmma::fill_fragment(c[i][j], 0.0f);

    // cp.async geometry: 128 rows x 64 cols bf16 per tile; each thread: row=tid>>1,
    // 4 contiguous 16B chunks starting at (tid&1)*64 bytes into the row.
    int row = tid >> 1;
    int cb  = (tid & 1) * 4;                    // chunk index base (of 8 per row)
    const __nv_bfloat16* Ag = A + (size_t)(bm + row) * 1024 + cb * 8;
    const __nv_bfloat16* Bg = W + (size_t)(bn + row) * 1024 + cb * 8;
    uint32_t aDst[2], bDst[2];
    aDst[0] = smem_u32(AsBuf[0]) + row * (GLD * 2) + cb * 16;
    aDst[1] = smem_u32(AsBuf[1]) + row * (GLD * 2) + cb * 16;
    bDst[0] = smem_u32(BsBuf[0]) + row * (GLD * 2) + cb * 16;
    bDst[1] = smem_u32(BsBuf[1]) + row * (GLD * 2) + cb * 16;

    // prologue: stages 0 and 1 in flight
    #pragma unroll
    for (int j = 0; j < 4; j++) {
        cp_async16(aDst[0] + j * 16, Ag + j * 8);
        cp_async16(bDst[0] + j * 16, Bg + j * 8);
    }
    CP_COMMIT();
    #pragma unroll
    for (int j = 0; j < 4; j++) {
        cp_async16(aDst[1] + j * 16, Ag + 64 + j * 8);
        cp_async16(bDst[1] + j * 16, Bg + 64 + j * 8);
    }
    CP_COMMIT();

    for (int kt = 0; kt < 16; kt++) {
        int buf = kt & 1;
        if (kt < 15) { CP_WAIT(1); } else { CP_WAIT(0); }
        __syncthreads();
        const __nv_bfloat16* as = AsBuf[buf];
        const __nv_bfloat16* bs = BsBuf[buf];
        int m0 = wm * 64, n0 = wn * 32;
        #pragma unroll
        for (int sk = 0; sk < 4; sk++) {
            int k0 = sk * 16;
            wmma::fragment<wmma::matrix_a, 16, 16, 16, __nv_bfloat16, wmma::row_major> af[4];
            wmma::fragment<wmma::matrix_b, 16, 16, 16, __nv_bfloat16, wmma::col_major> bf[2];
            #pragma unroll
            for (int i = 0; i < 4; i++)
                wmma::load_matrix_sync(af[i], &as[(m0 + i * 16) * GLD + k0], GLD);
            #pragma unroll
            for (int j = 0; j < 2; j++)
                wmma::load_matrix_sync(bf[j], &bs[(n0 + j * 16) * GLD + k0], GLD);
            #pragma unroll
            for (int i = 0; i < 4; i++)
                #pragma unroll
                for (int j = 0; j < 2; j++)
                    wmma::mma_sync(c[i][j], af[i], bf[j], c[i][j]);
        }
        __syncthreads();
        if (kt + 2 < 16) {
            int kn = (kt + 2) * 64;
            #pragma unroll
            for (int j = 0; j < 4; j++) {
                cp_async16(aDst[buf] + j * 16, Ag + kn + j * 8);
                cp_async16(bDst[buf] + j * 16, Bg + kn + j * 8);
            }
            CP_COMMIT();
        }
    }

    float wdeq = g_wdeq[wslot];
    float* Csw = &CsAll[wid * 320];
    #pragma unroll
    for (int i = 0; i < 4; i++) {
        #pragma unroll
        for (int j = 0; j < 2; j++) {
            __syncwarp();
            wmma::store_matrix_sync(Csw, c[i][j], 20, wmma::mem_row_major);
            __syncwarp();
            int r  = lane >> 1;
            int cc = (lane & 1) * 8;
            int grow = bm + wm * 64 + i * 16 + r;
            int gcol = bn + wn * 32 + j * 16 + cc;
            float sc = adeq[grow] * wdeq;
            float v[8];
            #pragma unroll
            for (int u = 0; u < 8; u++)
                v[u] = Csw[r * 20 + cc + u] * sc + bias[gcol + u];
            if (QKV) {
                int which = gcol >> 10;
                int rem = gcol & 1023;
                int h = rem >> 6, d = rem & 63;
                int b = grow >> 13, n = grow & 8191;
                int t = n >> 7, rr = n & 127;
                if (which < 2) {
                    int i0 = d >> 1;
                    #pragma unroll
                    for (int m = 0; m < 4; m++) {
                        float cth = cosb[n * 32 + i0 + m];
                        float sth = sinb[n * 32 + i0 + m];
                        float e = v[2*m], o = v[2*m+1];
                        v[2*m]   = e * cth - o * sth;
                        v[2*m+1] = o * cth + e * sth;
                    }
                }
                float* dstbase = (which == 0) ? g_q : (which == 1) ? g_k : g_v;
                float* dst = dstbase + (((size_t)b * NH + h) * NT + t) * (CHUNK * HD)
                           + (size_t)rr * 64 + d;
                *(float4*)(dst)     = make_float4(v[0], v[1], v[2], v[3]);
                *(float4*)(dst + 4) = make_float4(v[4], v[5], v[6], v[7]);
            } else {
                float* dst = C + (size_t)grow * N + gcol;
                *(float4*)(dst)     = make_float4(v[0], v[1], v[2], v[3]);
                *(float4*)(dst + 4) = make_float4(v[4], v[5], v[6], v[7]);
            }
        }
    }
}

// ---------------- intra-chunk attention (split-bf16 tensor cores) ----------------
#define QHI_OFF 0
#define QLO_OFF (128*72)
#define KHI_OFF (2*128*72)
#define KLO_OFF (3*128*72)
#define PHI_OFF (4*128*72)
#define PLO_OFF (4*128*72 + 128*136)
#define BF_TOTAL (4*128*72 + 2*128*136)
#define SS_LD 132

__global__ void __launch_bounds__(512) attn_intra() {
    int t = blockIdx.x, h = blockIdx.y, b = blockIdx.z;
    extern __shared__ __align__(16) char smraw[];
    __nv_bfloat16* bfm = (__nv_bfloat16*)smraw;
    float* sS = (float*)(smraw + (size_t)BF_TOTAL * 2);
    float* rowsum = sS + 128 * SS_LD;

    __nv_bfloat16* sQhi = bfm + QHI_OFF;
    __nv_bfloat16* sQlo = bfm + QLO_OFF;
    __nv_bfloat16* sKhi = bfm + KHI_OFF;
    __nv_bfloat16* sKlo = bfm + KLO_OFF;
    __nv_bfloat16* sPhi = bfm + PHI_OFF;
    __nv_bfloat16* sPlo = bfm + PLO_OFF;
    __nv_bfloat16* sVhi = sQhi;
    __nv_bfloat16* sVlo = sQlo;

    size_t base = (((size_t)b * NH + h) * NT + t) * (CHUNK * HD);
    int tid = threadIdx.x;
    int wid = tid >> 5;

    #pragma unroll
    for (int u = 0; u < 4; u++) {
        int i = tid + u * 512;
        int r = i >> 4, c4 = (i & 15) * 4;
        float4 qv = *(const float4*)(g_q + base + (size_t)r * 64 + c4);
        float4 kv = *(const float4*)(g_k + base + (size_t)r * 64 + c4);
        __nv_bfloat162 h01, l01, h23, l23;
        split4(qv, h01, l01, h23, l23);
        *(__nv_bfloat162*)(sQhi + r*72 + c4)     = h01;
        *(__nv_bfloat162*)(sQhi + r*72 + c4 + 2) = h23;
        *(__nv_bfloat162*)(sQlo + r*72 + c4)     = l01;
        *(__nv_bfloat162*)(sQlo + r*72 + c4 + 2) = l23;
        split4(kv, h01, l01, h23, l23);
        *(__nv_bfloat162*)(sKhi + r*72 + c4)     = h01;
        *(__nv_bfloat162*)(sKhi + r*72 + c4 + 2) = h23;
        *(__nv_bfloat162*)(sKlo + r*72 + c4)     = l01;
        *(__nv_bfloat162*)(sKlo + r*72 + c4 + 2) = l23;
    }
    __syncthreads();

    // QK^T: 16 warps, warp tile 16 rows x 64 cols
    {
        int r0 = (wid >> 1) * 16;
        int cbase = (wid & 1) * 64;
        wmma::fragment<wmma::accumulator, 16, 16, 16, float> c[4];
        #pragma unroll
        for (int j = 0; j < 4; j++) wmma::fill_fragment(c[j], 0.0f);
        #pragma unroll
        for (int sk = 0; sk < 4; sk++) {
            int k0 = sk * 16;
            wmma::fragment<wmma::matrix_a, 16, 16, 16, __nv_bfloat16, wmma::row_major> ah, al;
            wmma::load_matrix_sync(ah, &sQhi[r0 * 72 + k0], 72);
            wmma::load_matrix_sync(al, &sQlo[r0 * 72 + k0], 72);
            #pragma unroll
            for (int j = 0; j < 4; j++) {
                int col0 = cbase + j * 16;
                wmma::fragment<wmma::matrix_b, 16, 16, 16, __nv_bfloat16, wmma::col_major> bh, bl;
                wmma::load_matrix_sync(bh, &sKhi[col0 * 72 + k0], 72);
                wmma::load_matrix_sync(bl, &sKlo[col0 * 72 + k0], 72);
                wmma::mma_sync(c[j], ah, bh, c[j]);
                wmma::mma_sync(c[j], ah, bl, c[j]);
                wmma::mma_sync(c[j], al, bh, c[j]);
            }
        }
        #pragma unroll
        for (int j = 0; j < 4; j++) {
            #pragma unroll
            for (int e = 0; e < c[j].num_elements; e++) c[j].x[e] *= SCALE_ATTN;
            wmma::store_matrix_sync(&sS[r0 * SS_LD + cbase + j * 16], c[j], SS_LD, wmma::mem_row_major);
        }
    }
    __syncthreads();

    // softmax: 4 threads per row
    {
        int r = tid >> 2;
        int c0 = (tid & 3) * 32;
        float mx = -3.0e38f;
        for (int c = c0; c < c0 + 32; c++)
            if (c <= r) mx = fmaxf(mx, sS[r * SS_LD + c]);
        mx = fmaxf(mx, __shfl_xor_sync(0xffffffffu, mx, 1));
        mx = fmaxf(mx, __shfl_xor_sync(0xffffffffu, mx, 2));
        float sum = 0.f;
        for (int c = c0; c < c0 + 32; c++) {
            float e = (c <= r) ? fexp(sS[r * SS_LD + c] - mx) : 0.f;
            sum += e;
            __nv_bfloat16 hi, lo;
            split2(e, hi, lo);
            sPhi[r * 136 + c] = hi;
            sPlo[r * 136 + c] = lo;
        }
        sum += __shfl_xor_sync(0xffffffffu, sum, 1);
        sum += __shfl_xor_sync(0xffffffffu, sum, 2);
        if ((tid & 3) == 0) rowsum[r] = sum;
    }
    // V load into Q slots
    #pragma unroll
    for (int u = 0; u < 4; u++) {
        int i = tid + u * 512;
        int r = i >> 4, c4 = (i & 15) * 4;
        float4 vv = *(const float4*)(g_v + base + (size_t)r * 64 + c4);
        __nv_bfloat162 h01, l01, h23, l23;
        split4(vv, h01, l01, h23, l23);
        *(__nv_bfloat162*)(sVhi + r*72 + c4)     = h01;
        *(__nv_bfloat162*)(sVhi + r*72 + c4 + 2) = h23;
        *(__nv_bfloat162*)(sVlo + r*72 + c4)     = l01;
        *(__nv_bfloat162*)(sVlo + r*72 + c4 + 2) = l23;
    }
    __syncthreads();

    // S_t = K^T V (64x64): one 16x16 tile per warp
    {
        int d0 = (wid >> 2) * 16;
        int e0 = (wid & 3) * 16;
        wmma::fragment<wmma::accumulator, 16, 16, 16, float> c;
        wmma::fill_fragment(c, 0.0f);
        #pragma unroll
        for (int sk = 0; sk < 8; sk++) {
            int r0 = sk * 16;
            wmma::fragment<wmma::matrix_a, 16, 16, 16, __nv_bfloat16, wmma::col_major> ah, al;
            wmma::fragment<wmma::matrix_b, 16, 16, 16, __nv_bfloat16, wmma::row_major> bh, bl;
            wmma::load_matrix_sync(ah, &sKhi[r0 * 72 + d0], 72);
            wmma::load_matrix_sync(al, &sKlo[r0 * 72 + d0], 72);
            wmma::load_matrix_sync(bh, &sVhi[r0 * 72 + e0], 72);
            wmma::load_matrix_sync(bl, &sVlo[r0 * 72 + e0], 72);
            wmma::mma_sync(c, ah, bh, c);
            wmma::mma_sync(c, ah, bl, c);
            wmma::mma_sync(c, al, bh, c);
        }
        size_t kb = (((size_t)b * NH + h) * NT + t) * (HD * HD);
        wmma::store_matrix_sync(g_kvsum + kb + (size_t)d0 * 64 + e0, c, 64, wmma::mem_row_major);
    }

    // o_intra = P @ V (128x64): warp tile 16x32
    {
        int r0 = (wid >> 1) * 16;
        int cbase = (wid & 1) * 32;
        wmma::fragment<wmma::accumulator, 16, 16, 16, float> c[2];
        #pragma unroll
        for (int j = 0; j < 2; j++) wmma::fill_fragment(c[j], 0.0f);
        #pragma unroll
        for (int sk = 0; sk < 8; sk++) {
            int k0 = sk * 16;
            wmma::fragment<wmma::matrix_a, 16, 16, 16, __nv_bfloat16, wmma::row_major> ah, al;
            wmma::load_matrix_sync(ah, &sPhi[r0 * 136 + k0], 136);
            wmma::load_matrix_sync(al, &sPlo[r0 * 136 + k0], 136);
            #pragma unroll
            for (int j = 0; j < 2; j++) {
                int col0 = cbase + j * 16;
                wmma::fragment<wmma::matrix_b, 16, 16, 16, __nv_bfloat16, wmma::row_major> bh, bl;
                wmma::load_matrix_sync(bh, &sVhi[k0 * 72 + col0], 72);
                wmma::load_matrix_sync(bl, &sVlo[k0 * 72 + col0], 72);
                wmma::mma_sync(c[j], ah, bh, c[j]);
                wmma::mma_sync(c[j], ah, bl, c[j]);
                wmma::mma_sync(c[j], al, bh, c[j]);
            }
        }
        __syncthreads();
        #pragma unroll
        for (int j = 0; j < 2; j++)
            wmma::store_matrix_sync(&sS[r0 * SS_LD + cbase + j * 16], c[j], SS_LD, wmma::mem_row_major);
    }
    __syncthreads();

    #pragma unroll
    for (int u = 0; u < 4; u++) {
        int i = tid + u * 512;
        int r = i >> 4, c4 = (i & 15) * 4;
        float inv = 1.0f / rowsum[r];
        float4 o;
        o.x = sS[r * SS_LD + c4 + 0] * inv;
        o.y = sS[r * SS_LD + c4 + 1] * inv;
        o.z = sS[r * SS_LD + c4 + 2] * inv;
        o.w = sS[r * SS_LD + c4 + 3] * inv;
        size_t grow = (size_t)b * SEQ + (size_t)t * CHUNK + r;
        *(float4*)(g_attn + grow * DIMC + h * 64 + c4) = o;
    }
}

// ---------------- exclusive prefix-sum of chunk KV matrices ----------------
__global__ void __launch_bounds__(256) kv_prefix() {
    int blk = blockIdx.x;
    int bh = blk >> 3, s = blk & 7;
    int tid = threadIdx.x;
    size_t base = (size_t)bh * NT * (HD * HD) + s * 512 + tid * 2;
    float2 acc = make_float2(0.f, 0.f);
    for (int t = 0; t < NT; t++) {
        size_t off = base + (size_t)t * (HD * HD);
        float2 v = *(const float2*)(g_kvsum + off);
        *(float2*)(g_kvpre + off) = acc;
        acc.x += v.x; acc.y += v.y;
    }
}

// ---------------- o_inter = q @ kv_prefix ----------------
#define IQHI 0
#define IQLO (128*72)
#define IKHI (2*128*72)
#define IKLO (2*128*72 + 64*72)
#define IBF_TOTAL (2*128*72 + 2*64*72)
__global__ void __launch_bounds__(256) attn_inter() {
    int t = blockIdx.x, h = blockIdx.y, b = blockIdx.z;
    extern __shared__ __align__(16) char smraw2[];
    __nv_bfloat16* bfm = (__nv_bfloat16*)smraw2;
    float* sO = (float*)(smraw2 + (size_t)IBF_TOTAL * 2);

    __nv_bfloat16* sQhi = bfm + IQHI;
    __nv_bfloat16* sQlo = bfm + IQLO;
    __nv_bfloat16* sKhi = bfm + IKHI;
    __nv_bfloat16* sKlo = bfm + IKLO;

    size_t base = (((size_t)b * NH + h) * NT + t) * (CHUNK * HD);
    size_t kb   = (((size_t)b * NH + h) * NT + t) * (HD * HD);
    int tid = threadIdx.x;
    int wid = tid >> 5;

    #pragma unroll
    for (int u = 0; u < 8; u++) {
        int i = tid + u * 256;
        int r = i >> 4, c4 = (i & 15) * 4;
        float4 qv = *(const float4*)(g_q + base + (size_t)r * 64 + c4);
        __nv_bfloat162 h01, l01, h23, l23;
        split4(qv, h01, l01, h23, l23);
        *(__nv_bfloat162*)(sQhi + r*72 + c4)     = h01;
        *(__nv_bfloat162*)(sQhi + r*72 + c4 + 2) = h23;
        *(__nv_bfloat162*)(sQlo + r*72 + c4)     = l01;
        *(__nv_bfloat162*)(sQlo + r*72 + c4 + 2) = l23;
    }
    #pragma unroll
    for (int u = 0; u < 4; u++) {
        int i = tid + u * 256;
        int r = i >> 4, c4 = (i & 15) * 4;
        float4 kv = *(const float4*)(g_kvpre + kb + (size_t)r * 64 + c4);
        __nv_bfloat162 h01, l01, h23, l23;
        split4(kv, h01, l01, h23, l23);
        *(__nv_bfloat162*)(sKhi + r*72 + c4)     = h01;
        *(__nv_bfloat162*)(sKhi + r*72 + c4 + 2) = h23;
        *(__nv_bfloat162*)(sKlo + r*72 + c4)     = l01;
        *(__nv_bfloat162*)(sKlo + r*72 + c4 + 2) = l23;
    }
    __syncthreads();

    {
        int r0 = wid * 16;
        wmma::fragment<wmma::accumulator, 16, 16, 16, float> c[4];
        #pragma unroll
        for (int j = 0; j < 4; j++) wmma::fill_fragment(c[j], 0.0f);
        #pragma unroll
        for (int sk = 0; sk < 4; sk++) {
            int k0 = sk * 16;
            wmma::fragment<wmma::matrix_a, 16, 16, 16, __nv_bfloat16, wmma::row_major> ah, al;
            wmma::load_matrix_sync(ah, &sQhi[r0 * 72 + k0], 72);
            wmma::load_matrix_sync(al, &sQlo[r0 * 72 + k0], 72);
            #pragma unroll
            for (int j = 0; j < 4; j++) {
                int col0 = j * 16;
                wmma::fragment<wmma::matrix_b, 16, 16, 16, __nv_bfloat16, wmma::row_major> bh, bl;
                wmma::load_matrix_sync(bh, &sKhi[k0 * 72 + col0], 72);
                wmma::load_matrix_sync(bl, &sKlo[k0 * 72 + col0], 72);
                wmma::mma_sync(c[j], ah, bh, c[j]);
                wmma::mma_sync(c[j], ah, bl, c[j]);
                wmma::mma_sync(c[j], al, bh, c[j]);
            }
        }
        #pragma unroll
        for (int j = 0; j < 4; j++)
            wmma::store_matrix_sync(&sO[r0 * 68 + j * 16], c[j], 68, wmma::mem_row_major);
    }
    __syncthreads();

    #pragma unroll
    for (int u = 0; u < 8; u++) {
        int i = tid + u * 256;
        int r = i >> 4, c4 = (i & 15) * 4;
        size_t grow = (size_t)b * SEQ + (size_t)t * CHUNK + r;
        float* dst = g_attn + grow * DIMC + h * 64 + c4;
        float4 old = *(float4*)dst;
        old.x += sO[r * 68 + c4 + 0];
        old.y += sO[r * 68 + c4 + 1];
        old.z += sO[r * 68 + c4 + 2];
        old.w += sO[r * 68 + c4 + 3];
        *(float4*)dst = old;
    }
}

// ---------------- launch ----------------
extern "C" void kernel_launch(void* const* d_in, const int* in_sizes, int n_in,
                              void* d_out, int out_size) {
    const float* x       = (const float*)d_in[0];
    const float* cosb    = (const float*)d_in[1];
    const float* sinb    = (const float*)d_in[2];
    const float* qkv_w   = (const float*)d_in[3];
    const float* qkv_b   = (const float*)d_in[4];
    const float* qkv_nw  = (const float*)d_in[5];
    const float* proj_w  = (const float*)d_in[6];
    const float* proj_b  = (const float*)d_in[7];
    const float* proj_nw = (const float*)d_in[8];
    const float* norm_w  = (const float*)d_in[9];
    float* out = (float*)d_out;

    size_t smem_intra = (size_t)BF_TOTAL * 2 + (128 * SS_LD + 128) * sizeof(float);
    size_t smem_inter = (size_t)IBF_TOTAL * 2 + (128 * 68) * sizeof(float);

    static bool attr_done = false;
    if (!attr_done) {
        cudaFuncSetAttribute(attn_intra, cudaFuncAttributeMaxDynamicSharedMemorySize, (int)smem_intra);
        cudaFuncSetAttribute(attn_inter, cudaFuncAttributeMaxDynamicSharedMemorySize, (int)smem_inter);
        cudaFuncSetAttribute(gemm_bf16_t<true>,  cudaFuncAttributeMaxDynamicSharedMemorySize, GEMM_SMEM);
        cudaFuncSetAttribute(gemm_bf16_t<false>, cudaFuncAttributeMaxDynamicSharedMemorySize, GEMM_SMEM);
        attr_done = true;
    }

    __nv_bfloat16 *xq_p, *wqkv_p, *wproj_p, *xq2_p;
    float *adeq_p, *adeq2_p;
    cudaGetSymbolAddress((void**)&xq_p,    g_xq);
    cudaGetSymbolAddress((void**)&wqkv_p,  g_wq_qkv);
    cudaGetSymbolAddress((void**)&wproj_p, g_wq_proj);
    cudaGetSymbolAddress((void**)&xq2_p,   g_xq2);
    cudaGetSymbolAddress((void**)&adeq_p,  g_adeq);
    cudaGetSymbolAddress((void**)&adeq2_p, g_adeq2);

    // Launch order: gemm<QKV> is launch #4 -> ncu capture slot.
    absmean_partial<<<256, 256>>>(qkv_w, QKVN * DIMC);                                    // 1
    quant_weight_fused<<<QKVN * DIMC / 1024, 256>>>(qkv_w, wqkv_p, QKVN * DIMC, 0);       // 2
    act_quant_x<<<NROWS, 256>>>(x, qkv_nw);                                               // 3
    {
        dim3 grid(QKVN / 128, NROWS / 128);
        gemm_bf16_t<true><<<grid, 256, GEMM_SMEM>>>(xq_p, wqkv_p, nullptr, QKVN,
                                                    adeq_p, 0, qkv_b, cosb, sinb);        // 4 <- profiled
    }
    absmean_partial<<<256, 256>>>(proj_w, DIMC * DIMC);                                   // 5
    quant_weight_fused<<<DIMC * DIMC / 1024, 256>>>(proj_w, wproj_p, DIMC * DIMC, 1);     // 6

    {
        dim3 grid(NT, NH, BATCH);
        attn_intra<<<grid, 512, smem_intra>>>();                                          // 7
    }
    kv_prefix<<<256, 256>>>();                                                            // 8
    {
        dim3 grid(NT, NH, BATCH);
        attn_inter<<<grid, 256, smem_inter>>>();                                          // 9
    }

    norm2_quant<<<NROWS, 256>>>(norm_w, proj_nw);                                         // 10
    {
        dim3 grid(DIMC / 128, NROWS / 128);
        gemm_bf16_t<false><<<grid, 256, GEMM_SMEM>>>(xq2_p, wproj_p, out, DIMC,
                                                     adeq2_p, 1, proj_b, cosb, sinb);     // 11
    }
}

// round 9
// speedup vs baseline: 2.0161x; 1.0275x over previous
#include <cuda_runtime.h>
#include <cuda_bf16.h>
#include <mma.h>
#include <cstdint>

using namespace nvcuda;

#define BATCH 2
#define SEQ   8192
#define DIMC  1024
#define NH    16
#define HD    64
#define CHUNK 128
#define NT    64
#define NROWS 16384
#define QKVN  3072
#define SCALE_ATTN 0.125f
#define EPS_BIT 1.1920929e-07f
#define EPS_OUT 1e-06f

// ---------------- static device scratch ----------------
__device__ __nv_bfloat16 g_xq[(size_t)NROWS * DIMC];
__device__ float         g_adeq[NROWS];
__device__ __nv_bfloat16 g_wq_qkv[(size_t)QKVN * DIMC];
__device__ __nv_bfloat16 g_wq_proj[(size_t)DIMC * DIMC];
__device__ float         g_wdeq[2];
__device__ float         g_part[256];
__device__ float         g_q[(size_t)BATCH * NH * NT * CHUNK * HD];
__device__ float         g_k[(size_t)BATCH * NH * NT * CHUNK * HD];
__device__ float         g_v[(size_t)BATCH * NH * NT * CHUNK * HD];
__device__ float         g_kvsum[(size_t)BATCH * NH * NT * HD * HD];
__device__ float         g_kvpre[(size_t)BATCH * NH * NT * HD * HD];
__device__ float         g_attn[(size_t)NROWS * DIMC];
__device__ __nv_bfloat16 g_xq2[(size_t)NROWS * DIMC];
__device__ float         g_adeq2[NROWS];

// ---------------- helpers ----------------
__device__ __forceinline__ uint32_t smem_u32(const void* smem_ptr) {
    uint32_t addr;
    asm("{ .reg .u64 tmp; cvta.to.shared.u64 tmp, %1; cvt.u32.u64 %0, tmp; }"
        : "=r"(addr) : "l"(smem_ptr));
    return addr;
}
__device__ __forceinline__ void cp_async16(uint32_t dst, const void* src) {
    asm volatile("cp.async.cg.shared.global [%0], [%1], 16;" :: "r"(dst), "l"(src) : "memory");
}
#define CP_COMMIT() asm volatile("cp.async.commit_group;" ::: "memory")
#define CP_WAIT(n)  asm volatile("cp.async.wait_group %0;" :: "n"(n) : "memory")

__device__ __forceinline__ float fexp(float x) {
    x = fmaxf(x, -80.0f);
    float y = x * 1.4426950408889634f;
    float n = rintf(y);
    float g = fmaf(-n, 0.6931471805599453f, x);
    float p = 1.9841270e-4f;
    p = fmaf(p, g, 1.3888889e-3f);
    p = fmaf(p, g, 8.3333333e-3f);
    p = fmaf(p, g, 4.1666667e-2f);
    p = fmaf(p, g, 1.6666667e-1f);
    p = fmaf(p, g, 5.0e-1f);
    p = fmaf(p, g, 1.0f);
    p = fmaf(p, g, 1.0f);
    float s = __int_as_float(((int)n + 127) << 23);
    return p * s;
}
__device__ __forceinline__ void split2(float v, __nv_bfloat16& hi, __nv_bfloat16& lo) {
    hi = __float2bfloat16(v);
    lo = __float2bfloat16(v - __bfloat162float(hi));
}
__device__ __forceinline__ void split4(float4 v,
    __nv_bfloat162& h01, __nv_bfloat162& l01,
    __nv_bfloat162& h23, __nv_bfloat162& l23) {
    h01.x = __float2bfloat16(v.x); l01.x = __float2bfloat16(v.x - __bfloat162float(h01.x));
    h01.y = __float2bfloat16(v.y); l01.y = __float2bfloat16(v.y - __bfloat162float(h01.y));
    h23.x = __float2bfloat16(v.z); l23.x = __float2bfloat16(v.z - __bfloat162float(h23.x));
    h23.y = __float2bfloat16(v.w); l23.y = __float2bfloat16(v.w - __bfloat162float(h23.y));
}

// ---------------- weight quant ----------------
__global__ void absmean_partial(const float* __restrict__ w, int n) {
    __shared__ float red[256];
    int tid = threadIdx.x;
    float s = 0.f;
    for (int i = blockIdx.x * 256 + tid; i < n; i += 65536) s += fabsf(w[i]);
    red[tid] = s; __syncthreads();
    for (int st = 128; st > 0; st >>= 1) { if (tid < st) red[tid] += red[tid + st]; __syncthreads(); }
    if (tid == 0) g_part[blockIdx.x] = red[0];
}

__global__ void __launch_bounds__(256) quant_weight_fused(const float* __restrict__ w,
                                                          __nv_bfloat16* __restrict__ wq,
                                                          int n, int slot) {
    __shared__ float red[256];
    int tid = threadIdx.x;
    red[tid] = g_part[tid]; __syncthreads();
    for (int st = 128; st > 0; st >>= 1) { if (tid < st) red[tid] += red[tid + st]; __syncthreads(); }
    float wdeq = fmaxf(red[0] / (float)n, 1e-5f);
    if (blockIdx.x == 0 && tid == 0) g_wdeq[slot] = wdeq;
    float s = 1.0f / wdeq;
    int i4 = (blockIdx.x * 256 + tid) * 4;
    if (i4 >= n) return;
    float4 wv = *(const float4*)(w + i4);
    __nv_bfloat162 p0, p1;
    p0.x = __float2bfloat16(fminf(fmaxf(rintf(wv.x * s), -1.f), 1.f));
    p0.y = __float2bfloat16(fminf(fmaxf(rintf(wv.y * s), -1.f), 1.f));
    p1.x = __float2bfloat16(fminf(fmaxf(rintf(wv.z * s), -1.f), 1.f));
    p1.y = __float2bfloat16(fminf(fmaxf(rintf(wv.w * s), -1.f), 1.f));
    *(__nv_bfloat162*)(wq + i4)     = p0;
    *(__nv_bfloat162*)(wq + i4 + 2) = p1;
}

// ---------------- activation quant for QKV input ----------------
__global__ void __launch_bounds__(256) act_quant_x(const float* __restrict__ x,
                                                   const float* __restrict__ nw) {
    __shared__ float red[256];
    __shared__ float bc;
    int row = blockIdx.x, tid = threadIdx.x;
    float4 xv = ((const float4*)(x + (size_t)row * DIMC))[tid];
    float4 wv = ((const float4*)nw)[tid];
    float ss = xv.x*xv.x + xv.y*xv.y + xv.z*xv.z + xv.w*xv.w;
    red[tid] = ss; __syncthreads();
    for (int st = 128; st > 0; st >>= 1) { if (tid < st) red[tid] += red[tid + st]; __syncthreads(); }
    if (tid == 0) bc = rsqrtf(red[0] * (1.0f / DIMC) + EPS_BIT);
    __syncthreads();
    float r = bc;
    float n0 = xv.x*r*wv.x, n1 = xv.y*r*wv.y, n2 = xv.z*r*wv.z, n3 = xv.w*r*wv.w;
    float amax = fmaxf(fmaxf(fabsf(n0), fabsf(n1)), fmaxf(fabsf(n2), fabsf(n3)));
    red[tid] = amax; __syncthreads();
    for (int st = 128; st > 0; st >>= 1) { if (tid < st) red[tid] = fmaxf(red[tid], red[tid + st]); __syncthreads(); }
    if (tid == 0) {
        float mx = fmaxf(red[0], 1e-5f);
        bc = 127.0f / mx;
        g_adeq[row] = mx * (1.0f / 127.0f);
    }
    __syncthreads();
    float sc = bc;
    __nv_bfloat162 p0, p1;
    p0.x = __float2bfloat16(fminf(fmaxf(rintf(n0 * sc), -128.f), 127.f));
    p0.y = __float2bfloat16(fminf(fmaxf(rintf(n1 * sc), -128.f), 127.f));
    p1.x = __float2bfloat16(fminf(fmaxf(rintf(n2 * sc), -128.f), 127.f));
    p1.y = __float2bfloat16(fminf(fmaxf(rintf(n3 * sc), -128.f), 127.f));
    __nv_bfloat16* out = g_xq + (size_t)row * DIMC + tid * 4;
    *(__nv_bfloat162*)(out)     = p0;
    *(__nv_bfloat162*)(out + 2) = p1;
}

// ---------------- double-norm + act quant for proj input ----------------
__global__ void __launch_bounds__(256) norm2_quant(const float* __restrict__ nw,
                                                   const float* __restrict__ pnw) {
    __shared__ float red[256];
    __shared__ float bc;
    int row = blockIdx.x, tid = threadIdx.x;
    float4 xv = ((const float4*)(g_attn + (size_t)row * DIMC))[tid];
    float4 wv = ((const float4*)nw)[tid];
    float4 pv = ((const float4*)pnw)[tid];
    float ss = xv.x*xv.x + xv.y*xv.y + xv.z*xv.z + xv.w*xv.w;
    red[tid] = ss; __syncthreads();
    for (int st = 128; st > 0; st >>= 1) { if (tid < st) red[tid] += red[tid + st]; __syncthreads(); }
    if (tid == 0) bc = rsqrtf(red[0] * (1.0f / DIMC) + EPS_OUT);
    __syncthreads();
    float r1 = bc;
    float z0 = xv.x*r1*wv.x, z1 = xv.y*r1*wv.y, z2 = xv.z*r1*wv.z, z3 = xv.w*r1*wv.w;
    float ss2 = z0*z0 + z1*z1 + z2*z2 + z3*z3;
    red[tid] = ss2; __syncthreads();
    for (int st = 128; st > 0; st >>= 1) { if (tid < st) red[tid] += red[tid + st]; __syncthreads(); }
    if (tid == 0) bc = rsqrtf(red[0] * (1.0f / DIMC) + EPS_BIT);
    __syncthreads();
    float r2 = bc;
    float n0 = z0*r2*pv.x, n1 = z1*r2*pv.y, n2 = z2*r2*pv.z, n3 = z3*r2*pv.w;
    float amax = fmaxf(fmaxf(fabsf(n0), fabsf(n1)), fmaxf(fabsf(n2), fabsf(n3)));
    red[tid] = amax; __syncthreads();
    for (int st = 128; st > 0; st >>= 1) { if (tid < st) red[tid] = fmaxf(red[tid], red[tid + st]); __syncthreads(); }
    if (tid == 0) {
        float mx = fmaxf(red[0], 1e-5f);
        bc = 127.0f / mx;
        g_adeq2[row] = mx * (1.0f / 127.0f);
    }
    __syncthreads();
    float sc = bc;
    __nv_bfloat162 p0, p1;
    p0.x = __float2bfloat16(fminf(fmaxf(rintf(n0 * sc), -128.f), 127.f));
    p0.y = __float2bfloat16(fminf(fmaxf(rintf(n1 * sc), -128.f), 127.f));
    p1.x = __float2bfloat16(fminf(fmaxf(rintf(n2 * sc), -128.f), 127.f));
    p1.y = __float2bfloat16(fminf(fmaxf(rintf(n3 * sc), -128.f), 127.f));
    __nv_bfloat16* out = g_xq2 + (size_t)row * DIMC + tid * 4;
    *(__nv_bfloat162*)(out)     = p0;
    *(__nv_bfloat162*)(out + 2) = p1;
}

// ---------------- bf16 HMMA GEMM, 3-stage cp.async ring, ONE sync per K-tile ----------------
// C[M,N] = A[M,1024] @ W[N,1024]^T * (adeq[m]*wdeq) + bias[n]
#define GLD 72
#define HALF_STAGE (128 * GLD * 2)            // one operand tile (bytes)
#define STAGE_BYTES (2 * HALF_STAGE)          // A+B per stage = 36864
#define GEMM_SMEM (3 * STAGE_BYTES)           // 110592; epilogue reuses stage 0
template<bool QKV>
__global__ void __launch_bounds__(256, 2) gemm_bf16_t(
    const __nv_bfloat16* __restrict__ A, const __nv_bfloat16* __restrict__ W,
    float* __restrict__ C, int N,
    const float* __restrict__ adeq, int wslot, const float* __restrict__ bias,
    const float* __restrict__ cosb, const float* __restrict__ sinb)
{
    extern __shared__ __align__(16) char gsm[];

    int tid = threadIdx.x;
    int wid = tid >> 5, lane = tid & 31;
    int wm = wid >> 2, wn = wid & 3;            // warp tile 64(M) x 32(N)
    int bm = blockIdx.y * 128;
    int bn = blockIdx.x * 128;

    wmma::fragment<wmma::accumulator, 16, 16, 16, float> c[4][2];
    #pragma unroll
    for (int i = 0; i < 4; i++)
        #pragma unroll
        for (int j = 0; j < 2; j++) wmma::fill_fragment(c[i][j], 0.0f);

    // cp.async geometry: 128 rows x 64 cols bf16 per operand tile.
    int row = tid >> 1;
    int cb  = (tid & 1) * 4;                    // 4 of 8 16B-chunks per row
    const __nv_bfloat16* Ag = A + (size_t)(bm + row) * 1024 + cb * 8;
    const __nv_bfloat16* Bg = W + (size_t)(bn + row) * 1024 + cb * 8;
    uint32_t base = smem_u32(gsm) + row * (GLD * 2) + cb * 16;

    // prologue: stages 0 and 1 in flight
    #pragma unroll
    for (int j = 0; j < 4; j++) {
        cp_async16(base + j * 16, Ag + j * 8);
        cp_async16(base + HALF_STAGE + j * 16, Bg + j * 8);
    }
    CP_COMMIT();
    #pragma unroll
    for (int j = 0; j < 4; j++) {
        cp_async16(base + STAGE_BYTES + j * 16, Ag + 64 + j * 8);
        cp_async16(base + STAGE_BYTES + HALF_STAGE + j * 16, Bg + 64 + j * 8);
    }
    CP_COMMIT();

    int m0 = wm * 64, n0 = wn * 32;
    for (int kt = 0; kt < 16; kt++) {
        int sRead = kt % 3;
        if (kt == 15) { CP_WAIT(0); } else { CP_WAIT(1); }
        __syncthreads();   // single barrier: kt data ready AND all warps done with kt-1
        // issue kt+2 into stage (kt+2)%3 == (kt-1)%3 (everyone finished reading it)
        if (kt + 2 < 16) {
            int sW = (kt + 2) % 3;
            int kn = (kt + 2) * 64;
            uint32_t wbase = base + sW * STAGE_BYTES;
            #pragma unroll
            for (int j = 0; j < 4; j++) {
                cp_async16(wbase + j * 16, Ag + kn + j * 8);
                cp_async16(wbase + HALF_STAGE + j * 16, Bg + kn + j * 8);
            }
            CP_COMMIT();
        }
        const __nv_bfloat16* as = (const __nv_bfloat16*)(gsm + sRead * STAGE_BYTES);
        const __nv_bfloat16* bs = (const __nv_bfloat16*)(gsm + sRead * STAGE_BYTES + HALF_STAGE);
        #pragma unroll
        for (int sk = 0; sk < 4; sk++) {
            int k0 = sk * 16;
            wmma::fragment<wmma::matrix_a, 16, 16, 16, __nv_bfloat16, wmma::row_major> af[4];
            wmma::fragment<wmma::matrix_b, 16, 16, 16, __nv_bfloat16, wmma::col_major> bf[2];
            #pragma unroll
            for (int i = 0; i < 4; i++)
                wmma::load_matrix_sync(af[i], &as[(m0 + i * 16) * GLD + k0], GLD);
            #pragma unroll
            for (int j = 0; j < 2; j++)
                wmma::load_matrix_sync(bf[j], &bs[(n0 + j * 16) * GLD + k0], GLD);
            #pragma unroll
            for (int i = 0; i < 4; i++)
                #pragma unroll
                for (int j = 0; j < 2; j++)
                    wmma::mma_sync(c[i][j], af[i], bf[j], c[i][j]);
        }
    }
    __syncthreads();   // all MMAs done; stage smem now reusable for C staging

    float wdeq = g_wdeq[wslot];
    float* CsAll = (float*)gsm;
    float* Csw = &CsAll[wid * 320];
    #pragma unroll
    for (int i = 0; i < 4; i++) {
        #pragma unroll
        for (int j = 0; j < 2; j++) {
            __syncwarp();
            wmma::store_matrix_sync(Csw, c[i][j], 20, wmma::mem_row_major);
            __syncwarp();
            int r  = lane >> 1;
            int cc = (lane & 1) * 8;
            int grow = bm + wm * 64 + i * 16 + r;
            int gcol = bn + wn * 32 + j * 16 + cc;
            float sc = adeq[grow] * wdeq;
            float v[8];
            #pragma unroll
            for (int u = 0; u < 8; u++)
                v[u] = Csw[r * 20 + cc + u] * sc + bias[gcol + u];
            if (QKV) {
                int which = gcol >> 10;
                int rem = gcol & 1023;
                int h = rem >> 6, d = rem & 63;
                int b = grow >> 13, n = grow & 8191;
                int t = n >> 7, rr = n & 127;
                if (which < 2) {
                    int i0 = d >> 1;
                    #pragma unroll
                    for (int m = 0; m < 4; m++) {
                        float cth = cosb[n * 32 + i0 + m];
                        float sth = sinb[n * 32 + i0 + m];
                        float e = v[2*m], o = v[2*m+1];
                        v[2*m]   = e * cth - o * sth;
                        v[2*m+1] = o * cth + e * sth;
                    }
                }
                float* dstbase = (which == 0) ? g_q : (which == 1) ? g_k : g_v;
                float* dst = dstbase + (((size_t)b * NH + h) * NT + t) * (CHUNK * HD)
                           + (size_t)rr * 64 + d;
                *(float4*)(dst)     = make_float4(v[0], v[1], v[2], v[3]);
                *(float4*)(dst + 4) = make_float4(v[4], v[5], v[6], v[7]);
            } else {
                float* dst = C + (size_t)grow * N + gcol;
                *(float4*)(dst)     = make_float4(v[0], v[1], v[2], v[3]);
                *(float4*)(dst + 4) = make_float4(v[4], v[5], v[6], v[7]);
            }
        }
    }
}

// ---------------- intra-chunk attention (split-bf16 tensor cores) ----------------
#define QHI_OFF 0
#define QLO_OFF (128*72)
#define KHI_OFF (2*128*72)
#define KLO_OFF (3*128*72)
#define PHI_OFF (4*128*72)
#define PLO_OFF (4*128*72 + 128*136)
#define BF_TOTAL (4*128*72 + 2*128*136)
#define SS_LD 132

__global__ void __launch_bounds__(512) attn_intra() {
    int t = blockIdx.x, h = blockIdx.y, b = blockIdx.z;
    extern __shared__ __align__(16) char smraw[];
    __nv_bfloat16* bfm = (__nv_bfloat16*)smraw;
    float* sS = (float*)(smraw + (size_t)BF_TOTAL * 2);
    float* rowsum = sS + 128 * SS_LD;

    __nv_bfloat16* sQhi = bfm + QHI_OFF;
    __nv_bfloat16* sQlo = bfm + QLO_OFF;
    __nv_bfloat16* sKhi = bfm + KHI_OFF;
    __nv_bfloat16* sKlo = bfm + KLO_OFF;
    __nv_bfloat16* sPhi = bfm + PHI_OFF;
    __nv_bfloat16* sPlo = bfm + PLO_OFF;
    __nv_bfloat16* sVhi = sQhi;
    __nv_bfloat16* sVlo = sQlo;

    size_t base = (((size_t)b * NH + h) * NT + t) * (CHUNK * HD);
    int tid = threadIdx.x;
    int wid = tid >> 5;

    #pragma unroll
    for (int u = 0; u < 4; u++) {
        int i = tid + u * 512;
        int r = i >> 4, c4 = (i & 15) * 4;
        float4 qv = *(const float4*)(g_q + base + (size_t)r * 64 + c4);
        float4 kv = *(const float4*)(g_k + base + (size_t)r * 64 + c4);
        __nv_bfloat162 h01, l01, h23, l23;
        split4(qv, h01, l01, h23, l23);
        *(__nv_bfloat162*)(sQhi + r*72 + c4)     = h01;
        *(__nv_bfloat162*)(sQhi + r*72 + c4 + 2) = h23;
        *(__nv_bfloat162*)(sQlo + r*72 + c4)     = l01;
        *(__nv_bfloat162*)(sQlo + r*72 + c4 + 2) = l23;
        split4(kv, h01, l01, h23, l23);
        *(__nv_bfloat162*)(sKhi + r*72 + c4)     = h01;
        *(__nv_bfloat162*)(sKhi + r*72 + c4 + 2) = h23;
        *(__nv_bfloat162*)(sKlo + r*72 + c4)     = l01;
        *(__nv_bfloat162*)(sKlo + r*72 + c4 + 2) = l23;
    }
    __syncthreads();

    // QK^T: 16 warps, warp tile 16 rows x 64 cols
    {
        int r0 = (wid >> 1) * 16;
        int cbase = (wid & 1) * 64;
        wmma::fragment<wmma::accumulator, 16, 16, 16, float> c[4];
        #pragma unroll
        for (int j = 0; j < 4; j++) wmma::fill_fragment(c[j], 0.0f);
        #pragma unroll
        for (int sk = 0; sk < 4; sk++) {
            int k0 = sk * 16;
            wmma::fragment<wmma::matrix_a, 16, 16, 16, __nv_bfloat16, wmma::row_major> ah, al;
            wmma::load_matrix_sync(ah, &sQhi[r0 * 72 + k0], 72);
            wmma::load_matrix_sync(al, &sQlo[r0 * 72 + k0], 72);
            #pragma unroll
            for (int j = 0; j < 4; j++) {
                int col0 = cbase + j * 16;
                wmma::fragment<wmma::matrix_b, 16, 16, 16, __nv_bfloat16, wmma::col_major> bh, bl;
                wmma::load_matrix_sync(bh, &sKhi[col0 * 72 + k0], 72);
                wmma::load_matrix_sync(bl, &sKlo[col0 * 72 + k0], 72);
                wmma::mma_sync(c[j], ah, bh, c[j]);
                wmma::mma_sync(c[j], ah, bl, c[j]);
                wmma::mma_sync(c[j], al, bh, c[j]);
            }
        }
        #pragma unroll
        for (int j = 0; j < 4; j++) {
            #pragma unroll
            for (int e = 0; e < c[j].num_elements; e++) c[j].x[e] *= SCALE_ATTN;
            wmma::store_matrix_sync(&sS[r0 * SS_LD + cbase + j * 16], c[j], SS_LD, wmma::mem_row_major);
        }
    }
    __syncthreads();

    // softmax: 4 threads per row
    {
        int r = tid >> 2;
        int c0 = (tid & 3) * 32;
        float mx = -3.0e38f;
        for (int c = c0; c < c0 + 32; c++)
            if (c <= r) mx = fmaxf(mx, sS[r * SS_LD + c]);
        mx = fmaxf(mx, __shfl_xor_sync(0xffffffffu, mx, 1));
        mx = fmaxf(mx, __shfl_xor_sync(0xffffffffu, mx, 2));
        float sum = 0.f;
        for (int c = c0; c < c0 + 32; c++) {
            float e = (c <= r) ? fexp(sS[r * SS_LD + c] - mx) : 0.f;
            sum += e;
            __nv_bfloat16 hi, lo;
            split2(e, hi, lo);
            sPhi[r * 136 + c] = hi;
            sPlo[r * 136 + c] = lo;
        }
        sum += __shfl_xor_sync(0xffffffffu, sum, 1);
        sum += __shfl_xor_sync(0xffffffffu, sum, 2);
        if ((tid & 3) == 0) rowsum[r] = sum;
    }
    // V load into Q slots
    #pragma unroll
    for (int u = 0; u < 4; u++) {
        int i = tid + u * 512;
        int r = i >> 4, c4 = (i & 15) * 4;
        float4 vv = *(const float4*)(g_v + base + (size_t)r * 64 + c4);
        __nv_bfloat162 h01, l01, h23, l23;
        split4(vv, h01, l01, h23, l23);
        *(__nv_bfloat162*)(sVhi + r*72 + c4)     = h01;
        *(__nv_bfloat162*)(sVhi + r*72 + c4 + 2) = h23;
        *(__nv_bfloat162*)(sVlo + r*72 + c4)     = l01;
        *(__nv_bfloat162*)(sVlo + r*72 + c4 + 2) = l23;
    }
    __syncthreads();

    // S_t = K^T V (64x64): one 16x16 tile per warp
    {
        int d0 = (wid >> 2) * 16;
        int e0 = (wid & 3) * 16;
        wmma::fragment<wmma::accumulator, 16, 16, 16, float> c;
        wmma::fill_fragment(c, 0.0f);
        #pragma unroll
        for (int sk = 0; sk < 8; sk++) {
            int r0 = sk * 16;
            wmma::fragment<wmma::matrix_a, 16, 16, 16, __nv_bfloat16, wmma::col_major> ah, al;
            wmma::fragment<wmma::matrix_b, 16, 16, 16, __nv_bfloat16, wmma::row_major> bh, bl;
            wmma::load_matrix_sync(ah, &sKhi[r0 * 72 + d0], 72);
            wmma::load_matrix_sync(al, &sKlo[r0 * 72 + d0], 72);
            wmma::load_matrix_sync(bh, &sVhi[r0 * 72 + e0], 72);
            wmma::load_matrix_sync(bl, &sVlo[r0 * 72 + e0], 72);
            wmma::mma_sync(c, ah, bh, c);
            wmma::mma_sync(c, ah, bl, c);
            wmma::mma_sync(c, al, bh, c);
        }
        size_t kb = (((size_t)b * NH + h) * NT + t) * (HD * HD);
        wmma::store_matrix_sync(g_kvsum + kb + (size_t)d0 * 64 + e0, c, 64, wmma::mem_row_major);
    }

    // o_intra = P @ V (128x64): warp tile 16x32
    {
        int r0 = (wid >> 1) * 16;
        int cbase = (wid & 1) * 32;
        wmma::fragment<wmma::accumulator, 16, 16, 16, float> c[2];
        #pragma unroll
        for (int j = 0; j < 2; j++) wmma::fill_fragment(c[j], 0.0f);
        #pragma unroll
        for (int sk = 0; sk < 8; sk++) {
            int k0 = sk * 16;
            wmma::fragment<wmma::matrix_a, 16, 16, 16, __nv_bfloat16, wmma::row_major> ah, al;
            wmma::load_matrix_sync(ah, &sPhi[r0 * 136 + k0], 136);
            wmma::load_matrix_sync(al, &sPlo[r0 * 136 + k0], 136);
            #pragma unroll
            for (int j = 0; j < 2; j++) {
                int col0 = cbase + j * 16;
                wmma::fragment<wmma::matrix_b, 16, 16, 16, __nv_bfloat16, wmma::row_major> bh, bl;
                wmma::load_matrix_sync(bh, &sVhi[k0 * 72 + col0], 72);
                wmma::load_matrix_sync(bl, &sVlo[k0 * 72 + col0], 72);
                wmma::mma_sync(c[j], ah, bh, c[j]);
                wmma::mma_sync(c[j], ah, bl, c[j]);
                wmma::mma_sync(c[j], al, bh, c[j]);
            }
        }
        __syncthreads();
        #pragma unroll
        for (int j = 0; j < 2; j++)
            wmma::store_matrix_sync(&sS[r0 * SS_LD + cbase + j * 16], c[j], SS_LD, wmma::mem_row_major);
    }
    __syncthreads();

    #pragma unroll
    for (int u = 0; u < 4; u++) {
        int i = tid + u * 512;
        int r = i >> 4, c4 = (i & 15) * 4;
        float inv = 1.0f / rowsum[r];
        float4 o;
        o.x = sS[r * SS_LD + c4 + 0] * inv;
        o.y = sS[r * SS_LD + c4 + 1] * inv;
        o.z = sS[r * SS_LD + c4 + 2] * inv;
        o.w = sS[r * SS_LD + c4 + 3] * inv;
        size_t grow = (size_t)b * SEQ + (size_t)t * CHUNK + r;
        *(float4*)(g_attn + grow * DIMC + h * 64 + c4) = o;
    }
}

// ---------------- exclusive prefix-sum of chunk KV matrices ----------------
__global__ void __launch_bounds__(256) kv_prefix() {
    int blk = blockIdx.x;
    int bh = blk >> 3, s = blk & 7;
    int tid = threadIdx.x;
    size_t base = (size_t)bh * NT * (HD * HD) + s * 512 + tid * 2;
    float2 acc = make_float2(0.f, 0.f);
    for (int t = 0; t < NT; t++) {
        size_t off = base + (size_t)t * (HD * HD);
        float2 v = *(const float2*)(g_kvsum + off);
        *(float2*)(g_kvpre + off) = acc;
        acc.x += v.x; acc.y += v.y;
    }
}

// ---------------- o_inter = q @ kv_prefix ----------------
#define IQHI 0
#define IQLO (128*72)
#define IKHI (2*128*72)
#define IKLO (2*128*72 + 64*72)
#define IBF_TOTAL (2*128*72 + 2*64*72)
__global__ void __launch_bounds__(256) attn_inter() {
    int t = blockIdx.x, h = blockIdx.y, b = blockIdx.z;
    extern __shared__ __align__(16) char smraw2[];
    __nv_bfloat16* bfm = (__nv_bfloat16*)smraw2;
    float* sO = (float*)(smraw2 + (size_t)IBF_TOTAL * 2);

    __nv_bfloat16* sQhi = bfm + IQHI;
    __nv_bfloat16* sQlo = bfm + IQLO;
    __nv_bfloat16* sKhi = bfm + IKHI;
    __nv_bfloat16* sKlo = bfm + IKLO;

    size_t base = (((size_t)b * NH + h) * NT + t) * (CHUNK * HD);
    size_t kb   = (((size_t)b * NH + h) * NT + t) * (HD * HD);
    int tid = threadIdx.x;
    int wid = tid >> 5;

    #pragma unroll
    for (int u = 0; u < 8; u++) {
        int i = tid + u * 256;
        int r = i >> 4, c4 = (i & 15) * 4;
        float4 qv = *(const float4*)(g_q + base + (size_t)r * 64 + c4);
        __nv_bfloat162 h01, l01, h23, l23;
        split4(qv, h01, l01, h23, l23);
        *(__nv_bfloat162*)(sQhi + r*72 + c4)     = h01;
        *(__nv_bfloat162*)(sQhi + r*72 + c4 + 2) = h23;
        *(__nv_bfloat162*)(sQlo + r*72 + c4)     = l01;
        *(__nv_bfloat162*)(sQlo + r*72 + c4 + 2) = l23;
    }
    #pragma unroll
    for (int u = 0; u < 4; u++) {
        int i = tid + u * 256;
        int r = i >> 4, c4 = (i & 15) * 4;
        float4 kv = *(const float4*)(g_kvpre + kb + (size_t)r * 64 + c4);
        __nv_bfloat162 h01, l01, h23, l23;
        split4(kv, h01, l01, h23, l23);
        *(__nv_bfloat162*)(sKhi + r*72 + c4)     = h01;
        *(__nv_bfloat162*)(sKhi + r*72 + c4 + 2) = h23;
        *(__nv_bfloat162*)(sKlo + r*72 + c4)     = l01;
        *(__nv_bfloat162*)(sKlo + r*72 + c4 + 2) = l23;
    }
    __syncthreads();

    {
        int r0 = wid * 16;
        wmma::fragment<wmma::accumulator, 16, 16, 16, float> c[4];
        #pragma unroll
        for (int j = 0; j < 4; j++) wmma::fill_fragment(c[j], 0.0f);
        #pragma unroll
        for (int sk = 0; sk < 4; sk++) {
            int k0 = sk * 16;
            wmma::fragment<wmma::matrix_a, 16, 16, 16, __nv_bfloat16, wmma::row_major> ah, al;
            wmma::load_matrix_sync(ah, &sQhi[r0 * 72 + k0], 72);
            wmma::load_matrix_sync(al, &sQlo[r0 * 72 + k0], 72);
            #pragma unroll
            for (int j = 0; j < 4; j++) {
                int col0 = j * 16;
                wmma::fragment<wmma::matrix_b, 16, 16, 16, __nv_bfloat16, wmma::row_major> bh, bl;
                wmma::load_matrix_sync(bh, &sKhi[k0 * 72 + col0], 72);
                wmma::load_matrix_sync(bl, &sKlo[k0 * 72 + col0], 72);
                wmma::mma_sync(c[j], ah, bh, c[j]);
                wmma::mma_sync(c[j], ah, bl, c[j]);
                wmma::mma_sync(c[j], al, bh, c[j]);
            }
        }
        #pragma unroll
        for (int j = 0; j < 4; j++)
            wmma::store_matrix_sync(&sO[r0 * 68 + j * 16], c[j], 68, wmma::mem_row_major);
    }
    __syncthreads();

    #pragma unroll
    for (int u = 0; u < 8; u++) {
        int i = tid + u * 256;
        int r = i >> 4, c4 = (i & 15) * 4;
        size_t grow = (size_t)b * SEQ + (size_t)t * CHUNK + r;
        float* dst = g_attn + grow * DIMC + h * 64 + c4;
        float4 old = *(float4*)dst;
        old.x += sO[r * 68 + c4 + 0];
        old.y += sO[r * 68 + c4 + 1];
        old.z += sO[r * 68 + c4 + 2];
        old.w += sO[r * 68 + c4 + 3];
        *(float4*)dst = old;
    }
}

// ---------------- launch ----------------
extern "C" void kernel_launch(void* const* d_in, const int* in_sizes, int n_in,
                              void* d_out, int out_size) {
    const float* x       = (const float*)d_in[0];
    const float* cosb    = (const float*)d_in[1];
    const float* sinb    = (const float*)d_in[2];
    const float* qkv_w   = (const float*)d_in[3];
    const float* qkv_b   = (const float*)d_in[4];
    const float* qkv_nw  = (const float*)d_in[5];
    const float* proj_w  = (const float*)d_in[6];
    const float* proj_b  = (const float*)d_in[7];
    const float* proj_nw = (const float*)d_in[8];
    const float* norm_w  = (const float*)d_in[9];
    float* out = (float*)d_out;

    size_t smem_intra = (size_t)BF_TOTAL * 2 + (128 * SS_LD + 128) * sizeof(float);
    size_t smem_inter = (size_t)IBF_TOTAL * 2 + (128 * 68) * sizeof(float);

    static bool attr_done = false;
    if (!attr_done) {
        cudaFuncSetAttribute(attn_intra, cudaFuncAttributeMaxDynamicSharedMemorySize, (int)smem_intra);
        cudaFuncSetAttribute(attn_inter, cudaFuncAttributeMaxDynamicSharedMemorySize, (int)smem_inter);
        cudaFuncSetAttribute(gemm_bf16_t<true>,  cudaFuncAttributeMaxDynamicSharedMemorySize, GEMM_SMEM);
        cudaFuncSetAttribute(gemm_bf16_t<false>, cudaFuncAttributeMaxDynamicSharedMemorySize, GEMM_SMEM);
        attr_done = true;
    }

    __nv_bfloat16 *xq_p, *wqkv_p, *wproj_p, *xq2_p;
    float *adeq_p, *adeq2_p;
    cudaGetSymbolAddress((void**)&xq_p,    g_xq);
    cudaGetSymbolAddress((void**)&wqkv_p,  g_wq_qkv);
    cudaGetSymbolAddress((void**)&wproj_p, g_wq_proj);
    cudaGetSymbolAddress((void**)&xq2_p,   g_xq2);
    cudaGetSymbolAddress((void**)&adeq_p,  g_adeq);
    cudaGetSymbolAddress((void**)&adeq2_p, g_adeq2);

    // Launch order: gemm<QKV> is launch #4 -> ncu capture slot.
    absmean_partial<<<256, 256>>>(qkv_w, QKVN * DIMC);                                    // 1
    quant_weight_fused<<<QKVN * DIMC / 1024, 256>>>(qkv_w, wqkv_p, QKVN * DIMC, 0);       // 2
    act_quant_x<<<NROWS, 256>>>(x, qkv_nw);                                               // 3
    {
        dim3 grid(QKVN / 128, NROWS / 128);
        gemm_bf16_t<true><<<grid, 256, GEMM_SMEM>>>(xq_p, wqkv_p, nullptr, QKVN,
                                                    adeq_p, 0, qkv_b, cosb, sinb);        // 4 <- profiled
    }
    absmean_partial<<<256, 256>>>(proj_w, DIMC * DIMC);                                   // 5
    quant_weight_fused<<<DIMC * DIMC / 1024, 256>>>(proj_w, wproj_p, DIMC * DIMC, 1);     // 6

    {
        dim3 grid(NT, NH, BATCH);
        attn_intra<<<grid, 512, smem_intra>>>();                                          // 7
    }
    kv_prefix<<<256, 256>>>();                                                            // 8
    {
        dim3 grid(NT, NH, BATCH);
        attn_inter<<<grid, 256, smem_inter>>>();                                          // 9
    }

    norm2_quant<<<NROWS, 256>>>(norm_w, proj_nw);                                         // 10
    {
        dim3 grid(DIMC / 128, NROWS / 128);
        gemm_bf16_t<false><<<grid, 256, GEMM_SMEM>>>(xq2_p, wproj_p, out, DIMC,
                                                     adeq2_p, 1, proj_b, cosb, sinb);     // 11
    }
}

// round 10
// speedup vs baseline: 2.5777x; 1.2786x over previous
#include <cuda_runtime.h>
#include <cuda_bf16.h>
#include <mma.h>
#include <cstdint>

using namespace nvcuda;

#define BATCH 2
#define SEQ   8192
#define DIMC  1024
#define NH    16
#define HD    64
#define CHUNK 128
#define NT    64
#define NROWS 16384
#define QKVN  3072
#define SCALE_ATTN 0.125f
#define EPS_BIT 1.1920929e-07f
#define EPS_OUT 1e-06f

// tile-major padded layout: [rowblk][kt 16][row 128][72], only cols 0..63 meaningful
#define TPAD 72
#define TILE_ELEMS (128 * TPAD)          // 9216 elems
#define TILE_BYTES (TILE_ELEMS * 2)      // 18432 bytes

// ---------------- static device scratch ----------------
__device__ __nv_bfloat16 g_xq[(size_t)NROWS * 16 * TILE_ELEMS / 128];       // NROWS*1152
__device__ float         g_adeq[NROWS];
__device__ __nv_bfloat16 g_wq_qkv[(size_t)QKVN * 16 * TILE_ELEMS / 128];
__device__ __nv_bfloat16 g_wq_proj[(size_t)DIMC * 16 * TILE_ELEMS / 128];
__device__ float         g_wdeq[2];
__device__ float         g_part[256];
__device__ float         g_q[(size_t)BATCH * NH * NT * CHUNK * HD];
__device__ float         g_k[(size_t)BATCH * NH * NT * CHUNK * HD];
__device__ float         g_v[(size_t)BATCH * NH * NT * CHUNK * HD];
__device__ float         g_kvsum[(size_t)BATCH * NH * NT * HD * HD];
__device__ float         g_kvpre[(size_t)BATCH * NH * NT * HD * HD];
__device__ float         g_attn[(size_t)NROWS * DIMC];
__device__ __nv_bfloat16 g_xq2[(size_t)NROWS * 16 * TILE_ELEMS / 128];
__device__ float         g_adeq2[NROWS];

// ---------------- helpers ----------------
__device__ __forceinline__ uint32_t smem_u32(const void* smem_ptr) {
    uint32_t addr;
    asm("{ .reg .u64 tmp; cvta.to.shared.u64 tmp, %1; cvt.u32.u64 %0, tmp; }"
        : "=r"(addr) : "l"(smem_ptr));
    return addr;
}

#define MBAR_INIT(addr, cnt) \
    asm volatile("mbarrier.init.shared.b64 [%0], %1;" :: "r"((uint32_t)(addr)), "r"((uint32_t)(cnt)) : "memory")
#define MBAR_EXPECT_TX(addr, bytes) \
    asm volatile("mbarrier.arrive.expect_tx.shared.b64 _, [%0], %1;" :: "r"((uint32_t)(addr)), "r"((uint32_t)(bytes)) : "memory")
#define MBAR_WAIT_PARITY(mbar, parity) do { \
    uint32_t _mbar = (uint32_t)(mbar); \
    uint32_t _parity = (uint32_t)(parity); \
    uint32_t _done; \
    asm volatile( \
        "{\n\t.reg .pred p;\n\t" \
        "mbarrier.try_wait.parity.shared.b64 p, [%1], %2;\n\t" \
        "selp.b32 %0, 1, 0, p;\n\t}" \
        : "=r"(_done) : "r"(_mbar), "r"(_parity) : "memory"); \
    if (!_done) { \
        asm volatile( \
            "{\n\t.reg .pred P1;\n\t" \
            "WAIT_LOOP_%=:\n\t" \
            "mbarrier.try_wait.parity.shared.b64 P1, [%0], %1;\n\t" \
            "@P1 bra.uni WAIT_DONE_%=;\n\t" \
            "bra.uni WAIT_LOOP_%=;\n\t" \
            "WAIT_DONE_%=:\n\t}" \
            :: "r"(_mbar), "r"(_parity) : "memory"); \
    } \
} while(0)
// 1D bulk async copy gmem -> smem with mbarrier tx completion (sm_90 baseline)
#define BULK_G2S(dst, src, bytes, mbar) \
    asm volatile("cp.async.bulk.shared::cta.global.mbarrier::complete_tx::bytes [%0], [%1], %2, [%3];" \
        :: "r"((uint32_t)(dst)), "l"(src), "r"((uint32_t)(bytes)), "r"((uint32_t)(mbar)) : "memory")

__device__ __forceinline__ float fexp(float x) {
    x = fmaxf(x, -80.0f);
    float y = x * 1.4426950408889634f;
    float n = rintf(y);
    float g = fmaf(-n, 0.6931471805599453f, x);
    float p = 1.9841270e-4f;
    p = fmaf(p, g, 1.3888889e-3f);
    p = fmaf(p, g, 8.3333333e-3f);
    p = fmaf(p, g, 4.1666667e-2f);
    p = fmaf(p, g, 1.6666667e-1f);
    p = fmaf(p, g, 5.0e-1f);
    p = fmaf(p, g, 1.0f);
    p = fmaf(p, g, 1.0f);
    float s = __int_as_float(((int)n + 127) << 23);
    return p * s;
}
__device__ __forceinline__ void split2(float v, __nv_bfloat16& hi, __nv_bfloat16& lo) {
    hi = __float2bfloat16(v);
    lo = __float2bfloat16(v - __bfloat162float(hi));
}
__device__ __forceinline__ void split4(float4 v,
    __nv_bfloat162& h01, __nv_bfloat162& l01,
    __nv_bfloat162& h23, __nv_bfloat162& l23) {
    h01.x = __float2bfloat16(v.x); l01.x = __float2bfloat16(v.x - __bfloat162float(h01.x));
    h01.y = __float2bfloat16(v.y); l01.y = __float2bfloat16(v.y - __bfloat162float(h01.y));
    h23.x = __float2bfloat16(v.z); l23.x = __float2bfloat16(v.z - __bfloat162float(h23.x));
    h23.y = __float2bfloat16(v.w); l23.y = __float2bfloat16(v.w - __bfloat162float(h23.y));
}
// destination index in tile-major padded layout for logical (row, col) of a [*,1024] matrix
__device__ __forceinline__ size_t tile_idx(int row, int col) {
    return (((size_t)(row >> 7) * 16 + (col >> 6)) * 128 + (row & 127)) * TPAD + (col & 63);
}

// ---------------- weight quant ----------------
__global__ void absmean_partial(const float* __restrict__ w, int n) {
    __shared__ float red[256];
    int tid = threadIdx.x;
    float s = 0.f;
    for (int i = blockIdx.x * 256 + tid; i < n; i += 65536) s += fabsf(w[i]);
    red[tid] = s; __syncthreads();
    for (int st = 128; st > 0; st >>= 1) { if (tid < st) red[tid] += red[tid + st]; __syncthreads(); }
    if (tid == 0) g_part[blockIdx.x] = red[0];
}

__global__ void __launch_bounds__(256) quant_weight_fused(const float* __restrict__ w,
                                                          __nv_bfloat16* __restrict__ wq,
                                                          int n, int slot) {
    __shared__ float red[256];
    int tid = threadIdx.x;
    red[tid] = g_part[tid]; __syncthreads();
    for (int st = 128; st > 0; st >>= 1) { if (tid < st) red[tid] += red[tid + st]; __syncthreads(); }
    float wdeq = fmaxf(red[0] / (float)n, 1e-5f);
    if (blockIdx.x == 0 && tid == 0) g_wdeq[slot] = wdeq;
    float s = 1.0f / wdeq;
    int i4 = (blockIdx.x * 256 + tid) * 4;
    if (i4 >= n) return;
    float4 wv = *(const float4*)(w + i4);
    __nv_bfloat162 p0, p1;
    p0.x = __float2bfloat16(fminf(fmaxf(rintf(wv.x * s), -1.f), 1.f));
    p0.y = __float2bfloat16(fminf(fmaxf(rintf(wv.y * s), -1.f), 1.f));
    p1.x = __float2bfloat16(fminf(fmaxf(rintf(wv.z * s), -1.f), 1.f));
    p1.y = __float2bfloat16(fminf(fmaxf(rintf(wv.w * s), -1.f), 1.f));
    int row = i4 >> 10, col = i4 & 1023;
    __nv_bfloat16* out = wq + tile_idx(row, col);
    *(__nv_bfloat162*)(out)     = p0;
    *(__nv_bfloat162*)(out + 2) = p1;
}

// ---------------- activation quant for QKV input ----------------
__global__ void __launch_bounds__(256) act_quant_x(const float* __restrict__ x,
                                                   const float* __restrict__ nw) {
    __shared__ float red[256];
    __shared__ float bc;
    int row = blockIdx.x, tid = threadIdx.x;
    float4 xv = ((const float4*)(x + (size_t)row * DIMC))[tid];
    float4 wv = ((const float4*)nw)[tid];
    float ss = xv.x*xv.x + xv.y*xv.y + xv.z*xv.z + xv.w*xv.w;
    red[tid] = ss; __syncthreads();
    for (int st = 128; st > 0; st >>= 1) { if (tid < st) red[tid] += red[tid + st]; __syncthreads(); }
    if (tid == 0) bc = rsqrtf(red[0] * (1.0f / DIMC) + EPS_BIT);
    __syncthreads();
    float r = bc;
    float n0 = xv.x*r*wv.x, n1 = xv.y*r*wv.y, n2 = xv.z*r*wv.z, n3 = xv.w*r*wv.w;
    float amax = fmaxf(fmaxf(fabsf(n0), fabsf(n1)), fmaxf(fabsf(n2), fabsf(n3)));
    red[tid] = amax; __syncthreads();
    for (int st = 128; st > 0; st >>= 1) { if (tid < st) red[tid] = fmaxf(red[tid], red[tid + st]); __syncthreads(); }
    if (tid == 0) {
        float mx = fmaxf(red[0], 1e-5f);
        bc = 127.0f / mx;
        g_adeq[row] = mx * (1.0f / 127.0f);
    }
    __syncthreads();
    float sc = bc;
    __nv_bfloat162 p0, p1;
    p0.x = __float2bfloat16(fminf(fmaxf(rintf(n0 * sc), -128.f), 127.f));
    p0.y = __float2bfloat16(fminf(fmaxf(rintf(n1 * sc), -128.f), 127.f));
    p1.x = __float2bfloat16(fminf(fmaxf(rintf(n2 * sc), -128.f), 127.f));
    p1.y = __float2bfloat16(fminf(fmaxf(rintf(n3 * sc), -128.f), 127.f));
    __nv_bfloat16* out = g_xq + tile_idx(row, tid * 4);
    *(__nv_bfloat162*)(out)     = p0;
    *(__nv_bfloat162*)(out + 2) = p1;
}

// ---------------- double-norm + act quant for proj input ----------------
__global__ void __launch_bounds__(256) norm2_quant(const float* __restrict__ nw,
                                                   const float* __restrict__ pnw) {
    __shared__ float red[256];
    __shared__ float bc;
    int row = blockIdx.x, tid = threadIdx.x;
    float4 xv = ((const float4*)(g_attn + (size_t)row * DIMC))[tid];
    float4 wv = ((const float4*)nw)[tid];
    float4 pv = ((const float4*)pnw)[tid];
    float ss = xv.x*xv.x + xv.y*xv.y + xv.z*xv.z + xv.w*xv.w;
    red[tid] = ss; __syncthreads();
    for (int st = 128; st > 0; st >>= 1) { if (tid < st) red[tid] += red[tid + st]; __syncthreads(); }
    if (tid == 0) bc = rsqrtf(red[0] * (1.0f / DIMC) + EPS_OUT);
    __syncthreads();
    float r1 = bc;
    float z0 = xv.x*r1*wv.x, z1 = xv.y*r1*wv.y, z2 = xv.z*r1*wv.z, z3 = xv.w*r1*wv.w;
    float ss2 = z0*z0 + z1*z1 + z2*z2 + z3*z3;
    red[tid] = ss2; __syncthreads();
    for (int st = 128; st > 0; st >>= 1) { if (tid < st) red[tid] += red[tid + st]; __syncthreads(); }
    if (tid == 0) bc = rsqrtf(red[0] * (1.0f / DIMC) + EPS_BIT);
    __syncthreads();
    float r2 = bc;
    float n0 = z0*r2*pv.x, n1 = z1*r2*pv.y, n2 = z2*r2*pv.z, n3 = z3*r2*pv.w;
    float amax = fmaxf(fmaxf(fabsf(n0), fabsf(n1)), fmaxf(fabsf(n2), fabsf(n3)));
    red[tid] = amax; __syncthreads();
    for (int st = 128; st > 0; st >>= 1) { if (tid < st) red[tid] = fmaxf(red[tid], red[tid + st]); __syncthreads(); }
    if (tid == 0) {
        float mx = fmaxf(red[0], 1e-5f);
        bc = 127.0f / mx;
        g_adeq2[row] = mx * (1.0f / 127.0f);
    }
    __syncthreads();
    float sc = bc;
    __nv_bfloat162 p0, p1;
    p0.x = __float2bfloat16(fminf(fmaxf(rintf(n0 * sc), -128.f), 127.f));
    p0.y = __float2bfloat16(fminf(fmaxf(rintf(n1 * sc), -128.f), 127.f));
    p1.x = __float2bfloat16(fminf(fmaxf(rintf(n2 * sc), -128.f), 127.f));
    p1.y = __float2bfloat16(fminf(fmaxf(rintf(n3 * sc), -128.f), 127.f));
    __nv_bfloat16* out = g_xq2 + tile_idx(row, tid * 4);
    *(__nv_bfloat162*)(out)     = p0;
    *(__nv_bfloat162*)(out + 2) = p1;
}

// ---------------- bf16 HMMA GEMM, cp.async.bulk 3-stage ring ----------------
// A, W in tile-major padded layout. C[M,N] = A@W^T * adeq*wdeq + bias.
#define GLD TPAD
#define STAGE_BYTES (2 * TILE_BYTES)          // A+B per stage = 36864
#define MBAR_OFF (3 * STAGE_BYTES)            // 110592
#define GEMM_SMEM (MBAR_OFF + 64)
template<bool QKV>
__global__ void __launch_bounds__(256, 2) gemm_bf16_t(
    const __nv_bfloat16* __restrict__ A, const __nv_bfloat16* __restrict__ W,
    float* __restrict__ C, int N,
    const float* __restrict__ adeq, int wslot, const float* __restrict__ bias,
    const float* __restrict__ cosb, const float* __restrict__ sinb)
{
    extern __shared__ __align__(16) char gsm[];
    uint32_t sb = smem_u32(gsm);
    uint32_t mb = sb + MBAR_OFF;

    int tid = threadIdx.x;
    int wid = tid >> 5, lane = tid & 31;
    int wm = wid >> 2, wn = wid & 3;            // warp tile 64(M) x 32(N)
    int bm = blockIdx.y * 128;
    int bn = blockIdx.x * 128;

    const __nv_bfloat16* Asrc = A + (size_t)blockIdx.y * 16 * TILE_ELEMS;
    const __nv_bfloat16* Bsrc = W + (size_t)blockIdx.x * 16 * TILE_ELEMS;

    wmma::fragment<wmma::accumulator, 16, 16, 16, float> c[4][2];
    #pragma unroll
    for (int i = 0; i < 4; i++)
        #pragma unroll
        for (int j = 0; j < 2; j++) wmma::fill_fragment(c[i][j], 0.0f);

    if (tid == 0) {
        #pragma unroll
        for (int s = 0; s < 3; s++) MBAR_INIT(mb + s * 8, 1);
    }
    __syncthreads();
    if (tid == 0) {
        #pragma unroll
        for (int s = 0; s < 2; s++) {
            MBAR_EXPECT_TX(mb + s * 8, 2 * TILE_BYTES);
            BULK_G2S(sb + s * STAGE_BYTES,              Asrc + s * TILE_ELEMS, TILE_BYTES, mb + s * 8);
            BULK_G2S(sb + s * STAGE_BYTES + TILE_BYTES, Bsrc + s * TILE_ELEMS, TILE_BYTES, mb + s * 8);
        }
    }

    int m0 = wm * 64, n0 = wn * 32;
    for (int kt = 0; kt < 16; kt++) {
        int sRead = kt % 3;
        MBAR_WAIT_PARITY(mb + sRead * 8, (kt / 3) & 1);
        __syncthreads();   // kt data ready AND all warps done with kt-1
        if (tid == 0 && kt + 2 < 16) {
            int sW = (kt + 2) % 3;
            MBAR_EXPECT_TX(mb + sW * 8, 2 * TILE_BYTES);
            BULK_G2S(sb + sW * STAGE_BYTES,              Asrc + (kt + 2) * TILE_ELEMS, TILE_BYTES, mb + sW * 8);
            BULK_G2S(sb + sW * STAGE_BYTES + TILE_BYTES, Bsrc + (kt + 2) * TILE_ELEMS, TILE_BYTES, mb + sW * 8);
        }
        const __nv_bfloat16* as = (const __nv_bfloat16*)(gsm + sRead * STAGE_BYTES);
        const __nv_bfloat16* bs = (const __nv_bfloat16*)(gsm + sRead * STAGE_BYTES + TILE_BYTES);
        #pragma unroll
        for (int sk = 0; sk < 4; sk++) {
            int k0 = sk * 16;
            wmma::fragment<wmma::matrix_a, 16, 16, 16, __nv_bfloat16, wmma::row_major> af[4];
            wmma::fragment<wmma::matrix_b, 16, 16, 16, __nv_bfloat16, wmma::col_major> bf[2];
            #pragma unroll
            for (int i = 0; i < 4; i++)
                wmma::load_matrix_sync(af[i], &as[(m0 + i * 16) * GLD + k0], GLD);
            #pragma unroll
            for (int j = 0; j < 2; j++)
                wmma::load_matrix_sync(bf[j], &bs[(n0 + j * 16) * GLD + k0], GLD);
            #pragma unroll
            for (int i = 0; i < 4; i++)
                #pragma unroll
                for (int j = 0; j < 2; j++)
                    wmma::mma_sync(c[i][j], af[i], bf[j], c[i][j]);
        }
    }
    __syncthreads();   // all MMAs done; stage smem reusable for C staging

    float wdeq = g_wdeq[wslot];
    float* CsAll = (float*)gsm;
    float* Csw = &CsAll[wid * 320];
    #pragma unroll
    for (int i = 0; i < 4; i++) {
        #pragma unroll
        for (int j = 0; j < 2; j++) {
            __syncwarp();
            wmma::store_matrix_sync(Csw, c[i][j], 20, wmma::mem_row_major);
            __syncwarp();
            int r  = lane >> 1;
            int cc = (lane & 1) * 8;
            int grow = bm + wm * 64 + i * 16 + r;
            int gcol = bn + wn * 32 + j * 16 + cc;
            float sc = adeq[grow] * wdeq;
            float v[8];
            #pragma unroll
            for (int u = 0; u < 8; u++)
                v[u] = Csw[r * 20 + cc + u] * sc + bias[gcol + u];
            if (QKV) {
                int which = gcol >> 10;
                int rem = gcol & 1023;
                int h = rem >> 6, d = rem & 63;
                int b = grow >> 13, n = grow & 8191;
                int t = n >> 7, rr = n & 127;
                if (which < 2) {
                    int i0 = d >> 1;
                    #pragma unroll
                    for (int m = 0; m < 4; m++) {
                        float cth = cosb[n * 32 + i0 + m];
                        float sth = sinb[n * 32 + i0 + m];
                        float e = v[2*m], o = v[2*m+1];
                        v[2*m]   = e * cth - o * sth;
                        v[2*m+1] = o * cth + e * sth;
                    }
                }
                float* dstbase = (which == 0) ? g_q : (which == 1) ? g_k : g_v;
                float* dst = dstbase + (((size_t)b * NH + h) * NT + t) * (CHUNK * HD)
                           + (size_t)rr * 64 + d;
                *(float4*)(dst)     = make_float4(v[0], v[1], v[2], v[3]);
                *(float4*)(dst + 4) = make_float4(v[4], v[5], v[6], v[7]);
            } else {
                float* dst = C + (size_t)grow * N + gcol;
                *(float4*)(dst)     = make_float4(v[0], v[1], v[2], v[3]);
                *(float4*)(dst + 4) = make_float4(v[4], v[5], v[6], v[7]);
            }
        }
    }
}

// ---------------- intra-chunk attention (split-bf16 tensor cores) ----------------
#define QHI_OFF 0
#define QLO_OFF (128*72)
#define KHI_OFF (2*128*72)
#define KLO_OFF (3*128*72)
#define PHI_OFF (4*128*72)
#define PLO_OFF (4*128*72 + 128*136)
#define BF_TOTAL (4*128*72 + 2*128*136)
#define SS_LD 132

__global__ void __launch_bounds__(512) attn_intra() {
    int t = blockIdx.x, h = blockIdx.y, b = blockIdx.z;
    extern __shared__ __align__(16) char smraw[];
    __nv_bfloat16* bfm = (__nv_bfloat16*)smraw;
    float* sS = (float*)(smraw + (size_t)BF_TOTAL * 2);
    float* rowsum = sS + 128 * SS_LD;

    __nv_bfloat16* sQhi = bfm + QHI_OFF;
    __nv_bfloat16* sQlo = bfm + QLO_OFF;
    __nv_bfloat16* sKhi = bfm + KHI_OFF;
    __nv_bfloat16* sKlo = bfm + KLO_OFF;
    __nv_bfloat16* sPhi = bfm + PHI_OFF;
    __nv_bfloat16* sPlo = bfm + PLO_OFF;
    __nv_bfloat16* sVhi = sQhi;
    __nv_bfloat16* sVlo = sQlo;

    size_t base = (((size_t)b * NH + h) * NT + t) * (CHUNK * HD);
    int tid = threadIdx.x;
    int wid = tid >> 5;

    #pragma unroll
    for (int u = 0; u < 4; u++) {
        int i = tid + u * 512;
        int r = i >> 4, c4 = (i & 15) * 4;
        float4 qv = *(const float4*)(g_q + base + (size_t)r * 64 + c4);
        float4 kv = *(const float4*)(g_k + base + (size_t)r * 64 + c4);
        __nv_bfloat162 h01, l01, h23, l23;
        split4(qv, h01, l01, h23, l23);
        *(__nv_bfloat162*)(sQhi + r*72 + c4)     = h01;
        *(__nv_bfloat162*)(sQhi + r*72 + c4 + 2) = h23;
        *(__nv_bfloat162*)(sQlo + r*72 + c4)     = l01;
        *(__nv_bfloat162*)(sQlo + r*72 + c4 + 2) = l23;
        split4(kv, h01, l01, h23, l23);
        *(__nv_bfloat162*)(sKhi + r*72 + c4)     = h01;
        *(__nv_bfloat162*)(sKhi + r*72 + c4 + 2) = h23;
        *(__nv_bfloat162*)(sKlo + r*72 + c4)     = l01;
        *(__nv_bfloat162*)(sKlo + r*72 + c4 + 2) = l23;
    }
    __syncthreads();

    // QK^T: 16 warps, warp tile 16 rows x 64 cols
    {
        int r0 = (wid >> 1) * 16;
        int cbase = (wid & 1) * 64;
        wmma::fragment<wmma::accumulator, 16, 16, 16, float> c[4];
        #pragma unroll
        for (int j = 0; j < 4; j++) wmma::fill_fragment(c[j], 0.0f);
        #pragma unroll
        for (int sk = 0; sk < 4; sk++) {
            int k0 = sk * 16;
            wmma::fragment<wmma::matrix_a, 16, 16, 16, __nv_bfloat16, wmma::row_major> ah, al;
            wmma::load_matrix_sync(ah, &sQhi[r0 * 72 + k0], 72);
            wmma::load_matrix_sync(al, &sQlo[r0 * 72 + k0], 72);
            #pragma unroll
            for (int j = 0; j < 4; j++) {
                int col0 = cbase + j * 16;
                wmma::fragment<wmma::matrix_b, 16, 16, 16, __nv_bfloat16, wmma::col_major> bh, bl;
                wmma::load_matrix_sync(bh, &sKhi[col0 * 72 + k0], 72);
                wmma::load_matrix_sync(bl, &sKlo[col0 * 72 + k0], 72);
                wmma::mma_sync(c[j], ah, bh, c[j]);
                wmma::mma_sync(c[j], ah, bl, c[j]);
                wmma::mma_sync(c[j], al, bh, c[j]);
            }
        }
        #pragma unroll
        for (int j = 0; j < 4; j++) {
            #pragma unroll
            for (int e = 0; e < c[j].num_elements; e++) c[j].x[e] *= SCALE_ATTN;
            wmma::store_matrix_sync(&sS[r0 * SS_LD + cbase + j * 16], c[j], SS_LD, wmma::mem_row_major);
        }
    }
    __syncthreads();

    // softmax: 4 threads per row
    {
        int r = tid >> 2;
        int c0 = (tid & 3) * 32;
        float mx = -3.0e38f;
        for (int c = c0; c < c0 + 32; c++)
            if (c <= r) mx = fmaxf(mx, sS[r * SS_LD + c]);
        mx = fmaxf(mx, __shfl_xor_sync(0xffffffffu, mx, 1));
        mx = fmaxf(mx, __shfl_xor_sync(0xffffffffu, mx, 2));
        float sum = 0.f;
        for (int c = c0; c < c0 + 32; c++) {
            float e = (c <= r) ? fexp(sS[r * SS_LD + c] - mx) : 0.f;
            sum += e;
            __nv_bfloat16 hi, lo;
            split2(e, hi, lo);
            sPhi[r * 136 + c] = hi;
            sPlo[r * 136 + c] = lo;
        }
        sum += __shfl_xor_sync(0xffffffffu, sum, 1);
        sum += __shfl_xor_sync(0xffffffffu, sum, 2);
        if ((tid & 3) == 0) rowsum[r] = sum;
    }
    // V load into Q slots
    #pragma unroll
    for (int u = 0; u < 4; u++) {
        int i = tid + u * 512;
        int r = i >> 4, c4 = (i & 15) * 4;
        float4 vv = *(const float4*)(g_v + base + (size_t)r * 64 + c4);
        __nv_bfloat162 h01, l01, h23, l23;
        split4(vv, h01, l01, h23, l23);
        *(__nv_bfloat162*)(sVhi + r*72 + c4)     = h01;
        *(__nv_bfloat162*)(sVhi + r*72 + c4 + 2) = h23;
        *(__nv_bfloat162*)(sVlo + r*72 + c4)     = l01;
        *(__nv_bfloat162*)(sVlo + r*72 + c4 + 2) = l23;
    }
    __syncthreads();

    // S_t = K^T V (64x64): one 16x16 tile per warp
    {
        int d0 = (wid >> 2) * 16;
        int e0 = (wid & 3) * 16;
        wmma::fragment<wmma::accumulator, 16, 16, 16, float> c;
        wmma::fill_fragment(c, 0.0f);
        #pragma unroll
        for (int sk = 0; sk < 8; sk++) {
            int r0 = sk * 16;
            wmma::fragment<wmma::matrix_a, 16, 16, 16, __nv_bfloat16, wmma::col_major> ah, al;
            wmma::fragment<wmma::matrix_b, 16, 16, 16, __nv_bfloat16, wmma::row_major> bh, bl;
            wmma::load_matrix_sync(ah, &sKhi[r0 * 72 + d0], 72);
            wmma::load_matrix_sync(al, &sKlo[r0 * 72 + d0], 72);
            wmma::load_matrix_sync(bh, &sVhi[r0 * 72 + e0], 72);
            wmma::load_matrix_sync(bl, &sVlo[r0 * 72 + e0], 72);
            wmma::mma_sync(c, ah, bh, c);
            wmma::mma_sync(c, ah, bl, c);
            wmma::mma_sync(c, al, bh, c);
        }
        size_t kb = (((size_t)b * NH + h) * NT + t) * (HD * HD);
        wmma::store_matrix_sync(g_kvsum + kb + (size_t)d0 * 64 + e0, c, 64, wmma::mem_row_major);
    }

    // o_intra = P @ V (128x64): warp tile 16x32
    {
        int r0 = (wid >> 1) * 16;
        int cbase = (wid & 1) * 32;
        wmma::fragment<wmma::accumulator, 16, 16, 16, float> c[2];
        #pragma unroll
        for (int j = 0; j < 2; j++) wmma::fill_fragment(c[j], 0.0f);
        #pragma unroll
        for (int sk = 0; sk < 8; sk++) {
            int k0 = sk * 16;
            wmma::fragment<wmma::matrix_a, 16, 16, 16, __nv_bfloat16, wmma::row_major> ah, al;
            wmma::load_matrix_sync(ah, &sPhi[r0 * 136 + k0], 136);
            wmma::load_matrix_sync(al, &sPlo[r0 * 136 + k0], 136);
            #pragma unroll
            for (int j = 0; j < 2; j++) {
                int col0 = cbase + j * 16;
                wmma::fragment<wmma::matrix_b, 16, 16, 16, __nv_bfloat16, wmma::row_major> bh, bl;
                wmma::load_matrix_sync(bh, &sVhi[k0 * 72 + col0], 72);
                wmma::load_matrix_sync(bl, &sVlo[k0 * 72 + col0], 72);
                wmma::mma_sync(c[j], ah, bh, c[j]);
                wmma::mma_sync(c[j], ah, bl, c[j]);
                wmma::mma_sync(c[j], al, bh, c[j]);
            }
        }
        __syncthreads();
        #pragma unroll
        for (int j = 0; j < 2; j++)
            wmma::store_matrix_sync(&sS[r0 * SS_LD + cbase + j * 16], c[j], SS_LD, wmma::mem_row_major);
    }
    __syncthreads();

    #pragma unroll
    for (int u = 0; u < 4; u++) {
        int i = tid + u * 512;
        int r = i >> 4, c4 = (i & 15) * 4;
        float inv = 1.0f / rowsum[r];
        float4 o;
        o.x = sS[r * SS_LD + c4 + 0] * inv;
        o.y = sS[r * SS_LD + c4 + 1] * inv;
        o.z = sS[r * SS_LD + c4 + 2] * inv;
        o.w = sS[r * SS_LD + c4 + 3] * inv;
        size_t grow = (size_t)b * SEQ + (size_t)t * CHUNK + r;
        *(float4*)(g_attn + grow * DIMC + h * 64 + c4) = o;
    }
}

// ---------------- exclusive prefix-sum of chunk KV matrices ----------------
__global__ void __launch_bounds__(256) kv_prefix() {
    int blk = blockIdx.x;
    int bh = blk >> 3, s = blk & 7;
    int tid = threadIdx.x;
    size_t base = (size_t)bh * NT * (HD * HD) + s * 512 + tid * 2;
    float2 acc = make_float2(0.f, 0.f);
    for (int t = 0; t < NT; t++) {
        size_t off = base + (size_t)t * (HD * HD);
        float2 v = *(const float2*)(g_kvsum + off);
        *(float2*)(g_kvpre + off) = acc;
        acc.x += v.x; acc.y += v.y;
    }
}

// ---------------- o_inter = q @ kv_prefix ----------------
#define IQHI 0
#define IQLO (128*72)
#define IKHI (2*128*72)
#define IKLO (2*128*72 + 64*72)
#define IBF_TOTAL (2*128*72 + 2*64*72)
__global__ void __launch_bounds__(256) attn_inter() {
    int t = blockIdx.x, h = blockIdx.y, b = blockIdx.z;
    extern __shared__ __align__(16) char smraw2[];
    __nv_bfloat16* bfm = (__nv_bfloat16*)smraw2;
    float* sO = (float*)(smraw2 + (size_t)IBF_TOTAL * 2);

    __nv_bfloat16* sQhi = bfm + IQHI;
    __nv_bfloat16* sQlo = bfm + IQLO;
    __nv_bfloat16* sKhi = bfm + IKHI;
    __nv_bfloat16* sKlo = bfm + IKLO;

    size_t base = (((size_t)b * NH + h) * NT + t) * (CHUNK * HD);
    size_t kb   = (((size_t)b * NH + h) * NT + t) * (HD * HD);
    int tid = threadIdx.x;
    int wid = tid >> 5;

    #pragma unroll
    for (int u = 0; u < 8; u++) {
        int i = tid + u * 256;
        int r = i >> 4, c4 = (i & 15) * 4;
        float4 qv = *(const float4*)(g_q + base + (size_t)r * 64 + c4);
        __nv_bfloat162 h01, l01, h23, l23;
        split4(qv, h01, l01, h23, l23);
        *(__nv_bfloat162*)(sQhi + r*72 + c4)     = h01;
        *(__nv_bfloat162*)(sQhi + r*72 + c4 + 2) = h23;
        *(__nv_bfloat162*)(sQlo + r*72 + c4)     = l01;
        *(__nv_bfloat162*)(sQlo + r*72 + c4 + 2) = l23;
    }
    #pragma unroll
    for (int u = 0; u < 4; u++) {
        int i = tid + u * 256;
        int r = i >> 4, c4 = (i & 15) * 4;
        float4 kv = *(const float4*)(g_kvpre + kb + (size_t)r * 64 + c4);
        __nv_bfloat162 h01, l01, h23, l23;
        split4(kv, h01, l01, h23, l23);
        *(__nv_bfloat162*)(sKhi + r*72 + c4)     = h01;
        *(__nv_bfloat162*)(sKhi + r*72 + c4 + 2) = h23;
        *(__nv_bfloat162*)(sKlo + r*72 + c4)     = l01;
        *(__nv_bfloat162*)(sKlo + r*72 + c4 + 2) = l23;
    }
    __syncthreads();

    {
        int r0 = wid * 16;
        wmma::fragment<wmma::accumulator, 16, 16, 16, float> c[4];
        #pragma unroll
        for (int j = 0; j < 4; j++) wmma::fill_fragment(c[j], 0.0f);
        #pragma unroll
        for (int sk = 0; sk < 4; sk++) {
            int k0 = sk * 16;
            wmma::fragment<wmma::matrix_a, 16, 16, 16, __nv_bfloat16, wmma::row_major> ah, al;
            wmma::load_matrix_sync(ah, &sQhi[r0 * 72 + k0], 72);
            wmma::load_matrix_sync(al, &sQlo[r0 * 72 + k0], 72);
            #pragma unroll
            for (int j = 0; j < 4; j++) {
                int col0 = j * 16;
                wmma::fragment<wmma::matrix_b, 16, 16, 16, __nv_bfloat16, wmma::row_major> bh, bl;
                wmma::load_matrix_sync(bh, &sKhi[k0 * 72 + col0], 72);
                wmma::load_matrix_sync(bl, &sKlo[k0 * 72 + col0], 72);
                wmma::mma_sync(c[j], ah, bh, c[j]);
                wmma::mma_sync(c[j], ah, bl, c[j]);
                wmma::mma_sync(c[j], al, bh, c[j]);
            }
        }
        #pragma unroll
        for (int j = 0; j < 4; j++)
            wmma::store_matrix_sync(&sO[r0 * 68 + j * 16], c[j], 68, wmma::mem_row_major);
    }
    __syncthreads();

    #pragma unroll
    for (int u = 0; u < 8; u++) {
        int i = tid + u * 256;
        int r = i >> 4, c4 = (i & 15) * 4;
        size_t grow = (size_t)b * SEQ + (size_t)t * CHUNK + r;
        float* dst = g_attn + grow * DIMC + h * 64 + c4;
        float4 old = *(float4*)dst;
        old.x += sO[r * 68 + c4 + 0];
        old.y += sO[r * 68 + c4 + 1];
        old.z += sO[r * 68 + c4 + 2];
        old.w += sO[r * 68 + c4 + 3];
        *(float4*)dst = old;
    }
}

// ---------------- launch ----------------
extern "C" void kernel_launch(void* const* d_in, const int* in_sizes, int n_in,
                              void* d_out, int out_size) {
    const float* x       = (const float*)d_in[0];
    const float* cosb    = (const float*)d_in[1];
    const float* sinb    = (const float*)d_in[2];
    const float* qkv_w   = (const float*)d_in[3];
    const float* qkv_b   = (const float*)d_in[4];
    const float* qkv_nw  = (const float*)d_in[5];
    const float* proj_w  = (const float*)d_in[6];
    const float* proj_b  = (const float*)d_in[7];
    const float* proj_nw = (const float*)d_in[8];
    const float* norm_w  = (const float*)d_in[9];
    float* out = (float*)d_out;

    size_t smem_intra = (size_t)BF_TOTAL * 2 + (128 * SS_LD + 128) * sizeof(float);
    size_t smem_inter = (size_t)IBF_TOTAL * 2 + (128 * 68) * sizeof(float);

    static bool attr_done = false;
    if (!attr_done) {
        cudaFuncSetAttribute(attn_intra, cudaFuncAttributeMaxDynamicSharedMemorySize, (int)smem_intra);
        cudaFuncSetAttribute(attn_inter, cudaFuncAttributeMaxDynamicSharedMemorySize, (int)smem_inter);
        cudaFuncSetAttribute(gemm_bf16_t<true>,  cudaFuncAttributeMaxDynamicSharedMemorySize, GEMM_SMEM);
        cudaFuncSetAttribute(gemm_bf16_t<false>, cudaFuncAttributeMaxDynamicSharedMemorySize, GEMM_SMEM);
        attr_done = true;
    }

    __nv_bfloat16 *xq_p, *wqkv_p, *wproj_p, *xq2_p;
    float *adeq_p, *adeq2_p;
    cudaGetSymbolAddress((void**)&xq_p,    g_xq);
    cudaGetSymbolAddress((void**)&wqkv_p,  g_wq_qkv);
    cudaGetSymbolAddress((void**)&wproj_p, g_wq_proj);
    cudaGetSymbolAddress((void**)&xq2_p,   g_xq2);
    cudaGetSymbolAddress((void**)&adeq_p,  g_adeq);
    cudaGetSymbolAddress((void**)&adeq2_p, g_adeq2);

    // Launch order: gemm<QKV> is launch #4 -> ncu capture slot.
    absmean_partial<<<256, 256>>>(qkv_w, QKVN * DIMC);                                    // 1
    quant_weight_fused<<<QKVN * DIMC / 1024, 256>>>(qkv_w, wqkv_p, QKVN * DIMC, 0);       // 2
    act_quant_x<<<NROWS, 256>>>(x, qkv_nw);                                               // 3
    {
        dim3 grid(QKVN / 128, NROWS / 128);
        gemm_bf16_t<true><<<grid, 256, GEMM_SMEM>>>(xq_p, wqkv_p, nullptr, QKVN,
                                                    adeq_p, 0, qkv_b, cosb, sinb);        // 4 <- profiled
    }
    absmean_partial<<<256, 256>>>(proj_w, DIMC * DIMC);                                   // 5
    quant_weight_fused<<<DIMC * DIMC / 1024, 256>>>(proj_w, wproj_p, DIMC * DIMC, 1);     // 6

    {
        dim3 grid(NT, NH, BATCH);
        attn_intra<<<grid, 512, smem_intra>>>();                                          // 7
    }
    kv_prefix<<<256, 256>>>();                                                            // 8
    {
        dim3 grid(NT, NH, BATCH);
        attn_inter<<<grid, 256, smem_inter>>>();                                          // 9
    }

    norm2_quant<<<NROWS, 256>>>(norm_w, proj_nw);                                         // 10
    {
        dim3 grid(DIMC / 128, NROWS / 128);
        gemm_bf16_t<false><<<grid, 256, GEMM_SMEM>>>(xq2_p, wproj_p, out, DIMC,
                                                     adeq2_p, 1, proj_b, cosb, sinb);     // 11
    }
}

// round 11
// speedup vs baseline: 2.6083x; 1.0119x over previous
#include <cuda_runtime.h>
#include <cuda_bf16.h>
#include <mma.h>
#include <cstdint>

using namespace nvcuda;

#define BATCH 2
#define SEQ   8192
#define DIMC  1024
#define NH    16
#define HD    64
#define CHUNK 128
#define NT    64
#define NROWS 16384
#define QKVN  3072
#define SCALE_ATTN 0.125f
#define EPS_BIT 1.1920929e-07f
#define EPS_OUT 1e-06f

// tile-major padded layout: [rowblk][kt 16][row 128][72], only cols 0..63 meaningful
#define TPAD 72
#define TILE_ELEMS (128 * TPAD)          // 9216 elems
#define TILE_BYTES (TILE_ELEMS * 2)      // 18432 bytes

// ---------------- static device scratch ----------------
__device__ __nv_bfloat16 g_xq[(size_t)NROWS * 16 * TILE_ELEMS / 128];
__device__ float         g_adeq[NROWS];
__device__ __nv_bfloat16 g_wq_qkv[(size_t)QKVN * 16 * TILE_ELEMS / 128];
__device__ __nv_bfloat16 g_wq_proj[(size_t)DIMC * 16 * TILE_ELEMS / 128];
__device__ float         g_wdeq[2];
__device__ float         g_part[256];
__device__ float         g_q[(size_t)BATCH * NH * NT * CHUNK * HD];
__device__ float         g_k[(size_t)BATCH * NH * NT * CHUNK * HD];
__device__ float         g_v[(size_t)BATCH * NH * NT * CHUNK * HD];
__device__ float         g_kvsum[(size_t)BATCH * NH * NT * HD * HD];
__device__ float         g_kvpre[(size_t)BATCH * NH * NT * HD * HD];
__device__ float         g_attn[(size_t)NROWS * DIMC];
__device__ __nv_bfloat16 g_xq2[(size_t)NROWS * 16 * TILE_ELEMS / 128];
__device__ float         g_adeq2[NROWS];

// ---------------- helpers ----------------
__device__ __forceinline__ uint32_t smem_u32(const void* smem_ptr) {
    uint32_t addr;
    asm("{ .reg .u64 tmp; cvta.to.shared.u64 tmp, %1; cvt.u32.u64 %0, tmp; }"
        : "=r"(addr) : "l"(smem_ptr));
    return addr;
}

#define MBAR_INIT(addr, cnt) \
    asm volatile("mbarrier.init.shared.b64 [%0], %1;" :: "r"((uint32_t)(addr)), "r"((uint32_t)(cnt)) : "memory")
#define MBAR_EXPECT_TX(addr, bytes) \
    asm volatile("mbarrier.arrive.expect_tx.shared.b64 _, [%0], %1;" :: "r"((uint32_t)(addr)), "r"((uint32_t)(bytes)) : "memory")
#define MBAR_WAIT_PARITY(mbar, parity) do { \
    uint32_t _mbar = (uint32_t)(mbar); \
    uint32_t _parity = (uint32_t)(parity); \
    uint32_t _done; \
    asm volatile( \
        "{\n\t.reg .pred p;\n\t" \
        "mbarrier.try_wait.parity.shared.b64 p, [%1], %2;\n\t" \
        "selp.b32 %0, 1, 0, p;\n\t}" \
        : "=r"(_done) : "r"(_mbar), "r"(_parity) : "memory"); \
    if (!_done) { \
        asm volatile( \
            "{\n\t.reg .pred P1;\n\t" \
            "WAIT_LOOP_%=:\n\t" \
            "mbarrier.try_wait.parity.shared.b64 P1, [%0], %1;\n\t" \
            "@P1 bra.uni WAIT_DONE_%=;\n\t" \
            "bra.uni WAIT_LOOP_%=;\n\t" \
            "WAIT_DONE_%=:\n\t}" \
            :: "r"(_mbar), "r"(_parity) : "memory"); \
    } \
} while(0)
#define BULK_G2S(dst, src, bytes, mbar) \
    asm volatile("cp.async.bulk.shared::cta.global.mbarrier::complete_tx::bytes [%0], [%1], %2, [%3];" \
        :: "r"((uint32_t)(dst)), "l"(src), "r"((uint32_t)(bytes)), "r"((uint32_t)(mbar)) : "memory")

__device__ __forceinline__ float fexp(float x) {
    x = fmaxf(x, -80.0f);
    float y = x * 1.4426950408889634f;
    float n = rintf(y);
    float g = fmaf(-n, 0.6931471805599453f, x);
    float p = 1.9841270e-4f;
    p = fmaf(p, g, 1.3888889e-3f);
    p = fmaf(p, g, 8.3333333e-3f);
    p = fmaf(p, g, 4.1666667e-2f);
    p = fmaf(p, g, 1.6666667e-1f);
    p = fmaf(p, g, 5.0e-1f);
    p = fmaf(p, g, 1.0f);
    p = fmaf(p, g, 1.0f);
    float s = __int_as_float(((int)n + 127) << 23);
    return p * s;
}
__device__ __forceinline__ void split2(float v, __nv_bfloat16& hi, __nv_bfloat16& lo) {
    hi = __float2bfloat16(v);
    lo = __float2bfloat16(v - __bfloat162float(hi));
}
__device__ __forceinline__ void split4(float4 v,
    __nv_bfloat162& h01, __nv_bfloat162& l01,
    __nv_bfloat162& h23, __nv_bfloat162& l23) {
    h01.x = __float2bfloat16(v.x); l01.x = __float2bfloat16(v.x - __bfloat162float(h01.x));
    h01.y = __float2bfloat16(v.y); l01.y = __float2bfloat16(v.y - __bfloat162float(h01.y));
    h23.x = __float2bfloat16(v.z); l23.x = __float2bfloat16(v.z - __bfloat162float(h23.x));
    h23.y = __float2bfloat16(v.w); l23.y = __float2bfloat16(v.w - __bfloat162float(h23.y));
}
__device__ __forceinline__ size_t tile_idx(int row, int col) {
    return (((size_t)(row >> 7) * 16 + (col >> 6)) * 128 + (row & 127)) * TPAD + (col & 63);
}

// ---------------- weight quant ----------------
__global__ void absmean_partial(const float* __restrict__ w, int n) {
    __shared__ float red[256];
    int tid = threadIdx.x;
    float s = 0.f;
    for (int i = blockIdx.x * 256 + tid; i < n; i += 65536) s += fabsf(w[i]);
    red[tid] = s; __syncthreads();
    for (int st = 128; st > 0; st >>= 1) { if (tid < st) red[tid] += red[tid + st]; __syncthreads(); }
    if (tid == 0) g_part[blockIdx.x] = red[0];
}

__global__ void __launch_bounds__(256) quant_weight_fused(const float* __restrict__ w,
                                                          __nv_bfloat16* __restrict__ wq,
                                                          int n, int slot) {
    __shared__ float red[256];
    int tid = threadIdx.x;
    red[tid] = g_part[tid]; __syncthreads();
    for (int st = 128; st > 0; st >>= 1) { if (tid < st) red[tid] += red[tid + st]; __syncthreads(); }
    float wdeq = fmaxf(red[0] / (float)n, 1e-5f);
    if (blockIdx.x == 0 && tid == 0) g_wdeq[slot] = wdeq;
    float s = 1.0f / wdeq;
    int i4 = (blockIdx.x * 256 + tid) * 4;
    if (i4 >= n) return;
    float4 wv = *(const float4*)(w + i4);
    __nv_bfloat162 p0, p1;
    p0.x = __float2bfloat16(fminf(fmaxf(rintf(wv.x * s), -1.f), 1.f));
    p0.y = __float2bfloat16(fminf(fmaxf(rintf(wv.y * s), -1.f), 1.f));
    p1.x = __float2bfloat16(fminf(fmaxf(rintf(wv.z * s), -1.f), 1.f));
    p1.y = __float2bfloat16(fminf(fmaxf(rintf(wv.w * s), -1.f), 1.f));
    int row = i4 >> 10, col = i4 & 1023;
    __nv_bfloat16* out = wq + tile_idx(row, col);
    *(__nv_bfloat162*)(out)     = p0;
    *(__nv_bfloat162*)(out + 2) = p1;
}

// ---------------- activation quant for QKV input ----------------
__global__ void __launch_bounds__(256) act_quant_x(const float* __restrict__ x,
                                                   const float* __restrict__ nw) {
    __shared__ float red[256];
    __shared__ float bc;
    int row = blockIdx.x, tid = threadIdx.x;
    float4 xv = ((const float4*)(x + (size_t)row * DIMC))[tid];
    float4 wv = ((const float4*)nw)[tid];
    float ss = xv.x*xv.x + xv.y*xv.y + xv.z*xv.z + xv.w*xv.w;
    red[tid] = ss; __syncthreads();
    for (int st = 128; st > 0; st >>= 1) { if (tid < st) red[tid] += red[tid + st]; __syncthreads(); }
    if (tid == 0) bc = rsqrtf(red[0] * (1.0f / DIMC) + EPS_BIT);
    __syncthreads();
    float r = bc;
    float n0 = xv.x*r*wv.x, n1 = xv.y*r*wv.y, n2 = xv.z*r*wv.z, n3 = xv.w*r*wv.w;
    float amax = fmaxf(fmaxf(fabsf(n0), fabsf(n1)), fmaxf(fabsf(n2), fabsf(n3)));
    red[tid] = amax; __syncthreads();
    for (int st = 128; st > 0; st >>= 1) { if (tid < st) red[tid] = fmaxf(red[tid], red[tid + st]); __syncthreads(); }
    if (tid == 0) {
        float mx = fmaxf(red[0], 1e-5f);
        bc = 127.0f / mx;
        g_adeq[row] = mx * (1.0f / 127.0f);
    }
    __syncthreads();
    float sc = bc;
    __nv_bfloat162 p0, p1;
    p0.x = __float2bfloat16(fminf(fmaxf(rintf(n0 * sc), -128.f), 127.f));
    p0.y = __float2bfloat16(fminf(fmaxf(rintf(n1 * sc), -128.f), 127.f));
    p1.x = __float2bfloat16(fminf(fmaxf(rintf(n2 * sc), -128.f), 127.f));
    p1.y = __float2bfloat16(fminf(fmaxf(rintf(n3 * sc), -128.f), 127.f));
    __nv_bfloat16* out = g_xq + tile_idx(row, tid * 4);
    *(__nv_bfloat162*)(out)     = p0;
    *(__nv_bfloat162*)(out + 2) = p1;
}

// ---------------- double-norm + act quant for proj input ----------------
__global__ void __launch_bounds__(256) norm2_quant(const float* __restrict__ nw,
                                                   const float* __restrict__ pnw) {
    __shared__ float red[256];
    __shared__ float bc;
    int row = blockIdx.x, tid = threadIdx.x;
    float4 xv = ((const float4*)(g_attn + (size_t)row * DIMC))[tid];
    float4 wv = ((const float4*)nw)[tid];
    float4 pv = ((const float4*)pnw)[tid];
    float ss = xv.x*xv.x + xv.y*xv.y + xv.z*xv.z + xv.w*xv.w;
    red[tid] = ss; __syncthreads();
    for (int st = 128; st > 0; st >>= 1) { if (tid < st) red[tid] += red[tid + st]; __syncthreads(); }
    if (tid == 0) bc = rsqrtf(red[0] * (1.0f / DIMC) + EPS_OUT);
    __syncthreads();
    float r1 = bc;
    float z0 = xv.x*r1*wv.x, z1 = xv.y*r1*wv.y, z2 = xv.z*r1*wv.z, z3 = xv.w*r1*wv.w;
    float ss2 = z0*z0 + z1*z1 + z2*z2 + z3*z3;
    red[tid] = ss2; __syncthreads();
    for (int st = 128; st > 0; st >>= 1) { if (tid < st) red[tid] += red[tid + st]; __syncthreads(); }
    if (tid == 0) bc = rsqrtf(red[0] * (1.0f / DIMC) + EPS_BIT);
    __syncthreads();
    float r2 = bc;
    float n0 = z0*r2*pv.x, n1 = z1*r2*pv.y, n2 = z2*r2*pv.z, n3 = z3*r2*pv.w;
    float amax = fmaxf(fmaxf(fabsf(n0), fabsf(n1)), fmaxf(fabsf(n2), fabsf(n3)));
    red[tid] = amax; __syncthreads();
    for (int st = 128; st > 0; st >>= 1) { if (tid < st) red[tid] = fmaxf(red[tid], red[tid + st]); __syncthreads(); }
    if (tid == 0) {
        float mx = fmaxf(red[0], 1e-5f);
        bc = 127.0f / mx;
        g_adeq2[row] = mx * (1.0f / 127.0f);
    }
    __syncthreads();
    float sc = bc;
    __nv_bfloat162 p0, p1;
    p0.x = __float2bfloat16(fminf(fmaxf(rintf(n0 * sc), -128.f), 127.f));
    p0.y = __float2bfloat16(fminf(fmaxf(rintf(n1 * sc), -128.f), 127.f));
    p1.x = __float2bfloat16(fminf(fmaxf(rintf(n2 * sc), -128.f), 127.f));
    p1.y = __float2bfloat16(fminf(fmaxf(rintf(n3 * sc), -128.f), 127.f));
    __nv_bfloat16* out = g_xq2 + tile_idx(row, tid * 4);
    *(__nv_bfloat162*)(out)     = p0;
    *(__nv_bfloat162*)(out + 2) = p1;
}

// ---------------- bf16 HMMA GEMM: block 128x256, warp tile 64x64, bulk 3-stage ring ----------------
#define GLD TPAD
#define BSTAGE (3 * TILE_BYTES)               // A(1 tile) + B(2 tiles) = 55296
#define MBAR_OFF (3 * BSTAGE)                 // 165888
#define GEMM_SMEM (MBAR_OFF + 64)
template<bool QKV>
__global__ void __launch_bounds__(256) gemm_bf16_t(
    const __nv_bfloat16* __restrict__ A, const __nv_bfloat16* __restrict__ W,
    float* __restrict__ C, int N,
    const float* __restrict__ adeq, int wslot, const float* __restrict__ bias,
    const float* __restrict__ cosb, const float* __restrict__ sinb)
{
    extern __shared__ __align__(16) char gsm[];
    uint32_t sb = smem_u32(gsm);
    uint32_t mb = sb + MBAR_OFF;

    int tid = threadIdx.x;
    int wid = tid >> 5, lane = tid & 31;
    int wm = wid >> 2, wn = wid & 3;            // warp tile 64(M) x 64(N)
    int bm = blockIdx.y * 128;
    int bn = blockIdx.x * 256;

    const __nv_bfloat16* Asrc  = A + (size_t)blockIdx.y * 16 * TILE_ELEMS;
    const __nv_bfloat16* Bsrc0 = W + (size_t)(2 * blockIdx.x)     * 16 * TILE_ELEMS;
    const __nv_bfloat16* Bsrc1 = W + (size_t)(2 * blockIdx.x + 1) * 16 * TILE_ELEMS;

    wmma::fragment<wmma::accumulator, 16, 16, 16, float> c[4][4];
    #pragma unroll
    for (int i = 0; i < 4; i++)
        #pragma unroll
        for (int j = 0; j < 4; j++) wmma::fill_fragment(c[i][j], 0.0f);

    if (tid == 0) {
        #pragma unroll
        for (int s = 0; s < 3; s++) MBAR_INIT(mb + s * 8, 1);
    }
    __syncthreads();
    if (tid == 0) {
        #pragma unroll
        for (int s = 0; s < 2; s++) {
            MBAR_EXPECT_TX(mb + s * 8, BSTAGE);
            BULK_G2S(sb + s * BSTAGE,                  Asrc  + s * TILE_ELEMS, TILE_BYTES, mb + s * 8);
            BULK_G2S(sb + s * BSTAGE + TILE_BYTES,     Bsrc0 + s * TILE_ELEMS, TILE_BYTES, mb + s * 8);
            BULK_G2S(sb + s * BSTAGE + 2 * TILE_BYTES, Bsrc1 + s * TILE_ELEMS, TILE_BYTES, mb + s * 8);
        }
    }

    int m0 = wm * 64;
    int bhalf = (wn >> 1);                      // which 128-row half of B
    int n0 = (wn & 1) * 64;                     // row offset within the half
    for (int kt = 0; kt < 16; kt++) {
        int sRead = kt % 3;
        MBAR_WAIT_PARITY(mb + sRead * 8, (kt / 3) & 1);
        __syncthreads();   // data ready AND all warps done with kt-1
        if (tid == 0 && kt + 2 < 16) {
            int sW = (kt + 2) % 3;
            MBAR_EXPECT_TX(mb + sW * 8, BSTAGE);
            BULK_G2S(sb + sW * BSTAGE,                  Asrc  + (kt + 2) * TILE_ELEMS, TILE_BYTES, mb + sW * 8);
            BULK_G2S(sb + sW * BSTAGE + TILE_BYTES,     Bsrc0 + (kt + 2) * TILE_ELEMS, TILE_BYTES, mb + sW * 8);
            BULK_G2S(sb + sW * BSTAGE + 2 * TILE_BYTES, Bsrc1 + (kt + 2) * TILE_ELEMS, TILE_BYTES, mb + sW * 8);
        }
        const __nv_bfloat16* as = (const __nv_bfloat16*)(gsm + sRead * BSTAGE);
        const __nv_bfloat16* bs = (const __nv_bfloat16*)(gsm + sRead * BSTAGE + TILE_BYTES
                                                         + bhalf * TILE_BYTES);
        #pragma unroll
        for (int sk = 0; sk < 4; sk++) {
            int k0 = sk * 16;
            wmma::fragment<wmma::matrix_a, 16, 16, 16, __nv_bfloat16, wmma::row_major> af[4];
            wmma::fragment<wmma::matrix_b, 16, 16, 16, __nv_bfloat16, wmma::col_major> bf[4];
            #pragma unroll
            for (int i = 0; i < 4; i++)
                wmma::load_matrix_sync(af[i], &as[(m0 + i * 16) * GLD + k0], GLD);
            #pragma unroll
            for (int j = 0; j < 4; j++)
                wmma::load_matrix_sync(bf[j], &bs[(n0 + j * 16) * GLD + k0], GLD);
            #pragma unroll
            for (int i = 0; i < 4; i++)
                #pragma unroll
                for (int j = 0; j < 4; j++)
                    wmma::mma_sync(c[i][j], af[i], bf[j], c[i][j]);
        }
    }
    __syncthreads();   // all MMAs done; stage smem reusable for C staging

    float wdeq = g_wdeq[wslot];
    float* CsAll = (float*)gsm;
    float* Csw = &CsAll[wid * 320];
    #pragma unroll
    for (int i = 0; i < 4; i++) {
        #pragma unroll
        for (int j = 0; j < 4; j++) {
            __syncwarp();
            wmma::store_matrix_sync(Csw, c[i][j], 20, wmma::mem_row_major);
            __syncwarp();
            int r  = lane >> 1;
            int cc = (lane & 1) * 8;
            int grow = bm + wm * 64 + i * 16 + r;
            int gcol = bn + wn * 64 + j * 16 + cc;
            float sc = adeq[grow] * wdeq;
            float v[8];
            #pragma unroll
            for (int u = 0; u < 8; u++)
                v[u] = Csw[r * 20 + cc + u] * sc + bias[gcol + u];
            if (QKV) {
                int which = gcol >> 10;
                int rem = gcol & 1023;
                int h = rem >> 6, d = rem & 63;
                int b = grow >> 13, n = grow & 8191;
                int t = n >> 7, rr = n & 127;
                if (which < 2) {
                    int i0 = d >> 1;
                    #pragma unroll
                    for (int m = 0; m < 4; m++) {
                        float cth = cosb[n * 32 + i0 + m];
                        float sth = sinb[n * 32 + i0 + m];
                        float e = v[2*m], o = v[2*m+1];
                        v[2*m]   = e * cth - o * sth;
                        v[2*m+1] = o * cth + e * sth;
                    }
                }
                float* dstbase = (which == 0) ? g_q : (which == 1) ? g_k : g_v;
                float* dst = dstbase + (((size_t)b * NH + h) * NT + t) * (CHUNK * HD)
                           + (size_t)rr * 64 + d;
                *(float4*)(dst)     = make_float4(v[0], v[1], v[2], v[3]);
                *(float4*)(dst + 4) = make_float4(v[4], v[5], v[6], v[7]);
            } else {
                float* dst = C + (size_t)grow * N + gcol;
                *(float4*)(dst)     = make_float4(v[0], v[1], v[2], v[3]);
                *(float4*)(dst + 4) = make_float4(v[4], v[5], v[6], v[7]);
            }
        }
    }
}

// ---------------- intra-chunk attention (split-bf16 tensor cores) ----------------
#define QHI_OFF 0
#define QLO_OFF (128*72)
#define KHI_OFF (2*128*72)
#define KLO_OFF (3*128*72)
#define PHI_OFF (4*128*72)
#define PLO_OFF (4*128*72 + 128*136)
#define BF_TOTAL (4*128*72 + 2*128*136)
#define SS_LD 132

__global__ void __launch_bounds__(512) attn_intra() {
    int t = blockIdx.x, h = blockIdx.y, b = blockIdx.z;
    extern __shared__ __align__(16) char smraw[];
    __nv_bfloat16* bfm = (__nv_bfloat16*)smraw;
    float* sS = (float*)(smraw + (size_t)BF_TOTAL * 2);
    float* rowsum = sS + 128 * SS_LD;

    __nv_bfloat16* sQhi = bfm + QHI_OFF;
    __nv_bfloat16* sQlo = bfm + QLO_OFF;
    __nv_bfloat16* sKhi = bfm + KHI_OFF;
    __nv_bfloat16* sKlo = bfm + KLO_OFF;
    __nv_bfloat16* sPhi = bfm + PHI_OFF;
    __nv_bfloat16* sPlo = bfm + PLO_OFF;
    __nv_bfloat16* sVhi = sQhi;
    __nv_bfloat16* sVlo = sQlo;

    size_t base = (((size_t)b * NH + h) * NT + t) * (CHUNK * HD);
    int tid = threadIdx.x;
    int wid = tid >> 5;

    #pragma unroll
    for (int u = 0; u < 4; u++) {
        int i = tid + u * 512;
        int r = i >> 4, c4 = (i & 15) * 4;
        float4 qv = *(const float4*)(g_q + base + (size_t)r * 64 + c4);
        float4 kv = *(const float4*)(g_k + base + (size_t)r * 64 + c4);
        __nv_bfloat162 h01, l01, h23, l23;
        split4(qv, h01, l01, h23, l23);
        *(__nv_bfloat162*)(sQhi + r*72 + c4)     = h01;
        *(__nv_bfloat162*)(sQhi + r*72 + c4 + 2) = h23;
        *(__nv_bfloat162*)(sQlo + r*72 + c4)     = l01;
        *(__nv_bfloat162*)(sQlo + r*72 + c4 + 2) = l23;
        split4(kv, h01, l01, h23, l23);
        *(__nv_bfloat162*)(sKhi + r*72 + c4)     = h01;
        *(__nv_bfloat162*)(sKhi + r*72 + c4 + 2) = h23;
        *(__nv_bfloat162*)(sKlo + r*72 + c4)     = l01;
        *(__nv_bfloat162*)(sKlo + r*72 + c4 + 2) = l23;
    }
    __syncthreads();

    // QK^T: 16 warps, warp tile 16 rows x 64 cols
    {
        int r0 = (wid >> 1) * 16;
        int cbase = (wid & 1) * 64;
        wmma::fragment<wmma::accumulator, 16, 16, 16, float> c[4];
        #pragma unroll
        for (int j = 0; j < 4; j++) wmma::fill_fragment(c[j], 0.0f);
        #pragma unroll
        for (int sk = 0; sk < 4; sk++) {
            int k0 = sk * 16;
            wmma::fragment<wmma::matrix_a, 16, 16, 16, __nv_bfloat16, wmma::row_major> ah, al;
            wmma::load_matrix_sync(ah, &sQhi[r0 * 72 + k0], 72);
            wmma::load_matrix_sync(al, &sQlo[r0 * 72 + k0], 72);
            #pragma unroll
            for (int j = 0; j < 4; j++) {
                int col0 = cbase + j * 16;
                wmma::fragment<wmma::matrix_b, 16, 16, 16, __nv_bfloat16, wmma::col_major> bh, bl;
                wmma::load_matrix_sync(bh, &sKhi[col0 * 72 + k0], 72);
                wmma::load_matrix_sync(bl, &sKlo[col0 * 72 + k0], 72);
                wmma::mma_sync(c[j], ah, bh, c[j]);
                wmma::mma_sync(c[j], ah, bl, c[j]);
                wmma::mma_sync(c[j], al, bh, c[j]);
            }
        }
        #pragma unroll
        for (int j = 0; j < 4; j++) {
            #pragma unroll
            for (int e = 0; e < c[j].num_elements; e++) c[j].x[e] *= SCALE_ATTN;
            wmma::store_matrix_sync(&sS[r0 * SS_LD + cbase + j * 16], c[j], SS_LD, wmma::mem_row_major);
        }
    }
    __syncthreads();

    // softmax: 4 threads per row
    {
        int r = tid >> 2;
        int c0 = (tid & 3) * 32;
        float mx = -3.0e38f;
        for (int c = c0; c < c0 + 32; c++)
            if (c <= r) mx = fmaxf(mx, sS[r * SS_LD + c]);
        mx = fmaxf(mx, __shfl_xor_sync(0xffffffffu, mx, 1));
        mx = fmaxf(mx, __shfl_xor_sync(0xffffffffu, mx, 2));
        float sum = 0.f;
        for (int c = c0; c < c0 + 32; c++) {
            float e = (c <= r) ? fexp(sS[r * SS_LD + c] - mx) : 0.f;
            sum += e;
            __nv_bfloat16 hi, lo;
            split2(e, hi, lo);
            sPhi[r * 136 + c] = hi;
            sPlo[r * 136 + c] = lo;
        }
        sum += __shfl_xor_sync(0xffffffffu, sum, 1);
        sum += __shfl_xor_sync(0xffffffffu, sum, 2);
        if ((tid & 3) == 0) rowsum[r] = sum;
    }
    // V load into Q slots
    #pragma unroll
    for (int u = 0; u < 4; u++) {
        int i = tid + u * 512;
        int r = i >> 4, c4 = (i & 15) * 4;
        float4 vv = *(const float4*)(g_v + base + (size_t)r * 64 + c4);
        __nv_bfloat162 h01, l01, h23, l23;
        split4(vv, h01, l01, h23, l23);
        *(__nv_bfloat162*)(sVhi + r*72 + c4)     = h01;
        *(__nv_bfloat162*)(sVhi + r*72 + c4 + 2) = h23;
        *(__nv_bfloat162*)(sVlo + r*72 + c4)     = l01;
        *(__nv_bfloat162*)(sVlo + r*72 + c4 + 2) = l23;
    }
    __syncthreads();

    // S_t = K^T V (64x64): one 16x16 tile per warp
    {
        int d0 = (wid >> 2) * 16;
        int e0 = (wid & 3) * 16;
        wmma::fragment<wmma::accumulator, 16, 16, 16, float> c;
        wmma::fill_fragment(c, 0.0f);
        #pragma unroll
        for (int sk = 0; sk < 8; sk++) {
            int r0 = sk * 16;
            wmma::fragment<wmma::matrix_a, 16, 16, 16, __nv_bfloat16, wmma::col_major> ah, al;
            wmma::fragment<wmma::matrix_b, 16, 16, 16, __nv_bfloat16, wmma::row_major> bh, bl;
            wmma::load_matrix_sync(ah, &sKhi[r0 * 72 + d0], 72);
            wmma::load_matrix_sync(al, &sKlo[r0 * 72 + d0], 72);
            wmma::load_matrix_sync(bh, &sVhi[r0 * 72 + e0], 72);
            wmma::load_matrix_sync(bl, &sVlo[r0 * 72 + e0], 72);
            wmma::mma_sync(c, ah, bh, c);
            wmma::mma_sync(c, ah, bl, c);
            wmma::mma_sync(c, al, bh, c);
        }
        size_t kb = (((size_t)b * NH + h) * NT + t) * (HD * HD);
        wmma::store_matrix_sync(g_kvsum + kb + (size_t)d0 * 64 + e0, c, 64, wmma::mem_row_major);
    }

    // o_intra = P @ V (128x64): warp tile 16x32
    {
        int r0 = (wid >> 1) * 16;
        int cbase = (wid & 1) * 32;
        wmma::fragment<wmma::accumulator, 16, 16, 16, float> c[2];
        #pragma unroll
        for (int j = 0; j < 2; j++) wmma::fill_fragment(c[j], 0.0f);
        #pragma unroll
        for (int sk = 0; sk < 8; sk++) {
            int k0 = sk * 16;
            wmma::fragment<wmma::matrix_a, 16, 16, 16, __nv_bfloat16, wmma::row_major> ah, al;
            wmma::load_matrix_sync(ah, &sPhi[r0 * 136 + k0], 136);
            wmma::load_matrix_sync(al, &sPlo[r0 * 136 + k0], 136);
            #pragma unroll
            for (int j = 0; j < 2; j++) {
                int col0 = cbase + j * 16;
                wmma::fragment<wmma::matrix_b, 16, 16, 16, __nv_bfloat16, wmma::row_major> bh, bl;
                wmma::load_matrix_sync(bh, &sVhi[k0 * 72 + col0], 72);
                wmma::load_matrix_sync(bl, &sVlo[k0 * 72 + col0], 72);
                wmma::mma_sync(c[j], ah, bh, c[j]);
                wmma::mma_sync(c[j], ah, bl, c[j]);
                wmma::mma_sync(c[j], al, bh, c[j]);
            }
        }
        __syncthreads();
        #pragma unroll
        for (int j = 0; j < 2; j++)
            wmma::store_matrix_sync(&sS[r0 * SS_LD + cbase + j * 16], c[j], SS_LD, wmma::mem_row_major);
    }
    __syncthreads();

    #pragma unroll
    for (int u = 0; u < 4; u++) {
        int i = tid + u * 512;
        int r = i >> 4, c4 = (i & 15) * 4;
        float inv = 1.0f / rowsum[r];
        float4 o;
        o.x = sS[r * SS_LD + c4 + 0] * inv;
        o.y = sS[r * SS_LD + c4 + 1] * inv;
        o.z = sS[r * SS_LD + c4 + 2] * inv;
        o.w = sS[r * SS_LD + c4 + 3] * inv;
        size_t grow = (size_t)b * SEQ + (size_t)t * CHUNK + r;
        *(float4*)(g_attn + grow * DIMC + h * 64 + c4) = o;
    }
}

// ---------------- exclusive prefix-sum of chunk KV matrices ----------------
__global__ void __launch_bounds__(256) kv_prefix() {
    int blk = blockIdx.x;
    int bh = blk >> 3, s = blk & 7;
    int tid = threadIdx.x;
    size_t base = (size_t)bh * NT * (HD * HD) + s * 512 + tid * 2;
    float2 acc = make_float2(0.f, 0.f);
    for (int t = 0; t < NT; t++) {
        size_t off = base + (size_t)t * (HD * HD);
        float2 v = *(const float2*)(g_kvsum + off);
        *(float2*)(g_kvpre + off) = acc;
        acc.x += v.x; acc.y += v.y;
    }
}

// ---------------- o_inter = q @ kv_prefix ----------------
#define IQHI 0
#define IQLO (128*72)
#define IKHI (2*128*72)
#define IKLO (2*128*72 + 64*72)
#define IBF_TOTAL (2*128*72 + 2*64*72)
__global__ void __launch_bounds__(256) attn_inter() {
    int t = blockIdx.x, h = blockIdx.y, b = blockIdx.z;
    extern __shared__ __align__(16) char smraw2[];
    __nv_bfloat16* bfm = (__nv_bfloat16*)smraw2;
    float* sO = (float*)(smraw2 + (size_t)IBF_TOTAL * 2);

    __nv_bfloat16* sQhi = bfm + IQHI;
    __nv_bfloat16* sQlo = bfm + IQLO;
    __nv_bfloat16* sKhi = bfm + IKHI;
    __nv_bfloat16* sKlo = bfm + IKLO;

    size_t base = (((size_t)b * NH + h) * NT + t) * (CHUNK * HD);
    size_t kb   = (((size_t)b * NH + h) * NT + t) * (HD * HD);
    int tid = threadIdx.x;
    int wid = tid >> 5;

    #pragma unroll
    for (int u = 0; u < 8; u++) {
        int i = tid + u * 256;
        int r = i >> 4, c4 = (i & 15) * 4;
        float4 qv = *(const float4*)(g_q + base + (size_t)r * 64 + c4);
        __nv_bfloat162 h01, l01, h23, l23;
        split4(qv, h01, l01, h23, l23);
        *(__nv_bfloat162*)(sQhi + r*72 + c4)     = h01;
        *(__nv_bfloat162*)(sQhi + r*72 + c4 + 2) = h23;
        *(__nv_bfloat162*)(sQlo + r*72 + c4)     = l01;
        *(__nv_bfloat162*)(sQlo + r*72 + c4 + 2) = l23;
    }
    #pragma unroll
    for (int u = 0; u < 4; u++) {
        int i = tid + u * 256;
        int r = i >> 4, c4 = (i & 15) * 4;
        float4 kv = *(const float4*)(g_kvpre + kb + (size_t)r * 64 + c4);
        __nv_bfloat162 h01, l01, h23, l23;
        split4(kv, h01, l01, h23, l23);
        *(__nv_bfloat162*)(sKhi + r*72 + c4)     = h01;
        *(__nv_bfloat162*)(sKhi + r*72 + c4 + 2) = h23;
        *(__nv_bfloat162*)(sKlo + r*72 + c4)     = l01;
        *(__nv_bfloat162*)(sKlo + r*72 + c4 + 2) = l23;
    }
    __syncthreads();

    {
        int r0 = wid * 16;
        wmma::fragment<wmma::accumulator, 16, 16, 16, float> c[4];
        #pragma unroll
        for (int j = 0; j < 4; j++) wmma::fill_fragment(c[j], 0.0f);
        #pragma unroll
        for (int sk = 0; sk < 4; sk++) {
            int k0 = sk * 16;
            wmma::fragment<wmma::matrix_a, 16, 16, 16, __nv_bfloat16, wmma::row_major> ah, al;
            wmma::load_matrix_sync(ah, &sQhi[r0 * 72 + k0], 72);
            wmma::load_matrix_sync(al, &sQlo[r0 * 72 + k0], 72);
            #pragma unroll
            for (int j = 0; j < 4; j++) {
                int col0 = j * 16;
                wmma::fragment<wmma::matrix_b, 16, 16, 16, __nv_bfloat16, wmma::row_major> bh, bl;
                wmma::load_matrix_sync(bh, &sKhi[k0 * 72 + col0], 72);
                wmma::load_matrix_sync(bl, &sKlo[k0 * 72 + col0], 72);
                wmma::mma_sync(c[j], ah, bh, c[j]);
                wmma::mma_sync(c[j], ah, bl, c[j]);
                wmma::mma_sync(c[j], al, bh, c[j]);
            }
        }
        #pragma unroll
        for (int j = 0; j < 4; j++)
            wmma::store_matrix_sync(&sO[r0 * 68 + j * 16], c[j], 68, wmma::mem_row_major);
    }
    __syncthreads();

    #pragma unroll
    for (int u = 0; u < 8; u++) {
        int i = tid + u * 256;
        int r = i >> 4, c4 = (i & 15) * 4;
        size_t grow = (size_t)b * SEQ + (size_t)t * CHUNK + r;
        float* dst = g_attn + grow * DIMC + h * 64 + c4;
        float4 old = *(float4*)dst;
        old.x += sO[r * 68 + c4 + 0];
        old.y += sO[r * 68 + c4 + 1];
        old.z += sO[r * 68 + c4 + 2];
        old.w += sO[r * 68 + c4 + 3];
        *(float4*)dst = old;
    }
}

// ---------------- launch ----------------
extern "C" void kernel_launch(void* const* d_in, const int* in_sizes, int n_in,
                              void* d_out, int out_size) {
    const float* x       = (const float*)d_in[0];
    const float* cosb    = (const float*)d_in[1];
    const float* sinb    = (const float*)d_in[2];
    const float* qkv_w   = (const float*)d_in[3];
    const float* qkv_b   = (const float*)d_in[4];
    const float* qkv_nw  = (const float*)d_in[5];
    const float* proj_w  = (const float*)d_in[6];
    const float* proj_b  = (const float*)d_in[7];
    const float* proj_nw = (const float*)d_in[8];
    const float* norm_w  = (const float*)d_in[9];
    float* out = (float*)d_out;

    size_t smem_intra = (size_t)BF_TOTAL * 2 + (128 * SS_LD + 128) * sizeof(float);
    size_t smem_inter = (size_t)IBF_TOTAL * 2 + (128 * 68) * sizeof(float);

    static bool attr_done = false;
    if (!attr_done) {
        cudaFuncSetAttribute(attn_intra, cudaFuncAttributeMaxDynamicSharedMemorySize, (int)smem_intra);
        cudaFuncSetAttribute(attn_inter, cudaFuncAttributeMaxDynamicSharedMemorySize, (int)smem_inter);
        cudaFuncSetAttribute(gemm_bf16_t<true>,  cudaFuncAttributeMaxDynamicSharedMemorySize, GEMM_SMEM);
        cudaFuncSetAttribute(gemm_bf16_t<false>, cudaFuncAttributeMaxDynamicSharedMemorySize, GEMM_SMEM);
        attr_done = true;
    }

    __nv_bfloat16 *xq_p, *wqkv_p, *wproj_p, *xq2_p;
    float *adeq_p, *adeq2_p;
    cudaGetSymbolAddress((void**)&xq_p,    g_xq);
    cudaGetSymbolAddress((void**)&wqkv_p,  g_wq_qkv);
    cudaGetSymbolAddress((void**)&wproj_p, g_wq_proj);
    cudaGetSymbolAddress((void**)&xq2_p,   g_xq2);
    cudaGetSymbolAddress((void**)&adeq_p,  g_adeq);
    cudaGetSymbolAddress((void**)&adeq2_p, g_adeq2);

    // Launch order: gemm<QKV> is launch #4 -> ncu capture slot.
    absmean_partial<<<256, 256>>>(qkv_w, QKVN * DIMC);                                    // 1
    quant_weight_fused<<<QKVN * DIMC / 1024, 256>>>(qkv_w, wqkv_p, QKVN * DIMC, 0);       // 2
    act_quant_x<<<NROWS, 256>>>(x, qkv_nw);                                               // 3
    {
        dim3 grid(QKVN / 256, NROWS / 128);
        gemm_bf16_t<true><<<grid, 256, GEMM_SMEM>>>(xq_p, wqkv_p, nullptr, QKVN,
                                                    adeq_p, 0, qkv_b, cosb, sinb);        // 4 <- profiled
    }
    absmean_partial<<<256, 256>>>(proj_w, DIMC * DIMC);                                   // 5
    quant_weight_fused<<<DIMC * DIMC / 1024, 256>>>(proj_w, wproj_p, DIMC * DIMC, 1);     // 6

    {
        dim3 grid(NT, NH, BATCH);
        attn_intra<<<grid, 512, smem_intra>>>();                                          // 7
    }
    kv_prefix<<<256, 256>>>();                                                            // 8
    {
        dim3 grid(NT, NH, BATCH);
        attn_inter<<<grid, 256, smem_inter>>>();                                          // 9
    }

    norm2_quant<<<NROWS, 256>>>(norm_w, proj_nw);                                         // 10
    {
        dim3 grid(DIMC / 256, NROWS / 128);
        gemm_bf16_t<false><<<grid, 256, GEMM_SMEM>>>(xq2_p, wproj_p, out, DIMC,
                                                     adeq2_p, 1, proj_b, cosb, sinb);     // 11
    }
}

// round 12
// speedup vs baseline: 2.6522x; 1.0168x over previous
#include <cuda_runtime.h>
#include <cuda_bf16.h>
#include <mma.h>
#include <cstdint>

using namespace nvcuda;

#define BATCH 2
#define SEQ   8192
#define DIMC  1024
#define NH    16
#define HD    64
#define CHUNK 128
#define NT    64
#define NROWS 16384
#define QKVN  3072
#define SCALE_ATTN 0.125f
#define EPS_BIT 1.1920929e-07f
#define EPS_OUT 1e-06f

// tile-major padded layout: [rowblk][kt 16][row 128][72], only cols 0..63 meaningful
#define TPAD 72
#define TILE_ELEMS (128 * TPAD)          // 9216 elems
#define TILE_BYTES (TILE_ELEMS * 2)      // 18432 bytes

// ---------------- static device scratch ----------------
__device__ __nv_bfloat16 g_xq[(size_t)NROWS * 16 * TILE_ELEMS / 128];
__device__ float         g_adeq[NROWS];
__device__ __nv_bfloat16 g_wq_qkv[(size_t)QKVN * 16 * TILE_ELEMS / 128];
__device__ __nv_bfloat16 g_wq_proj[(size_t)DIMC * 16 * TILE_ELEMS / 128];
__device__ float         g_wdeq[2];
__device__ float         g_part[256];
__device__ float         g_q[(size_t)BATCH * NH * NT * CHUNK * HD];
__device__ float         g_k[(size_t)BATCH * NH * NT * CHUNK * HD];
__device__ float         g_v[(size_t)BATCH * NH * NT * CHUNK * HD];
__device__ float         g_kvsum[(size_t)BATCH * NH * NT * HD * HD];
__device__ float         g_kvpre[(size_t)BATCH * NH * NT * HD * HD];
__device__ float         g_attn[(size_t)NROWS * DIMC];
__device__ __nv_bfloat16 g_xq2[(size_t)NROWS * 16 * TILE_ELEMS / 128];
__device__ float         g_adeq2[NROWS];

// ---------------- helpers ----------------
__device__ __forceinline__ uint32_t smem_u32(const void* smem_ptr) {
    uint32_t addr;
    asm("{ .reg .u64 tmp; cvta.to.shared.u64 tmp, %1; cvt.u32.u64 %0, tmp; }"
        : "=r"(addr) : "l"(smem_ptr));
    return addr;
}

#define MBAR_INIT(addr, cnt) \
    asm volatile("mbarrier.init.shared.b64 [%0], %1;" :: "r"((uint32_t)(addr)), "r"((uint32_t)(cnt)) : "memory")
#define MBAR_ARRIVE(addr) \
    asm volatile("mbarrier.arrive.shared.b64 _, [%0];" :: "r"((uint32_t)(addr)) : "memory")
#define MBAR_EXPECT_TX(addr, bytes) \
    asm volatile("mbarrier.arrive.expect_tx.shared.b64 _, [%0], %1;" :: "r"((uint32_t)(addr)), "r"((uint32_t)(bytes)) : "memory")
#define MBAR_WAIT_PARITY(mbar, parity) do { \
    uint32_t _mbar = (uint32_t)(mbar); \
    uint32_t _parity = (uint32_t)(parity); \
    uint32_t _done; \
    asm volatile( \
        "{\n\t.reg .pred p;\n\t" \
        "mbarrier.try_wait.parity.shared.b64 p, [%1], %2;\n\t" \
        "selp.b32 %0, 1, 0, p;\n\t}" \
        : "=r"(_done) : "r"(_mbar), "r"(_parity) : "memory"); \
    if (!_done) { \
        asm volatile( \
            "{\n\t.reg .pred P1;\n\t" \
            "WAIT_LOOP_%=:\n\t" \
            "mbarrier.try_wait.parity.shared.b64 P1, [%0], %1;\n\t" \
            "@P1 bra.uni WAIT_DONE_%=;\n\t" \
            "bra.uni WAIT_LOOP_%=;\n\t" \
            "WAIT_DONE_%=:\n\t}" \
            :: "r"(_mbar), "r"(_parity) : "memory"); \
    } \
} while(0)
#define BULK_G2S(dst, src, bytes, mbar) \
    asm volatile("cp.async.bulk.shared::cta.global.mbarrier::complete_tx::bytes [%0], [%1], %2, [%3];" \
        :: "r"((uint32_t)(dst)), "l"(src), "r"((uint32_t)(bytes)), "r"((uint32_t)(mbar)) : "memory")

__device__ __forceinline__ float fexp(float x) {
    x = fmaxf(x, -80.0f);
    float y = x * 1.4426950408889634f;
    float n = rintf(y);
    float g = fmaf(-n, 0.6931471805599453f, x);
    float p = 1.9841270e-4f;
    p = fmaf(p, g, 1.3888889e-3f);
    p = fmaf(p, g, 8.3333333e-3f);
    p = fmaf(p, g, 4.1666667e-2f);
    p = fmaf(p, g, 1.6666667e-1f);
    p = fmaf(p, g, 5.0e-1f);
    p = fmaf(p, g, 1.0f);
    p = fmaf(p, g, 1.0f);
    float s = __int_as_float(((int)n + 127) << 23);
    return p * s;
}
__device__ __forceinline__ void split2(float v, __nv_bfloat16& hi, __nv_bfloat16& lo) {
    hi = __float2bfloat16(v);
    lo = __float2bfloat16(v - __bfloat162float(hi));
}
__device__ __forceinline__ void split4(float4 v,
    __nv_bfloat162& h01, __nv_bfloat162& l01,
    __nv_bfloat162& h23, __nv_bfloat162& l23) {
    h01.x = __float2bfloat16(v.x); l01.x = __float2bfloat16(v.x - __bfloat162float(h01.x));
    h01.y = __float2bfloat16(v.y); l01.y = __float2bfloat16(v.y - __bfloat162float(h01.y));
    h23.x = __float2bfloat16(v.z); l23.x = __float2bfloat16(v.z - __bfloat162float(h23.x));
    h23.y = __float2bfloat16(v.w); l23.y = __float2bfloat16(v.w - __bfloat162float(h23.y));
}
__device__ __forceinline__ size_t tile_idx(int row, int col) {
    return (((size_t)(row >> 7) * 16 + (col >> 6)) * 128 + (row & 127)) * TPAD + (col & 63);
}

// ---------------- weight quant ----------------
__global__ void absmean_partial(const float* __restrict__ w, int n) {
    __shared__ float red[256];
    int tid = threadIdx.x;
    float s = 0.f;
    for (int i = blockIdx.x * 256 + tid; i < n; i += 65536) s += fabsf(w[i]);
    red[tid] = s; __syncthreads();
    for (int st = 128; st > 0; st >>= 1) { if (tid < st) red[tid] += red[tid + st]; __syncthreads(); }
    if (tid == 0) g_part[blockIdx.x] = red[0];
}

__global__ void __launch_bounds__(256) quant_weight_fused(const float* __restrict__ w,
                                                          __nv_bfloat16* __restrict__ wq,
                                                          int n, int slot) {
    __shared__ float red[256];
    int tid = threadIdx.x;
    red[tid] = g_part[tid]; __syncthreads();
    for (int st = 128; st > 0; st >>= 1) { if (tid < st) red[tid] += red[tid + st]; __syncthreads(); }
    float wdeq = fmaxf(red[0] / (float)n, 1e-5f);
    if (blockIdx.x == 0 && tid == 0) g_wdeq[slot] = wdeq;
    float s = 1.0f / wdeq;
    int i4 = (blockIdx.x * 256 + tid) * 4;
    if (i4 >= n) return;
    float4 wv = *(const float4*)(w + i4);
    __nv_bfloat162 p0, p1;
    p0.x = __float2bfloat16(fminf(fmaxf(rintf(wv.x * s), -1.f), 1.f));
    p0.y = __float2bfloat16(fminf(fmaxf(rintf(wv.y * s), -1.f), 1.f));
    p1.x = __float2bfloat16(fminf(fmaxf(rintf(wv.z * s), -1.f), 1.f));
    p1.y = __float2bfloat16(fminf(fmaxf(rintf(wv.w * s), -1.f), 1.f));
    int row = i4 >> 10, col = i4 & 1023;
    __nv_bfloat16* out = wq + tile_idx(row, col);
    *(__nv_bfloat162*)(out)     = p0;
    *(__nv_bfloat162*)(out + 2) = p1;
}

// ---------------- activation quant for QKV input ----------------
__global__ void __launch_bounds__(256) act_quant_x(const float* __restrict__ x,
                                                   const float* __restrict__ nw) {
    __shared__ float red[256];
    __shared__ float bc;
    int row = blockIdx.x, tid = threadIdx.x;
    float4 xv = ((const float4*)(x + (size_t)row * DIMC))[tid];
    float4 wv = ((const float4*)nw)[tid];
    float ss = xv.x*xv.x + xv.y*xv.y + xv.z*xv.z + xv.w*xv.w;
    red[tid] = ss; __syncthreads();
    for (int st = 128; st > 0; st >>= 1) { if (tid < st) red[tid] += red[tid + st]; __syncthreads(); }
    if (tid == 0) bc = rsqrtf(red[0] * (1.0f / DIMC) + EPS_BIT);
    __syncthreads();
    float r = bc;
    float n0 = xv.x*r*wv.x, n1 = xv.y*r*wv.y, n2 = xv.z*r*wv.z, n3 = xv.w*r*wv.w;
    float amax = fmaxf(fmaxf(fabsf(n0), fabsf(n1)), fmaxf(fabsf(n2), fabsf(n3)));
    red[tid] = amax; __syncthreads();
    for (int st = 128; st > 0; st >>= 1) { if (tid < st) red[tid] = fmaxf(red[tid], red[tid + st]); __syncthreads(); }
    if (tid == 0) {
        float mx = fmaxf(red[0], 1e-5f);
        bc = 127.0f / mx;
        g_adeq[row] = mx * (1.0f / 127.0f);
    }
    __syncthreads();
    float sc = bc;
    __nv_bfloat162 p0, p1;
    p0.x = __float2bfloat16(fminf(fmaxf(rintf(n0 * sc), -128.f), 127.f));
    p0.y = __float2bfloat16(fminf(fmaxf(rintf(n1 * sc), -128.f), 127.f));
    p1.x = __float2bfloat16(fminf(fmaxf(rintf(n2 * sc), -128.f), 127.f));
    p1.y = __float2bfloat16(fminf(fmaxf(rintf(n3 * sc), -128.f), 127.f));
    __nv_bfloat16* out = g_xq + tile_idx(row, tid * 4);
    *(__nv_bfloat162*)(out)     = p0;
    *(__nv_bfloat162*)(out + 2) = p1;
}

// ---------------- double-norm + act quant for proj input ----------------
__global__ void __launch_bounds__(256) norm2_quant(const float* __restrict__ nw,
                                                   const float* __restrict__ pnw) {
    __shared__ float red[256];
    __shared__ float bc;
    int row = blockIdx.x, tid = threadIdx.x;
    float4 xv = ((const float4*)(g_attn + (size_t)row * DIMC))[tid];
    float4 wv = ((const float4*)nw)[tid];
    float4 pv = ((const float4*)pnw)[tid];
    float ss = xv.x*xv.x + xv.y*xv.y + xv.z*xv.z + xv.w*xv.w;
    red[tid] = ss; __syncthreads();
    for (int st = 128; st > 0; st >>= 1) { if (tid < st) red[tid] += red[tid + st]; __syncthreads(); }
    if (tid == 0) bc = rsqrtf(red[0] * (1.0f / DIMC) + EPS_OUT);
    __syncthreads();
    float r1 = bc;
    float z0 = xv.x*r1*wv.x, z1 = xv.y*r1*wv.y, z2 = xv.z*r1*wv.z, z3 = xv.w*r1*wv.w;
    float ss2 = z0*z0 + z1*z1 + z2*z2 + z3*z3;
    red[tid] = ss2; __syncthreads();
    for (int st = 128; st > 0; st >>= 1) { if (tid < st) red[tid] += red[tid + st]; __syncthreads(); }
    if (tid == 0) bc = rsqrtf(red[0] * (1.0f / DIMC) + EPS_BIT);
    __syncthreads();
    float r2 = bc;
    float n0 = z0*r2*pv.x, n1 = z1*r2*pv.y, n2 = z2*r2*pv.z, n3 = z3*r2*pv.w;
    float amax = fmaxf(fmaxf(fabsf(n0), fabsf(n1)), fmaxf(fabsf(n2), fabsf(n3)));
    red[tid] = amax; __syncthreads();
    for (int st = 128; st > 0; st >>= 1) { if (tid < st) red[tid] = fmaxf(red[tid], red[tid + st]); __syncthreads(); }
    if (tid == 0) {
        float mx = fmaxf(red[0], 1e-5f);
        bc = 127.0f / mx;
        g_adeq2[row] = mx * (1.0f / 127.0f);
    }
    __syncthreads();
    float sc = bc;
    __nv_bfloat162 p0, p1;
    p0.x = __float2bfloat16(fminf(fmaxf(rintf(n0 * sc), -128.f), 127.f));
    p0.y = __float2bfloat16(fminf(fmaxf(rintf(n1 * sc), -128.f), 127.f));
    p1.x = __float2bfloat16(fminf(fmaxf(rintf(n2 * sc), -128.f), 127.f));
    p1.y = __float2bfloat16(fminf(fmaxf(rintf(n3 * sc), -128.f), 127.f));
    __nv_bfloat16* out = g_xq2 + tile_idx(row, tid * 4);
    *(__nv_bfloat162*)(out)     = p0;
    *(__nv_bfloat162*)(out + 2) = p1;
}

// ---------------- bf16 HMMA GEMM: block 128x256, warp tile 64x64 ----------------
// bulk 3-stage ring, producer/consumer mbarriers, NO per-K-tile __syncthreads.
#define GLD TPAD
#define BSTAGE (3 * TILE_BYTES)               // A(1 tile) + B(2 tiles) = 55296
#define MBAR_OFF (3 * BSTAGE)                 // 165888; full[0..2] then empty[0..2]
#define GEMM_SMEM (MBAR_OFF + 128)
template<bool QKV>
__global__ void __launch_bounds__(256) gemm_bf16_t(
    const __nv_bfloat16* __restrict__ A, const __nv_bfloat16* __restrict__ W,
    float* __restrict__ C, int N,
    const float* __restrict__ adeq, int wslot, const float* __restrict__ bias,
    const float* __restrict__ cosb, const float* __restrict__ sinb)
{
    extern __shared__ __align__(16) char gsm[];
    uint32_t sb = smem_u32(gsm);
    uint32_t fullb  = sb + MBAR_OFF;        // 3 x 8 bytes
    uint32_t emptyb = sb + MBAR_OFF + 24;   // 3 x 8 bytes

    int tid = threadIdx.x;
    int wid = tid >> 5, lane = tid & 31;
    int wm = wid >> 2, wn = wid & 3;            // warp tile 64(M) x 64(N)
    int bm = blockIdx.y * 128;
    int bn = blockIdx.x * 256;

    const __nv_bfloat16* Asrc  = A + (size_t)blockIdx.y * 16 * TILE_ELEMS;
    const __nv_bfloat16* Bsrc0 = W + (size_t)(2 * blockIdx.x)     * 16 * TILE_ELEMS;
    const __nv_bfloat16* Bsrc1 = W + (size_t)(2 * blockIdx.x + 1) * 16 * TILE_ELEMS;

    wmma::fragment<wmma::accumulator, 16, 16, 16, float> c[4][4];
    #pragma unroll
    for (int i = 0; i < 4; i++)
        #pragma unroll
        for (int j = 0; j < 4; j++) wmma::fill_fragment(c[i][j], 0.0f);

    if (tid == 0) {
        #pragma unroll
        for (int s = 0; s < 3; s++) {
            MBAR_INIT(fullb  + s * 8, 1);
            MBAR_INIT(emptyb + s * 8, 8);   // one arrive per warp
        }
    }
    __syncthreads();
    if (tid == 0) {
        #pragma unroll
        for (int s = 0; s < 2; s++) {
            MBAR_EXPECT_TX(fullb + s * 8, BSTAGE);
            BULK_G2S(sb + s * BSTAGE,                  Asrc  + s * TILE_ELEMS, TILE_BYTES, fullb + s * 8);
            BULK_G2S(sb + s * BSTAGE + TILE_BYTES,     Bsrc0 + s * TILE_ELEMS, TILE_BYTES, fullb + s * 8);
            BULK_G2S(sb + s * BSTAGE + 2 * TILE_BYTES, Bsrc1 + s * TILE_ELEMS, TILE_BYTES, fullb + s * 8);
        }
    }

    int m0 = wm * 64;
    int bhalf = (wn >> 1);
    int n0 = (wn & 1) * 64;
    for (int kt = 0; kt < 16; kt++) {
        int sRead = kt % 3;
        // producer: refill stage (kt+2)%3 once its previous readers (iteration kt-1) release it
        if (tid == 0 && kt + 2 < 16) {
            int sW = (kt + 2) % 3;
            if (kt >= 1) MBAR_WAIT_PARITY(emptyb + sW * 8, ((kt - 1) / 3) & 1);
            MBAR_EXPECT_TX(fullb + sW * 8, BSTAGE);
            BULK_G2S(sb + sW * BSTAGE,                  Asrc  + (kt + 2) * TILE_ELEMS, TILE_BYTES, fullb + sW * 8);
            BULK_G2S(sb + sW * BSTAGE + TILE_BYTES,     Bsrc0 + (kt + 2) * TILE_ELEMS, TILE_BYTES, fullb + sW * 8);
            BULK_G2S(sb + sW * BSTAGE + 2 * TILE_BYTES, Bsrc1 + (kt + 2) * TILE_ELEMS, TILE_BYTES, fullb + sW * 8);
        }
        // consumer: wait stage full (per-warp; no CTA barrier)
        MBAR_WAIT_PARITY(fullb + sRead * 8, (kt / 3) & 1);
        const __nv_bfloat16* as = (const __nv_bfloat16*)(gsm + sRead * BSTAGE);
        const __nv_bfloat16* bs = (const __nv_bfloat16*)(gsm + sRead * BSTAGE + TILE_BYTES
                                                         + bhalf * TILE_BYTES);
        #pragma unroll
        for (int sk = 0; sk < 4; sk++) {
            int k0 = sk * 16;
            wmma::fragment<wmma::matrix_a, 16, 16, 16, __nv_bfloat16, wmma::row_major> af[4];
            wmma::fragment<wmma::matrix_b, 16, 16, 16, __nv_bfloat16, wmma::col_major> bf[4];
            #pragma unroll
            for (int i = 0; i < 4; i++)
                wmma::load_matrix_sync(af[i], &as[(m0 + i * 16) * GLD + k0], GLD);
            #pragma unroll
            for (int j = 0; j < 4; j++)
                wmma::load_matrix_sync(bf[j], &bs[(n0 + j * 16) * GLD + k0], GLD);
            #pragma unroll
            for (int i = 0; i < 4; i++)
                #pragma unroll
                for (int j = 0; j < 4; j++)
                    wmma::mma_sync(c[i][j], af[i], bf[j], c[i][j]);
        }
        // release the stage (one arrive per warp)
        if (lane == 0) MBAR_ARRIVE(emptyb + sRead * 8);
    }
    __syncthreads();   // all MMAs done; stage smem reusable for C staging

    float wdeq = g_wdeq[wslot];
    float* CsAll = (float*)gsm;
    float* Csw = &CsAll[wid * 320];
    #pragma unroll
    for (int i = 0; i < 4; i++) {
        #pragma unroll
        for (int j = 0; j < 4; j++) {
            __syncwarp();
            wmma::store_matrix_sync(Csw, c[i][j], 20, wmma::mem_row_major);
            __syncwarp();
            int r  = lane >> 1;
            int cc = (lane & 1) * 8;
            int grow = bm + wm * 64 + i * 16 + r;
            int gcol = bn + wn * 64 + j * 16 + cc;
            float sc = adeq[grow] * wdeq;
            float v[8];
            #pragma unroll
            for (int u = 0; u < 8; u++)
                v[u] = Csw[r * 20 + cc + u] * sc + bias[gcol + u];
            if (QKV) {
                int which = gcol >> 10;
                int rem = gcol & 1023;
                int h = rem >> 6, d = rem & 63;
                int b = grow >> 13, n = grow & 8191;
                int t = n >> 7, rr = n & 127;
                if (which < 2) {
                    int i0 = d >> 1;
                    #pragma unroll
                    for (int m = 0; m < 4; m++) {
                        float cth = cosb[n * 32 + i0 + m];
                        float sth = sinb[n * 32 + i0 + m];
                        float e = v[2*m], o = v[2*m+1];
                        v[2*m]   = e * cth - o * sth;
                        v[2*m+1] = o * cth + e * sth;
                    }
                }
                float* dstbase = (which == 0) ? g_q : (which == 1) ? g_k : g_v;
                float* dst = dstbase + (((size_t)b * NH + h) * NT + t) * (CHUNK * HD)
                           + (size_t)rr * 64 + d;
                *(float4*)(dst)     = make_float4(v[0], v[1], v[2], v[3]);
                *(float4*)(dst + 4) = make_float4(v[4], v[5], v[6], v[7]);
            } else {
                float* dst = C + (size_t)grow * N + gcol;
                *(float4*)(dst)     = make_float4(v[0], v[1], v[2], v[3]);
                *(float4*)(dst + 4) = make_float4(v[4], v[5], v[6], v[7]);
            }
        }
    }
}

// ---------------- intra-chunk attention (split-bf16 tensor cores) ----------------
#define QHI_OFF 0
#define QLO_OFF (128*72)
#define KHI_OFF (2*128*72)
#define KLO_OFF (3*128*72)
#define PHI_OFF (4*128*72)
#define PLO_OFF (4*128*72 + 128*136)
#define BF_TOTAL (4*128*72 + 2*128*136)
#define SS_LD 132

__global__ void __launch_bounds__(512) attn_intra() {
    int t = blockIdx.x, h = blockIdx.y, b = blockIdx.z;
    extern __shared__ __align__(16) char smraw[];
    __nv_bfloat16* bfm = (__nv_bfloat16*)smraw;
    float* sS = (float*)(smraw + (size_t)BF_TOTAL * 2);
    float* rowsum = sS + 128 * SS_LD;

    __nv_bfloat16* sQhi = bfm + QHI_OFF;
    __nv_bfloat16* sQlo = bfm + QLO_OFF;
    __nv_bfloat16* sKhi = bfm + KHI_OFF;
    __nv_bfloat16* sKlo = bfm + KLO_OFF;
    __nv_bfloat16* sPhi = bfm + PHI_OFF;
    __nv_bfloat16* sPlo = bfm + PLO_OFF;
    __nv_bfloat16* sVhi = sQhi;
    __nv_bfloat16* sVlo = sQlo;

    size_t base = (((size_t)b * NH + h) * NT + t) * (CHUNK * HD);
    int tid = threadIdx.x;
    int wid = tid >> 5;

    #pragma unroll
    for (int u = 0; u < 4; u++) {
        int i = tid + u * 512;
        int r = i >> 4, c4 = (i & 15) * 4;
        float4 qv = *(const float4*)(g_q + base + (size_t)r * 64 + c4);
        float4 kv = *(const float4*)(g_k + base + (size_t)r * 64 + c4);
        __nv_bfloat162 h01, l01, h23, l23;
        split4(qv, h01, l01, h23, l23);
        *(__nv_bfloat162*)(sQhi + r*72 + c4)     = h01;
        *(__nv_bfloat162*)(sQhi + r*72 + c4 + 2) = h23;
        *(__nv_bfloat162*)(sQlo + r*72 + c4)     = l01;
        *(__nv_bfloat162*)(sQlo + r*72 + c4 + 2) = l23;
        split4(kv, h01, l01, h23, l23);
        *(__nv_bfloat162*)(sKhi + r*72 + c4)     = h01;
        *(__nv_bfloat162*)(sKhi + r*72 + c4 + 2) = h23;
        *(__nv_bfloat162*)(sKlo + r*72 + c4)     = l01;
        *(__nv_bfloat162*)(sKlo + r*72 + c4 + 2) = l23;
    }
    __syncthreads();

    // QK^T: 16 warps, warp tile 16 rows x 64 cols
    {
        int r0 = (wid >> 1) * 16;
        int cbase = (wid & 1) * 64;
        wmma::fragment<wmma::accumulator, 16, 16, 16, float> c[4];
        #pragma unroll
        for (int j = 0; j < 4; j++) wmma::fill_fragment(c[j], 0.0f);
        #pragma unroll
        for (int sk = 0; sk < 4; sk++) {
            int k0 = sk * 16;
            wmma::fragment<wmma::matrix_a, 16, 16, 16, __nv_bfloat16, wmma::row_major> ah, al;
            wmma::load_matrix_sync(ah, &sQhi[r0 * 72 + k0], 72);
            wmma::load_matrix_sync(al, &sQlo[r0 * 72 + k0], 72);
            #pragma unroll
            for (int j = 0; j < 4; j++) {
                int col0 = cbase + j * 16;
                wmma::fragment<wmma::matrix_b, 16, 16, 16, __nv_bfloat16, wmma::col_major> bh, bl;
                wmma::load_matrix_sync(bh, &sKhi[col0 * 72 + k0], 72);
                wmma::load_matrix_sync(bl, &sKlo[col0 * 72 + k0], 72);
                wmma::mma_sync(c[j], ah, bh, c[j]);
                wmma::mma_sync(c[j], ah, bl, c[j]);
                wmma::mma_sync(c[j], al, bh, c[j]);
            }
        }
        #pragma unroll
        for (int j = 0; j < 4; j++) {
            #pragma unroll
            for (int e = 0; e < c[j].num_elements; e++) c[j].x[e] *= SCALE_ATTN;
            wmma::store_matrix_sync(&sS[r0 * SS_LD + cbase + j * 16], c[j], SS_LD, wmma::mem_row_major);
        }
    }
    __syncthreads();

    // softmax: 4 threads per row
    {
        int r = tid >> 2;
        int c0 = (tid & 3) * 32;
        float mx = -3.0e38f;
        for (int c = c0; c < c0 + 32; c++)
            if (c <= r) mx = fmaxf(mx, sS[r * SS_LD + c]);
        mx = fmaxf(mx, __shfl_xor_sync(0xffffffffu, mx, 1));
        mx = fmaxf(mx, __shfl_xor_sync(0xffffffffu, mx, 2));
        float sum = 0.f;
        for (int c = c0; c < c0 + 32; c++) {
            float e = (c <= r) ? fexp(sS[r * SS_LD + c] - mx) : 0.f;
            sum += e;
            __nv_bfloat16 hi, lo;
            split2(e, hi, lo);
            sPhi[r * 136 + c] = hi;
            sPlo[r * 136 + c] = lo;
        }
        sum += __shfl_xor_sync(0xffffffffu, sum, 1);
        sum += __shfl_xor_sync(0xffffffffu, sum, 2);
        if ((tid & 3) == 0) rowsum[r] = sum;
    }
    // V load into Q slots
    #pragma unroll
    for (int u = 0; u < 4; u++) {
        int i = tid + u * 512;
        int r = i >> 4, c4 = (i & 15) * 4;
        float4 vv = *(const float4*)(g_v + base + (size_t)r * 64 + c4);
        __nv_bfloat162 h01, l01, h23, l23;
        split4(vv, h01, l01, h23, l23);
        *(__nv_bfloat162*)(sVhi + r*72 + c4)     = h01;
        *(__nv_bfloat162*)(sVhi + r*72 + c4 + 2) = h23;
        *(__nv_bfloat162*)(sVlo + r*72 + c4)     = l01;
        *(__nv_bfloat162*)(sVlo + r*72 + c4 + 2) = l23;
    }
    __syncthreads();

    // S_t = K^T V (64x64): one 16x16 tile per warp
    {
        int d0 = (wid >> 2) * 16;
        int e0 = (wid & 3) * 16;
        wmma::fragment<wmma::accumulator, 16, 16, 16, float> c;
        wmma::fill_fragment(c, 0.0f);
        #pragma unroll
        for (int sk = 0; sk < 8; sk++) {
            int r0 = sk * 16;
            wmma::fragment<wmma::matrix_a, 16, 16, 16, __nv_bfloat16, wmma::col_major> ah, al;
            wmma::fragment<wmma::matrix_b, 16, 16, 16, __nv_bfloat16, wmma::row_major> bh, bl;
            wmma::load_matrix_sync(ah, &sKhi[r0 * 72 + d0], 72);
            wmma::load_matrix_sync(al, &sKlo[r0 * 72 + d0], 72);
            wmma::load_matrix_sync(bh, &sVhi[r0 * 72 + e0], 72);
            wmma::load_matrix_sync(bl, &sVlo[r0 * 72 + e0], 72);
            wmma::mma_sync(c, ah, bh, c);
            wmma::mma_sync(c, ah, bl, c);
            wmma::mma_sync(c, al, bh, c);
        }
        size_t kb = (((size_t)b * NH + h) * NT + t) * (HD * HD);
        wmma::store_matrix_sync(g_kvsum + kb + (size_t)d0 * 64 + e0, c, 64, wmma::mem_row_major);
    }

    // o_intra = P @ V (128x64): warp tile 16x32
    {
        int r0 = (wid >> 1) * 16;
        int cbase = (wid & 1) * 32;
        wmma::fragment<wmma::accumulator, 16, 16, 16, float> c[2];
        #pragma unroll
        for (int j = 0; j < 2; j++) wmma::fill_fragment(c[j], 0.0f);
        #pragma unroll
        for (int sk = 0; sk < 8; sk++) {
            int k0 = sk * 16;
            wmma::fragment<wmma::matrix_a, 16, 16, 16, __nv_bfloat16, wmma::row_major> ah, al;
            wmma::load_matrix_sync(ah, &sPhi[r0 * 136 + k0], 136);
            wmma::load_matrix_sync(al, &sPlo[r0 * 136 + k0], 136);
            #pragma unroll
            for (int j = 0; j < 2; j++) {
                int col0 = cbase + j * 16;
                wmma::fragment<wmma::matrix_b, 16, 16, 16, __nv_bfloat16, wmma::row_major> bh, bl;
                wmma::load_matrix_sync(bh, &sVhi[k0 * 72 + col0], 72);
                wmma::load_matrix_sync(bl, &sVlo[k0 * 72 + col0], 72);
                wmma::mma_sync(c[j], ah, bh, c[j]);
                wmma::mma_sync(c[j], ah, bl, c[j]);
                wmma::mma_sync(c[j], al, bh, c[j]);
            }
        }
        __syncthreads();
        #pragma unroll
        for (int j = 0; j < 2; j++)
            wmma::store_matrix_sync(&sS[r0 * SS_LD + cbase + j * 16], c[j], SS_LD, wmma::mem_row_major);
    }
    __syncthreads();

    #pragma unroll
    for (int u = 0; u < 4; u++) {
        int i = tid + u * 512;
        int r = i >> 4, c4 = (i & 15) * 4;
        float inv = 1.0f / rowsum[r];
        float4 o;
        o.x = sS[r * SS_LD + c4 + 0] * inv;
        o.y = sS[r * SS_LD + c4 + 1] * inv;
        o.z = sS[r * SS_LD + c4 + 2] * inv;
        o.w = sS[r * SS_LD + c4 + 3] * inv;
        size_t grow = (size_t)b * SEQ + (size_t)t * CHUNK + r;
        *(float4*)(g_attn + grow * DIMC + h * 64 + c4) = o;
    }
}

// ---------------- exclusive prefix-sum of chunk KV matrices ----------------
__global__ void __launch_bounds__(256) kv_prefix() {
    int blk = blockIdx.x;
    int bh = blk >> 3, s = blk & 7;
    int tid = threadIdx.x;
    size_t base = (size_t)bh * NT * (HD * HD) + s * 512 + tid * 2;
    float2 acc = make_float2(0.f, 0.f);
    for (int t = 0; t < NT; t++) {
        size_t off = base + (size_t)t * (HD * HD);
        float2 v = *(const float2*)(g_kvsum + off);
        *(float2*)(g_kvpre + off) = acc;
        acc.x += v.x; acc.y += v.y;
    }
}

// ---------------- o_inter = q @ kv_prefix ----------------
#define IQHI 0
#define IQLO (128*72)
#define IKHI (2*128*72)
#define IKLO (2*128*72 + 64*72)
#define IBF_TOTAL (2*128*72 + 2*64*72)
__global__ void __launch_bounds__(256) attn_inter() {
    int t = blockIdx.x, h = blockIdx.y, b = blockIdx.z;
    extern __shared__ __align__(16) char smraw2[];
    __nv_bfloat16* bfm = (__nv_bfloat16*)smraw2;
    float* sO = (float*)(smraw2 + (size_t)IBF_TOTAL * 2);

    __nv_bfloat16* sQhi = bfm + IQHI;
    __nv_bfloat16* sQlo = bfm + IQLO;
    __nv_bfloat16* sKhi = bfm + IKHI;
    __nv_bfloat16* sKlo = bfm + IKLO;

    size_t base = (((size_t)b * NH + h) * NT + t) * (CHUNK * HD);
    size_t kb   = (((size_t)b * NH + h) * NT + t) * (HD * HD);
    int tid = threadIdx.x;
    int wid = tid >> 5;

    #pragma unroll
    for (int u = 0; u < 8; u++) {
        int i = tid + u * 256;
        int r = i >> 4, c4 = (i & 15) * 4;
        float4 qv = *(const float4*)(g_q + base + (size_t)r * 64 + c4);
        __nv_bfloat162 h01, l01, h23, l23;
        split4(qv, h01, l01, h23, l23);
        *(__nv_bfloat162*)(sQhi + r*72 + c4)     = h01;
        *(__nv_bfloat162*)(sQhi + r*72 + c4 + 2) = h23;
        *(__nv_bfloat162*)(sQlo + r*72 + c4)     = l01;
        *(__nv_bfloat162*)(sQlo + r*72 + c4 + 2) = l23;
    }
    #pragma unroll
    for (int u = 0; u < 4; u++) {
        int i = tid + u * 256;
        int r = i >> 4, c4 = (i & 15) * 4;
        float4 kv = *(const float4*)(g_kvpre + kb + (size_t)r * 64 + c4);
        __nv_bfloat162 h01, l01, h23, l23;
        split4(kv, h01, l01, h23, l23);
        *(__nv_bfloat162*)(sKhi + r*72 + c4)     = h01;
        *(__nv_bfloat162*)(sKhi + r*72 + c4 + 2) = h23;
        *(__nv_bfloat162*)(sKlo + r*72 + c4)     = l01;
        *(__nv_bfloat162*)(sKlo + r*72 + c4 + 2) = l23;
    }
    __syncthreads();

    {
        int r0 = wid * 16;
        wmma::fragment<wmma::accumulator, 16, 16, 16, float> c[4];
        #pragma unroll
        for (int j = 0; j < 4; j++) wmma::fill_fragment(c[j], 0.0f);
        #pragma unroll
        for (int sk = 0; sk < 4; sk++) {
            int k0 = sk * 16;
            wmma::fragment<wmma::matrix_a, 16, 16, 16, __nv_bfloat16, wmma::row_major> ah, al;
            wmma::load_matrix_sync(ah, &sQhi[r0 * 72 + k0], 72);
            wmma::load_matrix_sync(al, &sQlo[r0 * 72 + k0], 72);
            #pragma unroll
            for (int j = 0; j < 4; j++) {
                int col0 = j * 16;
                wmma::fragment<wmma::matrix_b, 16, 16, 16, __nv_bfloat16, wmma::row_major> bh, bl;
                wmma::load_matrix_sync(bh, &sKhi[k0 * 72 + col0], 72);
                wmma::load_matrix_sync(bl, &sKlo[k0 * 72 + col0], 72);
                wmma::mma_sync(c[j], ah, bh, c[j]);
                wmma::mma_sync(c[j], ah, bl, c[j]);
                wmma::mma_sync(c[j], al, bh, c[j]);
            }
        }
        #pragma unroll
        for (int j = 0; j < 4; j++)
            wmma::store_matrix_sync(&sO[r0 * 68 + j * 16], c[j], 68, wmma::mem_row_major);
    }
    __syncthreads();

    #pragma unroll
    for (int u = 0; u < 8; u++) {
        int i = tid + u * 256;
        int r = i >> 4, c4 = (i & 15) * 4;
        size_t grow = (size_t)b * SEQ + (size_t)t * CHUNK + r;
        float* dst = g_attn + grow * DIMC + h * 64 + c4;
        float4 old = *(float4*)dst;
        old.x += sO[r * 68 + c4 + 0];
        old.y += sO[r * 68 + c4 + 1];
        old.z += sO[r * 68 + c4 + 2];
        old.w += sO[r * 68 + c4 + 3];
        *(float4*)dst = old;
    }
}

// ---------------- launch ----------------
extern "C" void kernel_launch(void* const* d_in, const int* in_sizes, int n_in,
                              void* d_out, int out_size) {
    const float* x       = (const float*)d_in[0];
    const float* cosb    = (const float*)d_in[1];
    const float* sinb    = (const float*)d_in[2];
    const float* qkv_w   = (const float*)d_in[3];
    const float* qkv_b   = (const float*)d_in[4];
    const float* qkv_nw  = (const float*)d_in[5];
    const float* proj_w  = (const float*)d_in[6];
    const float* proj_b  = (const float*)d_in[7];
    const float* proj_nw = (const float*)d_in[8];
    const float* norm_w  = (const float*)d_in[9];
    float* out = (float*)d_out;

    size_t smem_intra = (size_t)BF_TOTAL * 2 + (128 * SS_LD + 128) * sizeof(float);
    size_t smem_inter = (size_t)IBF_TOTAL * 2 + (128 * 68) * sizeof(float);

    static bool attr_done = false;
    if (!attr_done) {
        cudaFuncSetAttribute(attn_intra, cudaFuncAttributeMaxDynamicSharedMemorySize, (int)smem_intra);
        cudaFuncSetAttribute(attn_inter, cudaFuncAttributeMaxDynamicSharedMemorySize, (int)smem_inter);
        cudaFuncSetAttribute(gemm_bf16_t<true>,  cudaFuncAttributeMaxDynamicSharedMemorySize, GEMM_SMEM);
        cudaFuncSetAttribute(gemm_bf16_t<false>, cudaFuncAttributeMaxDynamicSharedMemorySize, GEMM_SMEM);
        attr_done = true;
    }

    __nv_bfloat16 *xq_p, *wqkv_p, *wproj_p, *xq2_p;
    float *adeq_p, *adeq2_p;
    cudaGetSymbolAddress((void**)&xq_p,    g_xq);
    cudaGetSymbolAddress((void**)&wqkv_p,  g_wq_qkv);
    cudaGetSymbolAddress((void**)&wproj_p, g_wq_proj);
    cudaGetSymbolAddress((void**)&xq2_p,   g_xq2);
    cudaGetSymbolAddress((void**)&adeq_p,  g_adeq);
    cudaGetSymbolAddress((void**)&adeq2_p, g_adeq2);

    // Launch order: gemm<QKV> is launch #4 -> ncu capture slot.
    absmean_partial<<<256, 256>>>(qkv_w, QKVN * DIMC);                                    // 1
    quant_weight_fused<<<QKVN * DIMC / 1024, 256>>>(qkv_w, wqkv_p, QKVN * DIMC, 0);       // 2
    act_quant_x<<<NROWS, 256>>>(x, qkv_nw);                                               // 3
    {
        dim3 grid(QKVN / 256, NROWS / 128);
        gemm_bf16_t<true><<<grid, 256, GEMM_SMEM>>>(xq_p, wqkv_p, nullptr, QKVN,
                                                    adeq_p, 0, qkv_b, cosb, sinb);        // 4 <- profiled
    }
    absmean_partial<<<256, 256>>>(proj_w, DIMC * DIMC);                                   // 5
    quant_weight_fused<<<DIMC * DIMC / 1024, 256>>>(proj_w, wproj_p, DIMC * DIMC, 1);     // 6

    {
        dim3 grid(NT, NH, BATCH);
        attn_intra<<<grid, 512, smem_intra>>>();                                          // 7
    }
    kv_prefix<<<256, 256>>>();                                                            // 8
    {
        dim3 grid(NT, NH, BATCH);
        attn_inter<<<grid, 256, smem_inter>>>();                                          // 9
    }

    norm2_quant<<<NROWS, 256>>>(norm_w, proj_nw);                                         // 10
    {
        dim3 grid(DIMC / 256, NROWS / 128);
        gemm_bf16_t<false><<<grid, 256, GEMM_SMEM>>>(xq2_p, wproj_p, out, DIMC,
                                                     adeq2_p, 1, proj_b, cosb, sinb);     // 11
    }
}